// round 9
// baseline (speedup 1.0000x reference)
#include <cuda_runtime.h>
#include <cuda_bf16.h>
#include <math.h>
#include <stdint.h>

// ---------------- problem constants ----------------
#define BB 4
#define TT 2048
#define DD 1024
#define HH 8
#define DKk 128
#define DVv 256
#define CC 64
#define NCHUNK (TT / CC)   // 32
#define MROWS (BB * TT)    // 8192
#define NBH (BB * HH)      // 32
#define NQKVG 6144         // q(1024) | k(1024) | v(2048) | g(2048)

// ---------------- scratch (no runtime allocation allowed) ----------------
__device__ float g_qkvg[MROWS * NQKVG];
__device__ float g_o[MROWS * HH * DVv];

// retention intermediates
__device__ float g_attn[NBH * NCHUNK * CC * CC];
__device__ float g_kv[NBH * NCHUNK * DKk * DVv];
__device__ float g_S[NBH * NCHUNK * DKk * DVv];

// bf16 split operands
__device__ __nv_bfloat16 g_xhi[MROWS * DD];
__device__ __nv_bfloat16 g_xlo[MROWS * DD];
__device__ __nv_bfloat16 g_ohi[MROWS * HH * DVv];
__device__ __nv_bfloat16 g_olo[MROWS * HH * DVv];
// transposed weights [N, K]
__device__ __nv_bfloat16 g_wall_hi[NQKVG * DD], g_wall_lo[NQKVG * DD];
__device__ __nv_bfloat16 g_wo_hi[2 * DD * DD],  g_wo_lo[2 * DD * DD];

// ================= PTX helpers (plain sm_80+ ISA only) =================
__device__ __forceinline__ uint32_t smem_u32(const void* p) {
    uint32_t a;
    asm("{ .reg .u64 t; cvta.to.shared.u64 t, %1; cvt.u32.u64 %0, t; }" : "=r"(a) : "l"(p));
    return a;
}
#define CP_ASYNC16(dst, src) \
    asm volatile("cp.async.cg.shared.global [%0], [%1], 16;" :: "r"(dst), "l"(src))
#define CP_ASYNC_COMMIT() asm volatile("cp.async.commit_group;" ::: "memory")
#define CP_ASYNC_WAIT1() asm volatile("cp.async.wait_group 1;" ::: "memory")

__device__ __forceinline__ void ldsm4(uint32_t* r, uint32_t addr) {
    asm volatile("ldmatrix.sync.aligned.m8n8.x4.shared.b16 {%0,%1,%2,%3}, [%4];"
        : "=r"(r[0]), "=r"(r[1]), "=r"(r[2]), "=r"(r[3]) : "r"(addr));
}
__device__ __forceinline__ void mma16816(float* c, const uint32_t* a, const uint32_t* b) {
    asm volatile("mma.sync.aligned.m16n8k16.row.col.f32.bf16.bf16.f32 "
        "{%0,%1,%2,%3}, {%4,%5,%6,%7}, {%8,%9}, {%0,%1,%2,%3};"
        : "+f"(c[0]), "+f"(c[1]), "+f"(c[2]), "+f"(c[3])
        : "r"(a[0]), "r"(a[1]), "r"(a[2]), "r"(a[3]), "r"(b[0]), "r"(b[1]));
}

// ================= split-bf16 tensor-core GEMM =================
// single-barrier delayed-refill 3-stage pipeline
#define GSTAGES 3
#define GMAT_BYTES (128 * 64)
#define GSTAGE_BYTES (4 * GMAT_BYTES)
#define GEMM_SMEM_BYTES (GSTAGES * GSTAGE_BYTES)

__device__ __forceinline__ uint32_t swz(int row, int c16) {
    return (uint32_t)(row * 64 + ((c16 ^ ((row >> 1) & 3)) << 4));
}

__device__ __forceinline__ void load_tile32(uint32_t dst, const __nv_bfloat16* src,
                                            int row0, int k0, int ldk, int tid) {
    const char* gbase = (const char*)(src + (size_t)row0 * ldk + k0);
    const size_t rowb = (size_t)ldk * 2;
#pragma unroll
    for (int j = 0; j < 4; j++) {
        int e = tid + j * 128;
        int r = e >> 2, c16 = e & 3;
        CP_ASYNC16(dst + swz(r, c16), gbase + (size_t)r * rowb + c16 * 16);
    }
}

__global__ __launch_bounds__(128, 2) void gemm_split_mma(
    const __nv_bfloat16* __restrict__ Ahi, const __nv_bfloat16* __restrict__ Alo,
    const __nv_bfloat16* __restrict__ Bhi, const __nv_bfloat16* __restrict__ Blo,
    float* __restrict__ C, int M, int N, int K) {
    extern __shared__ char smem[];
    const uint32_t sb = smem_u32(smem);
    const int tid = threadIdx.x, lane = tid & 31, wid = tid >> 5;
    const int wm = wid & 1, wn = wid >> 1;
    const int m0 = blockIdx.y * 128, n0 = blockIdx.x * 128;
    const int nchunk = K >> 5;

    const int a_row = (lane & 7) + 8 * ((lane >> 3) & 1);
    const int a_c8  = lane >> 4;
    const int b_row = (lane & 7) + 8 * (lane >> 4);
    const int b_c8  = (lane >> 3) & 1;

    const int arow = wm * 64 + a_row;
    const int selA = (arow >> 1) & 3;
    const int brow = wn * 64 + b_row;
    const int selB = (brow >> 1) & 3;

    float acc[4][8][4];
#pragma unroll
    for (int i = 0; i < 4; i++)
#pragma unroll
        for (int j = 0; j < 8; j++)
#pragma unroll
            for (int r = 0; r < 4; r++) acc[i][j][r] = 0.f;

    // prologue: chunks 0..2 into stages 0..2 (3 groups)
#pragma unroll
    for (int s = 0; s < GSTAGES; s++) {
        uint32_t st = sb + s * GSTAGE_BYTES;
        int k0 = s * 32;
        load_tile32(st,                  Ahi, m0, k0, K, tid);
        load_tile32(st + GMAT_BYTES,     Alo, m0, k0, K, tid);
        load_tile32(st + 2 * GMAT_BYTES, Bhi, n0, k0, K, tid);
        load_tile32(st + 3 * GMAT_BYTES, Blo, n0, k0, K, tid);
        CP_ASYNC_COMMIT();
    }

    for (int c = 0; c < nchunk; c++) {
        uint32_t st = sb + (c % GSTAGES) * GSTAGE_BYTES;
        CP_ASYNC_WAIT1();          // all groups but the most recent are done
        __syncthreads();           // everyone past compute(c-1); chunk c visible

        // delayed refill: chunk c+2 into stage (c+2)%3 (held chunk c-1, now free)
        if (c >= 1) {
            if (c + 2 < nchunk) {
                uint32_t st2 = sb + ((c + 2) % GSTAGES) * GSTAGE_BYTES;
                int k0 = (c + 2) * 32;
                load_tile32(st2,                  Ahi, m0, k0, K, tid);
                load_tile32(st2 + GMAT_BYTES,     Alo, m0, k0, K, tid);
                load_tile32(st2 + 2 * GMAT_BYTES, Bhi, n0, k0, K, tid);
                load_tile32(st2 + 3 * GMAT_BYTES, Blo, n0, k0, K, tid);
            }
            CP_ASYNC_COMMIT();     // empty group in tail keeps accounting uniform
        }

#pragma unroll
        for (int ks = 0; ks < 2; ks++) {
            const int ks2 = ks * 2;
            const uint32_t ca = (uint32_t)(((ks2 + a_c8) ^ selA) << 4);
            const uint32_t cb = (uint32_t)(((ks2 + b_c8) ^ selB) << 4);

            uint32_t ah[4][4], al[4][4];
#pragma unroll
            for (int mt = 0; mt < 4; mt++) {
                uint32_t ra = st + (uint32_t)((arow + mt * 16) * 64) + ca;
                ldsm4(ah[mt], ra);
                ldsm4(al[mt], ra + GMAT_BYTES);
            }
#pragma unroll
            for (int np = 0; np < 4; np++) {
                uint32_t bh[4], bl[4];
                uint32_t rb = st + 2 * GMAT_BYTES + (uint32_t)((brow + np * 16) * 64) + cb;
                ldsm4(bh, rb);
                ldsm4(bl, rb + GMAT_BYTES);
#pragma unroll
                for (int mt = 0; mt < 4; mt++)
#pragma unroll
                    for (int hf = 0; hf < 2; hf++) {
                        float* a4 = acc[mt][np * 2 + hf];
                        mma16816(a4, ah[mt], &bh[hf * 2]);
                        mma16816(a4, ah[mt], &bl[hf * 2]);
                        mma16816(a4, al[mt], &bh[hf * 2]);
                    }
            }
        }
    }

    const int crow = lane >> 2, ccol = (lane & 3) * 2;
#pragma unroll
    for (int mt = 0; mt < 4; mt++) {
        int rbase = m0 + wm * 64 + mt * 16 + crow;
#pragma unroll
        for (int nt = 0; nt < 8; nt++) {
            int cbase = n0 + wn * 64 + nt * 8 + ccol;
            float* d0 = C + (size_t)rbase * N + cbase;
            float* d1 = C + (size_t)(rbase + 8) * N + cbase;
            *(float2*)d0 = make_float2(acc[mt][nt][0], acc[mt][nt][1]);
            *(float2*)d1 = make_float2(acc[mt][nt][2], acc[mt][nt][3]);
        }
    }
}

// ================= split / transpose-split =================
__global__ __launch_bounds__(256) void split_kernel(const float* __restrict__ in,
                                                    __nv_bfloat16* __restrict__ hi,
                                                    __nv_bfloat16* __restrict__ lo, int n) {
    int i = blockIdx.x * blockDim.x + threadIdx.x;
    if (i >= n) return;
    float v = in[i];
    __nv_bfloat16 h = __float2bfloat16(v);
    hi[i] = h;
    lo[i] = __float2bfloat16(v - __bfloat162float(h));
}

__global__ __launch_bounds__(256) void tsplit_qkvg_kernel(const float* __restrict__ Wq,
                                                          const float* __restrict__ Wk,
                                                          const float* __restrict__ Wv,
                                                          const float* __restrict__ Wg,
                                                          __nv_bfloat16* __restrict__ Thi,
                                                          __nv_bfloat16* __restrict__ Tlo) {
    __shared__ float t[32][33];
    int n0 = blockIdx.x * 32, k0 = blockIdx.y * 32;
    const float* W;
    int srcN, ln0;
    if (n0 < 1024)       { W = Wq; srcN = 1024; ln0 = n0; }
    else if (n0 < 2048)  { W = Wk; srcN = 1024; ln0 = n0 - 1024; }
    else if (n0 < 4096)  { W = Wv; srcN = 2048; ln0 = n0 - 2048; }
    else                 { W = Wg; srcN = 2048; ln0 = n0 - 4096; }

    int tx = threadIdx.x & 31, ty = threadIdx.x >> 5;
#pragma unroll
    for (int i = ty; i < 32; i += 8)
        t[i][tx] = W[(size_t)(k0 + i) * srcN + ln0 + tx];
    __syncthreads();
#pragma unroll
    for (int i = ty; i < 32; i += 8) {
        float v = t[tx][i];
        __nv_bfloat16 h = __float2bfloat16(v);
        size_t oidx = (size_t)(n0 + i) * DD + k0 + tx;
        Thi[oidx] = h;
        Tlo[oidx] = __float2bfloat16(v - __bfloat162float(h));
    }
}

__global__ __launch_bounds__(256) void tsplit_kernel(const float* __restrict__ W,
                                                     __nv_bfloat16* __restrict__ Thi,
                                                     __nv_bfloat16* __restrict__ Tlo,
                                                     int K, int N) {
    __shared__ float t[32][33];
    int n0 = blockIdx.x * 32, k0 = blockIdx.y * 32;
    int tx = threadIdx.x & 31, ty = threadIdx.x >> 5;
#pragma unroll
    for (int i = ty; i < 32; i += 8)
        t[i][tx] = W[(size_t)(k0 + i) * N + n0 + tx];
    __syncthreads();
#pragma unroll
    for (int i = ty; i < 32; i += 8) {
        float v = t[tx][i];
        __nv_bfloat16 h = __float2bfloat16(v);
        size_t oidx = (size_t)(n0 + i) * K + k0 + tx;
        Thi[oidx] = h;
        Tlo[oidx] = __float2bfloat16(v - __bfloat162float(h));
    }
}

// ---------------- RoPE on the combined buffer --------------------------------
__global__ void rope_kernel(float* __restrict__ qkvg) {
    int idx = blockIdx.x * blockDim.x + threadIdx.x;
    const int total = BB * TT * HH * (DKk / 2);
    if (idx >= total) return;
    int i = idx & 63;
    int h = (idx >> 6) & (HH - 1);
    int t = (idx >> 9) & (TT - 1);
    int b = idx >> 20;

    float inv = powf(10000.f, -(float)i * (1.0f / 64.0f));
    float f = (float)t * inv;
    float s, c;
    sincosf(f, &s, &c);

    size_t base = ((size_t)b * TT + t) * NQKVG + h * DKk;
    const float sc = 0.08838834764831845f;
    float q1 = qkvg[base + i], q2 = qkvg[base + 64 + i];
    qkvg[base + i]      = (q1 * c - q2 * s) * sc;
    qkvg[base + 64 + i] = (q2 * c + q1 * s) * sc;
    size_t kb = base + 1024;
    float k1 = qkvg[kb + i], k2 = qkvg[kb + 64 + i];
    qkvg[kb + i]      = k1 * c - k2 * s;
    qkvg[kb + 64 + i] = k2 * c + k1 * s;
}

// ================= retention, 4 parallel phases ============

// Phase A: attn = (q@k^T)*M
#define ATTN_SMEM ((2 * 64 * 129 + 64) * 4)
__global__ __launch_bounds__(256) void ret_attn_kernel(const float* __restrict__ qkvg,
                                                       float* __restrict__ attn_out) {
    const int n = blockIdx.x, h = blockIdx.y, b = blockIdx.z;
    const int tid = threadIdx.x;
    extern __shared__ float sm[];
    float* qs   = sm;
    float* ks   = qs + 64 * 129;
    float* gpow = ks + 64 * 129;

    const float gamma = 1.0f - exp2f(-5.0f - (float)h);
    if (tid < 64) gpow[tid] = powf(gamma, (float)tid);

    const int t0 = n * CC;
    for (int e = tid; e < 64 * 128; e += 256) {
        int i = e >> 7, dk = e & 127;
        size_t gi = ((size_t)b * TT + t0 + i) * NQKVG + h * DKk + dk;
        qs[i * 129 + dk] = qkvg[gi];
        ks[i * 129 + dk] = qkvg[gi + 1024];
    }
    __syncthreads();

    const int ti = tid >> 4, te = tid & 15;
    float acc[4][4];
#pragma unroll
    for (int a = 0; a < 4; a++)
#pragma unroll
        for (int bq = 0; bq < 4; bq++) acc[a][bq] = 0.f;
    for (int dk = 0; dk < 128; dk++) {
        float ra[4], rb[4];
#pragma unroll
        for (int ii = 0; ii < 4; ii++) ra[ii] = qs[(ti * 4 + ii) * 129 + dk];
#pragma unroll
        for (int jj = 0; jj < 4; jj++) rb[jj] = ks[(te * 4 + jj) * 129 + dk];
#pragma unroll
        for (int ii = 0; ii < 4; ii++)
#pragma unroll
            for (int jj = 0; jj < 4; jj++) acc[ii][jj] += ra[ii] * rb[jj];
    }

    float* dst = attn_out + ((((size_t)b * HH + h) * NCHUNK + n) << 12);
#pragma unroll
    for (int ii = 0; ii < 4; ii++) {
        int i = ti * 4 + ii;
        float4 w;
        float* wp = &w.x;
#pragma unroll
        for (int jj = 0; jj < 4; jj++) {
            int j = te * 4 + jj;
            wp[jj] = (i >= j) ? acc[ii][jj] * gpow[i - j] : 0.f;
        }
        *(float4*)(dst + i * 64 + te * 4) = w;
    }
}

// Phase B: kv = (k*deck)^T @ v   (per DV slice of 128)
#define KV_SMEM ((64 * 129 + 64 * 130 + 64) * 4)
__global__ __launch_bounds__(256) void ret_kv_kernel(const float* __restrict__ qkvg,
                                                     float* __restrict__ kv_out) {
    const int sl = blockIdx.x & 1, n = blockIdx.x >> 1;
    const int h = blockIdx.y, b = blockIdx.z;
    const int tid = threadIdx.x;
    extern __shared__ float sm[];
    float* ks   = sm;               // 64*129
    float* vs   = ks + 64 * 129;    // 64*130 (pre-scaled by deck)
    float* deck = vs + 64 * 130;    // 64

    const float gamma = 1.0f - exp2f(-5.0f - (float)h);
    if (tid < 64) deck[tid] = powf(gamma, (float)(63 - tid));
    __syncthreads();

    const int t0 = n * CC;
    for (int e = tid; e < 64 * 128; e += 256) {
        int i = e >> 7, dk = e & 127;
        ks[i * 129 + dk] = qkvg[((size_t)b * TT + t0 + i) * NQKVG + 1024 + h * DKk + dk];
    }
    for (int e = tid; e < 64 * 128; e += 256) {
        int i = e >> 7, ev = e & 127;
        size_t gi = ((size_t)b * TT + t0 + i) * NQKVG + 2048 + h * DVv + sl * 128 + ev;
        vs[i * 130 + ev] = qkvg[gi] * deck[i];
    }
    __syncthreads();

    const int ti = tid >> 4, te = tid & 15;   // dk group of 8, ev group of 8
    float acc[8][8];
#pragma unroll
    for (int a = 0; a < 8; a++)
#pragma unroll
        for (int bq = 0; bq < 8; bq++) acc[a][bq] = 0.f;
    for (int j = 0; j < 64; j++) {
        float ra[8], rb[8];
#pragma unroll
        for (int dd = 0; dd < 8; dd++) ra[dd] = ks[j * 129 + ti * 8 + dd];
#pragma unroll
        for (int ee = 0; ee < 8; ee++) rb[ee] = vs[j * 130 + te * 8 + ee];
#pragma unroll
        for (int dd = 0; dd < 8; dd++)
#pragma unroll
            for (int ee = 0; ee < 8; ee++) acc[dd][ee] += ra[dd] * rb[ee];
    }

    float* dst = kv_out + ((((size_t)b * HH + h) * NCHUNK + n) * DKk) * DVv + sl * 128;
#pragma unroll
    for (int dd = 0; dd < 8; dd++) {
        int dk = ti * 8 + dd;
        float* row = dst + (size_t)dk * DVv + te * 8;
        *(float4*)(row)     = make_float4(acc[dd][0], acc[dd][1], acc[dd][2], acc[dd][3]);
        *(float4*)(row + 4) = make_float4(acc[dd][4], acc[dd][5], acc[dd][6], acc[dd][7]);
    }
}

// Phase C: prefix scan of kv -> Spre
__global__ __launch_bounds__(256) void ret_scan_kernel(const float* __restrict__ kv,
                                                       float* __restrict__ Spre) {
    const int idx = blockIdx.x * 256 + threadIdx.x;
    const int bh  = idx >> 15;
    const int pos = idx & 32767;
    const int h   = bh & (HH - 1);
    const float gamma = 1.0f - exp2f(-5.0f - (float)h);
    const float gC = powf(gamma, 64.0f);

    const size_t base = (size_t)bh * NCHUNK * 32768 + pos;
    float s = 0.f;
    Spre[base] = 0.f;
    for (int n = 1; n < NCHUNK; n++) {
        s = gC * s + kv[base + (size_t)(n - 1) * 32768];
        Spre[base + (size_t)n * 32768] = s;
    }
}

// Phase D: o = attn @ v + decq * (q @ S_pre)   (per DV slice of 128)
#define OUT_SMEM ((64 * 65 + 64 * 130 + 64 * 129 + 128 * 130 + 64) * 4)
__global__ __launch_bounds__(256) void ret_out_kernel(const float* __restrict__ qkvg,
                                                      const float* __restrict__ attn,
                                                      const float* __restrict__ Spre,
                                                      float* __restrict__ o) {
    const int sl = blockIdx.x & 1, n = blockIdx.x >> 1;
    const int h = blockIdx.y, b = blockIdx.z;
    const int tid = threadIdx.x;
    extern __shared__ float sm[];
    float* at   = sm;               // 64*65
    float* vs   = at + 64 * 65;     // 64*130
    float* qs   = vs + 64 * 130;    // 64*129
    float* Ss   = qs + 64 * 129;    // 128*130
    float* decq = Ss + 128 * 130;   // 64

    const float gamma = 1.0f - exp2f(-5.0f - (float)h);
    if (tid < 64) decq[tid] = powf(gamma, (float)(tid + 1));

    const int t0 = n * CC;
    const size_t bh = (size_t)b * HH + h;
    const float* asrc = attn + ((bh * NCHUNK + n) << 12);
    for (int e = tid; e < 64 * 64; e += 256) {
        int i = e >> 6, j = e & 63;
        at[i * 65 + j] = asrc[e];
    }
    for (int e = tid; e < 64 * 128; e += 256) {
        int i = e >> 7, ev = e & 127;
        vs[i * 130 + ev] = qkvg[((size_t)b * TT + t0 + i) * NQKVG + 2048 + h * DVv + sl * 128 + ev];
    }
    for (int e = tid; e < 64 * 128; e += 256) {
        int i = e >> 7, dk = e & 127;
        qs[i * 129 + dk] = qkvg[((size_t)b * TT + t0 + i) * NQKVG + h * DKk + dk];
    }
    const float* ssrc = Spre + ((bh * NCHUNK + n) * DKk) * DVv + sl * 128;
    for (int e = tid; e < 128 * 128; e += 256) {
        int dk = e >> 7, ev = e & 127;
        Ss[dk * 130 + ev] = ssrc[(size_t)dk * DVv + ev];
    }
    __syncthreads();

    const int ti = tid >> 4, te = tid & 15;   // i group of 4, ev group of 8
    float aI[4][8], aS[4][8];
#pragma unroll
    for (int a = 0; a < 4; a++)
#pragma unroll
        for (int bq = 0; bq < 8; bq++) { aI[a][bq] = 0.f; aS[a][bq] = 0.f; }

    for (int j = 0; j < 64; j++) {
        float ra[4], rb[8];
#pragma unroll
        for (int ii = 0; ii < 4; ii++) ra[ii] = at[(ti * 4 + ii) * 65 + j];
#pragma unroll
        for (int ee = 0; ee < 8; ee++) rb[ee] = vs[j * 130 + te * 8 + ee];
#pragma unroll
        for (int ii = 0; ii < 4; ii++)
#pragma unroll
            for (int ee = 0; ee < 8; ee++) aI[ii][ee] += ra[ii] * rb[ee];
    }
    for (int dk = 0; dk < 128; dk++) {
        float ra[4], rb[8];
#pragma unroll
        for (int ii = 0; ii < 4; ii++) ra[ii] = qs[(ti * 4 + ii) * 129 + dk];
#pragma unroll
        for (int ee = 0; ee < 8; ee++) rb[ee] = Ss[dk * 130 + te * 8 + ee];
#pragma unroll
        for (int ii = 0; ii < 4; ii++)
#pragma unroll
            for (int ee = 0; ee < 8; ee++) aS[ii][ee] += ra[ii] * rb[ee];
    }

#pragma unroll
    for (int ii = 0; ii < 4; ii++) {
        int i = ti * 4 + ii;
        float dq = decq[i];
        size_t base = (((size_t)b * TT + t0 + i) * HH + h) * DVv + sl * 128 + te * 8;
        *(float4*)(&o[base])     = make_float4(aI[ii][0] + dq * aS[ii][0],
                                               aI[ii][1] + dq * aS[ii][1],
                                               aI[ii][2] + dq * aS[ii][2],
                                               aI[ii][3] + dq * aS[ii][3]);
        *(float4*)(&o[base + 4]) = make_float4(aI[ii][4] + dq * aS[ii][4],
                                               aI[ii][5] + dq * aS[ii][5],
                                               aI[ii][6] + dq * aS[ii][6],
                                               aI[ii][7] + dq * aS[ii][7]);
    }
}

// ---------------- RMSNorm + swish gate + bf16 split ----
__global__ __launch_bounds__(256) void normgate_split_kernel(const float* __restrict__ o,
                                                             const float* __restrict__ qkvg,
                                                             const float* __restrict__ norm_w,
                                                             __nv_bfloat16* __restrict__ ohi,
                                                             __nv_bfloat16* __restrict__ olo) {
    int warp = (blockIdx.x * blockDim.x + threadIdx.x) >> 5;
    int lane = threadIdx.x & 31;
    if (warp >= MROWS * HH) return;
    size_t base  = (size_t)warp * DVv;
    size_t gbase = (size_t)(warp >> 3) * NQKVG + 4096 + (size_t)(warp & 7) * DVv;

    float vals[8];
    float ss = 0.f;
#pragma unroll
    for (int r = 0; r < 8; r++) {
        vals[r] = o[base + lane + 32 * r];
        ss += vals[r] * vals[r];
    }
#pragma unroll
    for (int off = 16; off; off >>= 1) ss += __shfl_xor_sync(0xFFFFFFFFu, ss, off);
    float inv = rsqrtf(ss * (1.0f / 256.0f) + 1e-5f);

#pragma unroll
    for (int r = 0; r < 8; r++) {
        int ev = lane + 32 * r;
        float gv = qkvg[gbase + ev];
        float sg = 1.f / (1.f + expf(-gv));
        float res = vals[r] * inv * norm_w[ev] * gv * sg;
        __nv_bfloat16 h = __float2bfloat16(res);
        ohi[base + ev] = h;
        olo[base + ev] = __float2bfloat16(res - __bfloat162float(h));
    }
}

// ---------------- launch ----------------
static void launch_gemm(const __nv_bfloat16* Ahi, const __nv_bfloat16* Alo,
                        const __nv_bfloat16* Bhi, const __nv_bfloat16* Blo,
                        float* C, int M, int N, int K) {
    gemm_split_mma<<<dim3(N / 128, M / 128), 128, GEMM_SMEM_BYTES>>>(Ahi, Alo, Bhi, Blo, C, M, N, K);
}

extern "C" void kernel_launch(void* const* d_in, const int* in_sizes, int n_in,
                              void* d_out, int out_size) {
    const float* x      = (const float*)d_in[0];
    const float* Wq     = (const float*)d_in[1];
    const float* Wk     = (const float*)d_in[2];
    const float* Wv     = (const float*)d_in[3];
    const float* Wg     = (const float*)d_in[4];
    const float* Wo     = (const float*)d_in[5];
    const float* norm_w = (const float*)d_in[6];
    float* out = (float*)d_out;

    float *qkvg, *o, *attn, *kv, *S;
    cudaGetSymbolAddress((void**)&qkvg, g_qkvg);
    cudaGetSymbolAddress((void**)&o, g_o);
    cudaGetSymbolAddress((void**)&attn, g_attn);
    cudaGetSymbolAddress((void**)&kv, g_kv);
    cudaGetSymbolAddress((void**)&S, g_S);
    __nv_bfloat16 *xhi, *xlo, *ohi, *olo, *wallh, *walll, *woh, *wol;
    cudaGetSymbolAddress((void**)&xhi, g_xhi);
    cudaGetSymbolAddress((void**)&xlo, g_xlo);
    cudaGetSymbolAddress((void**)&ohi, g_ohi);
    cudaGetSymbolAddress((void**)&olo, g_olo);
    cudaGetSymbolAddress((void**)&wallh, g_wall_hi);
    cudaGetSymbolAddress((void**)&walll, g_wall_lo);
    cudaGetSymbolAddress((void**)&woh, g_wo_hi);
    cudaGetSymbolAddress((void**)&wol, g_wo_lo);

    cudaFuncSetAttribute(gemm_split_mma, cudaFuncAttributeMaxDynamicSharedMemorySize, GEMM_SMEM_BYTES);
    cudaFuncSetAttribute(ret_attn_kernel, cudaFuncAttributeMaxDynamicSharedMemorySize, ATTN_SMEM);
    cudaFuncSetAttribute(ret_kv_kernel, cudaFuncAttributeMaxDynamicSharedMemorySize, KV_SMEM);
    cudaFuncSetAttribute(ret_out_kernel, cudaFuncAttributeMaxDynamicSharedMemorySize, OUT_SMEM);

    // split inputs + transpose-split weights
    {
        int n = MROWS * DD;
        split_kernel<<<(n + 255) / 256, 256>>>(x, xhi, xlo, n);
    }
    tsplit_qkvg_kernel<<<dim3(NQKVG / 32, DD / 32), 256>>>(Wq, Wk, Wv, Wg, wallh, walll);
    tsplit_kernel<<<dim3(DD / 32, 2 * DD / 32), 256>>>(Wo, woh, wol, 2 * DD, DD);

    // combined projection GEMM (q|k|v|g)
    launch_gemm(xhi, xlo, wallh, walll, qkvg, MROWS, NQKVG, DD);

    // rope + scale (on combined buffer)
    {
        int total = BB * TT * HH * (DKk / 2);
        rope_kernel<<<(total + 255) / 256, 256>>>(qkvg);
    }

    // retention: 4 parallel phases
    ret_attn_kernel<<<dim3(NCHUNK, HH, BB), 256, ATTN_SMEM>>>(qkvg, attn);
    ret_kv_kernel<<<dim3(2 * NCHUNK, HH, BB), 256, KV_SMEM>>>(qkvg, kv);
    ret_scan_kernel<<<(NBH * DKk * DVv) / 256, 256>>>(kv, S);
    ret_out_kernel<<<dim3(2 * NCHUNK, HH, BB), 256, OUT_SMEM>>>(qkvg, attn, S, o);

    // rmsnorm + gate + split (fused)
    {
        int warps = MROWS * HH;
        normgate_split_kernel<<<(warps * 32 + 255) / 256, 256>>>(o, qkvg, norm_w, ohi, olo);
    }

    // output projection on tensor cores
    launch_gemm(ohi, olo, woh, wol, out, MROWS, DD, 2 * DD);
}

// round 10
// speedup vs baseline: 1.1721x; 1.1721x over previous
#include <cuda_runtime.h>
#include <cuda_bf16.h>
#include <math.h>
#include <stdint.h>

// ---------------- problem constants ----------------
#define BB 4
#define TT 2048
#define DD 1024
#define HH 8
#define DKk 128
#define DVv 256
#define CC 64
#define NCHUNK (TT / CC)   // 32
#define MROWS (BB * TT)    // 8192
#define NBH (BB * HH)      // 32
#define NQKVG 6144         // q(1024) | k(1024) | v(2048) | g(2048)

// ---------------- scratch (no runtime allocation allowed) ----------------
__device__ float g_qkvg[MROWS * NQKVG];
__device__ float g_o[MROWS * HH * DVv];

// retention intermediates
__device__ float g_attn[NBH * NCHUNK * CC * CC];
__device__ float g_kv[NBH * NCHUNK * DKk * DVv];
__device__ float g_S[NBH * NCHUNK * DKk * DVv];

// bf16 split operands
__device__ __nv_bfloat16 g_xhi[MROWS * DD];
__device__ __nv_bfloat16 g_xlo[MROWS * DD];
__device__ __nv_bfloat16 g_ohi[MROWS * HH * DVv];
__device__ __nv_bfloat16 g_olo[MROWS * HH * DVv];
// transposed weights [N, K]
__device__ __nv_bfloat16 g_wall_hi[NQKVG * DD], g_wall_lo[NQKVG * DD];
__device__ __nv_bfloat16 g_wo_hi[2 * DD * DD],  g_wo_lo[2 * DD * DD];

// ================= PTX helpers (plain sm_80+ ISA only) =================
__device__ __forceinline__ uint32_t smem_u32(const void* p) {
    uint32_t a;
    asm("{ .reg .u64 t; cvta.to.shared.u64 t, %1; cvt.u32.u64 %0, t; }" : "=r"(a) : "l"(p));
    return a;
}
#define CP_ASYNC16(dst, src) \
    asm volatile("cp.async.cg.shared.global [%0], [%1], 16;" :: "r"(dst), "l"(src))
#define CP_ASYNC_COMMIT() asm volatile("cp.async.commit_group;" ::: "memory")
#define CP_ASYNC_WAIT1() asm volatile("cp.async.wait_group 1;" ::: "memory")

__device__ __forceinline__ void ldsm4(uint32_t* r, uint32_t addr) {
    asm volatile("ldmatrix.sync.aligned.m8n8.x4.shared.b16 {%0,%1,%2,%3}, [%4];"
        : "=r"(r[0]), "=r"(r[1]), "=r"(r[2]), "=r"(r[3]) : "r"(addr));
}
__device__ __forceinline__ void mma16816(float* c, const uint32_t* a, const uint32_t* b) {
    asm volatile("mma.sync.aligned.m16n8k16.row.col.f32.bf16.bf16.f32 "
        "{%0,%1,%2,%3}, {%4,%5,%6,%7}, {%8,%9}, {%0,%1,%2,%3};"
        : "+f"(c[0]), "+f"(c[1]), "+f"(c[2]), "+f"(c[3])
        : "r"(a[0]), "r"(a[1]), "r"(a[2]), "r"(a[3]), "r"(b[0]), "r"(b[1]));
}

// ================= split-bf16 tensor-core GEMM =================
// single-barrier delayed-refill 3-stage pipeline (verified win in R9)
#define GSTAGES 3
#define GMAT_BYTES (128 * 64)
#define GSTAGE_BYTES (4 * GMAT_BYTES)
#define GEMM_SMEM_BYTES (GSTAGES * GSTAGE_BYTES)

__device__ __forceinline__ uint32_t swz(int row, int c16) {
    return (uint32_t)(row * 64 + ((c16 ^ ((row >> 1) & 3)) << 4));
}

__device__ __forceinline__ void load_tile32(uint32_t dst, const __nv_bfloat16* src,
                                            int row0, int k0, int ldk, int tid) {
    const char* gbase = (const char*)(src + (size_t)row0 * ldk + k0);
    const size_t rowb = (size_t)ldk * 2;
#pragma unroll
    for (int j = 0; j < 4; j++) {
        int e = tid + j * 128;
        int r = e >> 2, c16 = e & 3;
        CP_ASYNC16(dst + swz(r, c16), gbase + (size_t)r * rowb + c16 * 16);
    }
}

__global__ __launch_bounds__(128, 2) void gemm_split_mma(
    const __nv_bfloat16* __restrict__ Ahi, const __nv_bfloat16* __restrict__ Alo,
    const __nv_bfloat16* __restrict__ Bhi, const __nv_bfloat16* __restrict__ Blo,
    float* __restrict__ C, int M, int N, int K) {
    extern __shared__ char smem[];
    const uint32_t sb = smem_u32(smem);
    const int tid = threadIdx.x, lane = tid & 31, wid = tid >> 5;
    const int wm = wid & 1, wn = wid >> 1;
    const int m0 = blockIdx.y * 128, n0 = blockIdx.x * 128;
    const int nchunk = K >> 5;

    const int a_row = (lane & 7) + 8 * ((lane >> 3) & 1);
    const int a_c8  = lane >> 4;
    const int b_row = (lane & 7) + 8 * (lane >> 4);
    const int b_c8  = (lane >> 3) & 1;

    const int arow = wm * 64 + a_row;
    const int selA = (arow >> 1) & 3;
    const int brow = wn * 64 + b_row;
    const int selB = (brow >> 1) & 3;

    float acc[4][8][4];
#pragma unroll
    for (int i = 0; i < 4; i++)
#pragma unroll
        for (int j = 0; j < 8; j++)
#pragma unroll
            for (int r = 0; r < 4; r++) acc[i][j][r] = 0.f;

    // prologue: chunks 0..2 into stages 0..2 (3 groups)
#pragma unroll
    for (int s = 0; s < GSTAGES; s++) {
        uint32_t st = sb + s * GSTAGE_BYTES;
        int k0 = s * 32;
        load_tile32(st,                  Ahi, m0, k0, K, tid);
        load_tile32(st + GMAT_BYTES,     Alo, m0, k0, K, tid);
        load_tile32(st + 2 * GMAT_BYTES, Bhi, n0, k0, K, tid);
        load_tile32(st + 3 * GMAT_BYTES, Blo, n0, k0, K, tid);
        CP_ASYNC_COMMIT();
    }

    for (int c = 0; c < nchunk; c++) {
        uint32_t st = sb + (c % GSTAGES) * GSTAGE_BYTES;
        CP_ASYNC_WAIT1();          // all groups but the most recent are done
        __syncthreads();           // everyone past compute(c-1); chunk c visible

        // delayed refill: chunk c+2 into stage (c+2)%3 (held chunk c-1, now free)
        if (c >= 1) {
            if (c + 2 < nchunk) {
                uint32_t st2 = sb + ((c + 2) % GSTAGES) * GSTAGE_BYTES;
                int k0 = (c + 2) * 32;
                load_tile32(st2,                  Ahi, m0, k0, K, tid);
                load_tile32(st2 + GMAT_BYTES,     Alo, m0, k0, K, tid);
                load_tile32(st2 + 2 * GMAT_BYTES, Bhi, n0, k0, K, tid);
                load_tile32(st2 + 3 * GMAT_BYTES, Blo, n0, k0, K, tid);
            }
            CP_ASYNC_COMMIT();     // empty group in tail keeps accounting uniform
        }

#pragma unroll
        for (int ks = 0; ks < 2; ks++) {
            const int ks2 = ks * 2;
            const uint32_t ca = (uint32_t)(((ks2 + a_c8) ^ selA) << 4);
            const uint32_t cb = (uint32_t)(((ks2 + b_c8) ^ selB) << 4);

            uint32_t ah[4][4], al[4][4];
#pragma unroll
            for (int mt = 0; mt < 4; mt++) {
                uint32_t ra = st + (uint32_t)((arow + mt * 16) * 64) + ca;
                ldsm4(ah[mt], ra);
                ldsm4(al[mt], ra + GMAT_BYTES);
            }
#pragma unroll
            for (int np = 0; np < 4; np++) {
                uint32_t bh[4], bl[4];
                uint32_t rb = st + 2 * GMAT_BYTES + (uint32_t)((brow + np * 16) * 64) + cb;
                ldsm4(bh, rb);
                ldsm4(bl, rb + GMAT_BYTES);
#pragma unroll
                for (int mt = 0; mt < 4; mt++)
#pragma unroll
                    for (int hf = 0; hf < 2; hf++) {
                        float* a4 = acc[mt][np * 2 + hf];
                        mma16816(a4, ah[mt], &bh[hf * 2]);
                        mma16816(a4, ah[mt], &bl[hf * 2]);
                        mma16816(a4, al[mt], &bh[hf * 2]);
                    }
            }
        }
    }

    const int crow = lane >> 2, ccol = (lane & 3) * 2;
#pragma unroll
    for (int mt = 0; mt < 4; mt++) {
        int rbase = m0 + wm * 64 + mt * 16 + crow;
#pragma unroll
        for (int nt = 0; nt < 8; nt++) {
            int cbase = n0 + wn * 64 + nt * 8 + ccol;
            float* d0 = C + (size_t)rbase * N + cbase;
            float* d1 = C + (size_t)(rbase + 8) * N + cbase;
            *(float2*)d0 = make_float2(acc[mt][nt][0], acc[mt][nt][1]);
            *(float2*)d1 = make_float2(acc[mt][nt][2], acc[mt][nt][3]);
        }
    }
}

// ================= split / transpose-split =================
__global__ __launch_bounds__(256) void split_kernel(const float* __restrict__ in,
                                                    __nv_bfloat16* __restrict__ hi,
                                                    __nv_bfloat16* __restrict__ lo, int n) {
    int i = blockIdx.x * blockDim.x + threadIdx.x;
    if (i >= n) return;
    float v = in[i];
    __nv_bfloat16 h = __float2bfloat16(v);
    hi[i] = h;
    lo[i] = __float2bfloat16(v - __bfloat162float(h));
}

__global__ __launch_bounds__(256) void tsplit_qkvg_kernel(const float* __restrict__ Wq,
                                                          const float* __restrict__ Wk,
                                                          const float* __restrict__ Wv,
                                                          const float* __restrict__ Wg,
                                                          __nv_bfloat16* __restrict__ Thi,
                                                          __nv_bfloat16* __restrict__ Tlo) {
    __shared__ float t[32][33];
    int n0 = blockIdx.x * 32, k0 = blockIdx.y * 32;
    const float* W;
    int srcN, ln0;
    if (n0 < 1024)       { W = Wq; srcN = 1024; ln0 = n0; }
    else if (n0 < 2048)  { W = Wk; srcN = 1024; ln0 = n0 - 1024; }
    else if (n0 < 4096)  { W = Wv; srcN = 2048; ln0 = n0 - 2048; }
    else                 { W = Wg; srcN = 2048; ln0 = n0 - 4096; }

    int tx = threadIdx.x & 31, ty = threadIdx.x >> 5;
#pragma unroll
    for (int i = ty; i < 32; i += 8)
        t[i][tx] = W[(size_t)(k0 + i) * srcN + ln0 + tx];
    __syncthreads();
#pragma unroll
    for (int i = ty; i < 32; i += 8) {
        float v = t[tx][i];
        __nv_bfloat16 h = __float2bfloat16(v);
        size_t oidx = (size_t)(n0 + i) * DD + k0 + tx;
        Thi[oidx] = h;
        Tlo[oidx] = __float2bfloat16(v - __bfloat162float(h));
    }
}

__global__ __launch_bounds__(256) void tsplit_kernel(const float* __restrict__ W,
                                                     __nv_bfloat16* __restrict__ Thi,
                                                     __nv_bfloat16* __restrict__ Tlo,
                                                     int K, int N) {
    __shared__ float t[32][33];
    int n0 = blockIdx.x * 32, k0 = blockIdx.y * 32;
    int tx = threadIdx.x & 31, ty = threadIdx.x >> 5;
#pragma unroll
    for (int i = ty; i < 32; i += 8)
        t[i][tx] = W[(size_t)(k0 + i) * N + n0 + tx];
    __syncthreads();
#pragma unroll
    for (int i = ty; i < 32; i += 8) {
        float v = t[tx][i];
        __nv_bfloat16 h = __float2bfloat16(v);
        size_t oidx = (size_t)(n0 + i) * K + k0 + tx;
        Thi[oidx] = h;
        Tlo[oidx] = __float2bfloat16(v - __bfloat162float(h));
    }
}

// ---------------- RoPE on the combined buffer --------------------------------
__global__ void rope_kernel(float* __restrict__ qkvg) {
    int idx = blockIdx.x * blockDim.x + threadIdx.x;
    const int total = BB * TT * HH * (DKk / 2);
    if (idx >= total) return;
    int i = idx & 63;
    int h = (idx >> 6) & (HH - 1);
    int t = (idx >> 9) & (TT - 1);
    int b = idx >> 20;

    float inv = powf(10000.f, -(float)i * (1.0f / 64.0f));
    float f = (float)t * inv;
    float s, c;
    sincosf(f, &s, &c);

    size_t base = ((size_t)b * TT + t) * NQKVG + h * DKk;
    const float sc = 0.08838834764831845f;
    float q1 = qkvg[base + i], q2 = qkvg[base + 64 + i];
    qkvg[base + i]      = (q1 * c - q2 * s) * sc;
    qkvg[base + 64 + i] = (q2 * c + q1 * s) * sc;
    size_t kb = base + 1024;
    float k1 = qkvg[kb + i], k2 = qkvg[kb + 64 + i];
    qkvg[kb + i]      = k1 * c - k2 * s;
    qkvg[kb + 64 + i] = k2 * c + k1 * s;
}

// ================= retention, 4 parallel phases (R8 64-wide restored) ========

// Phase A: attn = (q@k^T)*M
#define ATTN_SMEM ((2 * 64 * 129 + 64) * 4)
__global__ __launch_bounds__(256) void ret_attn_kernel(const float* __restrict__ qkvg,
                                                       float* __restrict__ attn_out) {
    const int n = blockIdx.x, h = blockIdx.y, b = blockIdx.z;
    const int tid = threadIdx.x;
    extern __shared__ float sm[];
    float* qs   = sm;
    float* ks   = qs + 64 * 129;
    float* gpow = ks + 64 * 129;

    const float gamma = 1.0f - exp2f(-5.0f - (float)h);
    if (tid < 64) gpow[tid] = powf(gamma, (float)tid);

    const int t0 = n * CC;
    for (int e = tid; e < 64 * 128; e += 256) {
        int i = e >> 7, dk = e & 127;
        size_t gi = ((size_t)b * TT + t0 + i) * NQKVG + h * DKk + dk;
        qs[i * 129 + dk] = qkvg[gi];
        ks[i * 129 + dk] = qkvg[gi + 1024];
    }
    __syncthreads();

    const int ti = tid >> 4, te = tid & 15;
    float acc[4][4];
#pragma unroll
    for (int a = 0; a < 4; a++)
#pragma unroll
        for (int bq = 0; bq < 4; bq++) acc[a][bq] = 0.f;
    for (int dk = 0; dk < 128; dk++) {
        float ra[4], rb[4];
#pragma unroll
        for (int ii = 0; ii < 4; ii++) ra[ii] = qs[(ti * 4 + ii) * 129 + dk];
#pragma unroll
        for (int jj = 0; jj < 4; jj++) rb[jj] = ks[(te * 4 + jj) * 129 + dk];
#pragma unroll
        for (int ii = 0; ii < 4; ii++)
#pragma unroll
            for (int jj = 0; jj < 4; jj++) acc[ii][jj] += ra[ii] * rb[jj];
    }

    float* dst = attn_out + ((((size_t)b * HH + h) * NCHUNK + n) << 12);
#pragma unroll
    for (int ii = 0; ii < 4; ii++) {
        int i = ti * 4 + ii;
        float4 w;
        float* wp = &w.x;
#pragma unroll
        for (int jj = 0; jj < 4; jj++) {
            int j = te * 4 + jj;
            wp[jj] = (i >= j) ? acc[ii][jj] * gpow[i - j] : 0.f;
        }
        *(float4*)(dst + i * 64 + te * 4) = w;
    }
}

// Phase B: kv = (k*deck)^T @ v   (per DV slice of 64)
#define KV_SMEM ((64 * 129 + 64 * 65 + 64) * 4)
__global__ __launch_bounds__(256) void ret_kv_kernel(const float* __restrict__ qkvg,
                                                     float* __restrict__ kv_out) {
    const int sl = blockIdx.x & 3, n = blockIdx.x >> 2;
    const int h = blockIdx.y, b = blockIdx.z;
    const int tid = threadIdx.x;
    extern __shared__ float sm[];
    float* ks   = sm;
    float* vs   = ks + 64 * 129;
    float* deck = vs + 64 * 65;

    const float gamma = 1.0f - exp2f(-5.0f - (float)h);
    if (tid < 64) deck[tid] = powf(gamma, (float)(63 - tid));
    __syncthreads();

    const int t0 = n * CC;
    for (int e = tid; e < 64 * 128; e += 256) {
        int i = e >> 7, dk = e & 127;
        ks[i * 129 + dk] = qkvg[((size_t)b * TT + t0 + i) * NQKVG + 1024 + h * DKk + dk];
    }
    for (int e = tid; e < 64 * 64; e += 256) {
        int i = e >> 6, ev = e & 63;
        size_t gi = ((size_t)b * TT + t0 + i) * NQKVG + 2048 + h * DVv + sl * 64 + ev;
        vs[i * 65 + ev] = qkvg[gi] * deck[i];
    }
    __syncthreads();

    const int ti = tid >> 4, te = tid & 15;
    float acc[8][4];
#pragma unroll
    for (int a = 0; a < 8; a++)
#pragma unroll
        for (int bq = 0; bq < 4; bq++) acc[a][bq] = 0.f;
    for (int j = 0; j < 64; j++) {
        float ra[8], rb[4];
#pragma unroll
        for (int dd = 0; dd < 8; dd++) ra[dd] = ks[j * 129 + ti * 8 + dd];
#pragma unroll
        for (int ee = 0; ee < 4; ee++) rb[ee] = vs[j * 65 + te * 4 + ee];
#pragma unroll
        for (int dd = 0; dd < 8; dd++)
#pragma unroll
            for (int ee = 0; ee < 4; ee++) acc[dd][ee] += ra[dd] * rb[ee];
    }

    float* dst = kv_out + ((((size_t)b * HH + h) * NCHUNK + n) * DKk) * DVv + sl * 64;
#pragma unroll
    for (int dd = 0; dd < 8; dd++) {
        int dk = ti * 8 + dd;
        *(float4*)(dst + (size_t)dk * DVv + te * 4) =
            make_float4(acc[dd][0], acc[dd][1], acc[dd][2], acc[dd][3]);
    }
}

// Phase C: prefix scan of kv -> Spre
__global__ __launch_bounds__(256) void ret_scan_kernel(const float* __restrict__ kv,
                                                       float* __restrict__ Spre) {
    const int idx = blockIdx.x * 256 + threadIdx.x;
    const int bh  = idx >> 15;
    const int pos = idx & 32767;
    const int h   = bh & (HH - 1);
    const float gamma = 1.0f - exp2f(-5.0f - (float)h);
    const float gC = powf(gamma, 64.0f);

    const size_t base = (size_t)bh * NCHUNK * 32768 + pos;
    float s = 0.f;
    Spre[base] = 0.f;
    for (int n = 1; n < NCHUNK; n++) {
        s = gC * s + kv[base + (size_t)(n - 1) * 32768];
        Spre[base + (size_t)n * 32768] = s;
    }
}

// Phase D: o = attn @ v + decq * (q @ S_pre)   (per DV slice of 64)
#define OUT_SMEM ((64 * 65 + 64 * 65 + 64 * 129 + 128 * 65 + 64) * 4)
__global__ __launch_bounds__(256) void ret_out_kernel(const float* __restrict__ qkvg,
                                                      const float* __restrict__ attn,
                                                      const float* __restrict__ Spre,
                                                      float* __restrict__ o) {
    const int sl = blockIdx.x & 3, n = blockIdx.x >> 2;
    const int h = blockIdx.y, b = blockIdx.z;
    const int tid = threadIdx.x;
    extern __shared__ float sm[];
    float* at   = sm;
    float* vs   = at + 64 * 65;
    float* qs   = vs + 64 * 65;
    float* Ss   = qs + 64 * 129;
    float* decq = Ss + 128 * 65;

    const float gamma = 1.0f - exp2f(-5.0f - (float)h);
    if (tid < 64) decq[tid] = powf(gamma, (float)(tid + 1));

    const int t0 = n * CC;
    const size_t bh = (size_t)b * HH + h;
    const float* asrc = attn + ((bh * NCHUNK + n) << 12);
    for (int e = tid; e < 64 * 64; e += 256) {
        int i = e >> 6, j = e & 63;
        at[i * 65 + j] = asrc[e];
        vs[i * 65 + j] = qkvg[((size_t)b * TT + t0 + i) * NQKVG + 2048 + h * DVv + sl * 64 + j];
    }
    for (int e = tid; e < 64 * 128; e += 256) {
        int i = e >> 7, dk = e & 127;
        qs[i * 129 + dk] = qkvg[((size_t)b * TT + t0 + i) * NQKVG + h * DKk + dk];
    }
    const float* ssrc = Spre + ((bh * NCHUNK + n) * DKk) * DVv + sl * 64;
    for (int e = tid; e < 128 * 64; e += 256) {
        int dk = e >> 6, ev = e & 63;
        Ss[dk * 65 + ev] = ssrc[(size_t)dk * DVv + ev];
    }
    __syncthreads();

    const int ti = tid >> 4, te = tid & 15;
    float aI[4][4], aS[4][4];
#pragma unroll
    for (int a = 0; a < 4; a++)
#pragma unroll
        for (int bq = 0; bq < 4; bq++) { aI[a][bq] = 0.f; aS[a][bq] = 0.f; }

    for (int j = 0; j < 64; j++) {
        float ra[4], rb[4];
#pragma unroll
        for (int ii = 0; ii < 4; ii++) ra[ii] = at[(ti * 4 + ii) * 65 + j];
#pragma unroll
        for (int ee = 0; ee < 4; ee++) rb[ee] = vs[j * 65 + te * 4 + ee];
#pragma unroll
        for (int ii = 0; ii < 4; ii++)
#pragma unroll
            for (int ee = 0; ee < 4; ee++) aI[ii][ee] += ra[ii] * rb[ee];
    }
    for (int dk = 0; dk < 128; dk++) {
        float ra[4], rb[4];
#pragma unroll
        for (int ii = 0; ii < 4; ii++) ra[ii] = qs[(ti * 4 + ii) * 129 + dk];
#pragma unroll
        for (int ee = 0; ee < 4; ee++) rb[ee] = Ss[dk * 65 + te * 4 + ee];
#pragma unroll
        for (int ii = 0; ii < 4; ii++)
#pragma unroll
            for (int ee = 0; ee < 4; ee++) aS[ii][ee] += ra[ii] * rb[ee];
    }

#pragma unroll
    for (int ii = 0; ii < 4; ii++) {
        int i = ti * 4 + ii;
        float dq = decq[i];
        size_t base = (((size_t)b * TT + t0 + i) * HH + h) * DVv + sl * 64 + te * 4;
        *(float4*)(&o[base]) = make_float4(aI[ii][0] + dq * aS[ii][0],
                                           aI[ii][1] + dq * aS[ii][1],
                                           aI[ii][2] + dq * aS[ii][2],
                                           aI[ii][3] + dq * aS[ii][3]);
    }
}

// ---------------- RMSNorm + swish gate + bf16 split ----
__global__ __launch_bounds__(256) void normgate_split_kernel(const float* __restrict__ o,
                                                             const float* __restrict__ qkvg,
                                                             const float* __restrict__ norm_w,
                                                             __nv_bfloat16* __restrict__ ohi,
                                                             __nv_bfloat16* __restrict__ olo) {
    int warp = (blockIdx.x * blockDim.x + threadIdx.x) >> 5;
    int lane = threadIdx.x & 31;
    if (warp >= MROWS * HH) return;
    size_t base  = (size_t)warp * DVv;
    size_t gbase = (size_t)(warp >> 3) * NQKVG + 4096 + (size_t)(warp & 7) * DVv;

    float vals[8];
    float ss = 0.f;
#pragma unroll
    for (int r = 0; r < 8; r++) {
        vals[r] = o[base + lane + 32 * r];
        ss += vals[r] * vals[r];
    }
#pragma unroll
    for (int off = 16; off; off >>= 1) ss += __shfl_xor_sync(0xFFFFFFFFu, ss, off);
    float inv = rsqrtf(ss * (1.0f / 256.0f) + 1e-5f);

#pragma unroll
    for (int r = 0; r < 8; r++) {
        int ev = lane + 32 * r;
        float gv = qkvg[gbase + ev];
        float sg = 1.f / (1.f + expf(-gv));
        float res = vals[r] * inv * norm_w[ev] * gv * sg;
        __nv_bfloat16 h = __float2bfloat16(res);
        ohi[base + ev] = h;
        olo[base + ev] = __float2bfloat16(res - __bfloat162float(h));
    }
}

// ---------------- launch ----------------
static void launch_gemm(const __nv_bfloat16* Ahi, const __nv_bfloat16* Alo,
                        const __nv_bfloat16* Bhi, const __nv_bfloat16* Blo,
                        float* C, int M, int N, int K) {
    gemm_split_mma<<<dim3(N / 128, M / 128), 128, GEMM_SMEM_BYTES>>>(Ahi, Alo, Bhi, Blo, C, M, N, K);
}

extern "C" void kernel_launch(void* const* d_in, const int* in_sizes, int n_in,
                              void* d_out, int out_size) {
    const float* x      = (const float*)d_in[0];
    const float* Wq     = (const float*)d_in[1];
    const float* Wk     = (const float*)d_in[2];
    const float* Wv     = (const float*)d_in[3];
    const float* Wg     = (const float*)d_in[4];
    const float* Wo     = (const float*)d_in[5];
    const float* norm_w = (const float*)d_in[6];
    float* out = (float*)d_out;

    float *qkvg, *o, *attn, *kv, *S;
    cudaGetSymbolAddress((void**)&qkvg, g_qkvg);
    cudaGetSymbolAddress((void**)&o, g_o);
    cudaGetSymbolAddress((void**)&attn, g_attn);
    cudaGetSymbolAddress((void**)&kv, g_kv);
    cudaGetSymbolAddress((void**)&S, g_S);
    __nv_bfloat16 *xhi, *xlo, *ohi, *olo, *wallh, *walll, *woh, *wol;
    cudaGetSymbolAddress((void**)&xhi, g_xhi);
    cudaGetSymbolAddress((void**)&xlo, g_xlo);
    cudaGetSymbolAddress((void**)&ohi, g_ohi);
    cudaGetSymbolAddress((void**)&olo, g_olo);
    cudaGetSymbolAddress((void**)&wallh, g_wall_hi);
    cudaGetSymbolAddress((void**)&walll, g_wall_lo);
    cudaGetSymbolAddress((void**)&woh, g_wo_hi);
    cudaGetSymbolAddress((void**)&wol, g_wo_lo);

    cudaFuncSetAttribute(gemm_split_mma, cudaFuncAttributeMaxDynamicSharedMemorySize, GEMM_SMEM_BYTES);
    cudaFuncSetAttribute(ret_attn_kernel, cudaFuncAttributeMaxDynamicSharedMemorySize, ATTN_SMEM);
    cudaFuncSetAttribute(ret_kv_kernel, cudaFuncAttributeMaxDynamicSharedMemorySize, KV_SMEM);
    cudaFuncSetAttribute(ret_out_kernel, cudaFuncAttributeMaxDynamicSharedMemorySize, OUT_SMEM);

    // split inputs + transpose-split weights
    {
        int n = MROWS * DD;
        split_kernel<<<(n + 255) / 256, 256>>>(x, xhi, xlo, n);
    }
    tsplit_qkvg_kernel<<<dim3(NQKVG / 32, DD / 32), 256>>>(Wq, Wk, Wv, Wg, wallh, walll);
    tsplit_kernel<<<dim3(DD / 32, 2 * DD / 32), 256>>>(Wo, woh, wol, 2 * DD, DD);

    // combined projection GEMM (q|k|v|g)
    launch_gemm(xhi, xlo, wallh, walll, qkvg, MROWS, NQKVG, DD);

    // rope + scale (on combined buffer)
    {
        int total = BB * TT * HH * (DKk / 2);
        rope_kernel<<<(total + 255) / 256, 256>>>(qkvg);
    }

    // retention: 4 parallel phases (R8 64-wide geometry)
    ret_attn_kernel<<<dim3(NCHUNK, HH, BB), 256, ATTN_SMEM>>>(qkvg, attn);
    ret_kv_kernel<<<dim3(4 * NCHUNK, HH, BB), 256, KV_SMEM>>>(qkvg, kv);
    ret_scan_kernel<<<(NBH * DKk * DVv) / 256, 256>>>(kv, S);
    ret_out_kernel<<<dim3(4 * NCHUNK, HH, BB), 256, OUT_SMEM>>>(qkvg, attn, S, o);

    // rmsnorm + gate + split (fused)
    {
        int warps = MROWS * HH;
        normgate_split_kernel<<<(warps * 32 + 255) / 256, 256>>>(o, qkvg, norm_w, ohi, olo);
    }

    // output projection on tensor cores
    launch_gemm(ohi, olo, woh, wol, out, MROWS, DD, 2 * DD);
}

// round 11
// speedup vs baseline: 1.2273x; 1.0471x over previous
#include <cuda_runtime.h>
#include <cuda_bf16.h>
#include <math.h>
#include <stdint.h>

// ---------------- problem constants ----------------
#define BB 4
#define TT 2048
#define DD 1024
#define HH 8
#define DKk 128
#define DVv 256
#define CC 64
#define NCHUNK (TT / CC)   // 32
#define MROWS (BB * TT)    // 8192
#define NBH (BB * HH)      // 32
#define NQKVG 6144         // q(1024) | k(1024) | v(2048) | g(2048)

// ---------------- scratch (no runtime allocation allowed) ----------------
__device__ float g_qkvg[MROWS * NQKVG];
__device__ float g_o[MROWS * HH * DVv];

// retention intermediates
__device__ float g_attn[NBH * NCHUNK * CC * CC];
__device__ float g_kv[NBH * NCHUNK * DKk * DVv];
__device__ float g_S[NBH * NCHUNK * DKk * DVv];

// bf16 split operands
__device__ __nv_bfloat16 g_xhi[MROWS * DD];
__device__ __nv_bfloat16 g_xlo[MROWS * DD];
__device__ __nv_bfloat16 g_ohi[MROWS * HH * DVv];
__device__ __nv_bfloat16 g_olo[MROWS * HH * DVv];
// transposed weights [N, K]
__device__ __nv_bfloat16 g_wall_hi[NQKVG * DD], g_wall_lo[NQKVG * DD];
__device__ __nv_bfloat16 g_wo_hi[2 * DD * DD],  g_wo_lo[2 * DD * DD];

// ================= PTX helpers (plain sm_80+ ISA only) =================
__device__ __forceinline__ uint32_t smem_u32(const void* p) {
    uint32_t a;
    asm("{ .reg .u64 t; cvta.to.shared.u64 t, %1; cvt.u32.u64 %0, t; }" : "=r"(a) : "l"(p));
    return a;
}
#define CP_ASYNC16(dst, src) \
    asm volatile("cp.async.cg.shared.global [%0], [%1], 16;" :: "r"(dst), "l"(src))
#define CP_ASYNC_COMMIT() asm volatile("cp.async.commit_group;" ::: "memory")
#define CP_ASYNC_WAIT1() asm volatile("cp.async.wait_group 1;" ::: "memory")

__device__ __forceinline__ void ldsm4(uint32_t* r, uint32_t addr) {
    asm volatile("ldmatrix.sync.aligned.m8n8.x4.shared.b16 {%0,%1,%2,%3}, [%4];"
        : "=r"(r[0]), "=r"(r[1]), "=r"(r[2]), "=r"(r[3]) : "r"(addr));
}
__device__ __forceinline__ void mma16816(float* c, const uint32_t* a, const uint32_t* b) {
    asm volatile("mma.sync.aligned.m16n8k16.row.col.f32.bf16.bf16.f32 "
        "{%0,%1,%2,%3}, {%4,%5,%6,%7}, {%8,%9}, {%0,%1,%2,%3};"
        : "+f"(c[0]), "+f"(c[1]), "+f"(c[2]), "+f"(c[3])
        : "r"(a[0]), "r"(a[1]), "r"(a[2]), "r"(a[3]), "r"(b[0]), "r"(b[1]));
}

// ================= split-bf16 tensor-core GEMM =================
// single-barrier delayed-refill 3-stage pipeline (verified win in R9)
#define GSTAGES 3
#define GMAT_BYTES (128 * 64)
#define GSTAGE_BYTES (4 * GMAT_BYTES)
#define GEMM_SMEM_BYTES (GSTAGES * GSTAGE_BYTES)

__device__ __forceinline__ uint32_t swz(int row, int c16) {
    return (uint32_t)(row * 64 + ((c16 ^ ((row >> 1) & 3)) << 4));
}

__device__ __forceinline__ void load_tile32(uint32_t dst, const __nv_bfloat16* src,
                                            int row0, int k0, int ldk, int tid) {
    const char* gbase = (const char*)(src + (size_t)row0 * ldk + k0);
    const size_t rowb = (size_t)ldk * 2;
#pragma unroll
    for (int j = 0; j < 4; j++) {
        int e = tid + j * 128;
        int r = e >> 2, c16 = e & 3;
        CP_ASYNC16(dst + swz(r, c16), gbase + (size_t)r * rowb + c16 * 16);
    }
}

__global__ __launch_bounds__(128, 2) void gemm_split_mma(
    const __nv_bfloat16* __restrict__ Ahi, const __nv_bfloat16* __restrict__ Alo,
    const __nv_bfloat16* __restrict__ Bhi, const __nv_bfloat16* __restrict__ Blo,
    float* __restrict__ C, int M, int N, int K) {
    extern __shared__ char smem[];
    const uint32_t sb = smem_u32(smem);
    const int tid = threadIdx.x, lane = tid & 31, wid = tid >> 5;
    const int wm = wid & 1, wn = wid >> 1;
    const int m0 = blockIdx.y * 128, n0 = blockIdx.x * 128;
    const int nchunk = K >> 5;

    const int a_row = (lane & 7) + 8 * ((lane >> 3) & 1);
    const int a_c8  = lane >> 4;
    const int b_row = (lane & 7) + 8 * (lane >> 4);
    const int b_c8  = (lane >> 3) & 1;

    const int arow = wm * 64 + a_row;
    const int selA = (arow >> 1) & 3;
    const int brow = wn * 64 + b_row;
    const int selB = (brow >> 1) & 3;

    float acc[4][8][4];
#pragma unroll
    for (int i = 0; i < 4; i++)
#pragma unroll
        for (int j = 0; j < 8; j++)
#pragma unroll
            for (int r = 0; r < 4; r++) acc[i][j][r] = 0.f;

    // prologue: chunks 0..2 into stages 0..2 (3 groups)
#pragma unroll
    for (int s = 0; s < GSTAGES; s++) {
        uint32_t st = sb + s * GSTAGE_BYTES;
        int k0 = s * 32;
        load_tile32(st,                  Ahi, m0, k0, K, tid);
        load_tile32(st + GMAT_BYTES,     Alo, m0, k0, K, tid);
        load_tile32(st + 2 * GMAT_BYTES, Bhi, n0, k0, K, tid);
        load_tile32(st + 3 * GMAT_BYTES, Blo, n0, k0, K, tid);
        CP_ASYNC_COMMIT();
    }

    for (int c = 0; c < nchunk; c++) {
        uint32_t st = sb + (c % GSTAGES) * GSTAGE_BYTES;
        CP_ASYNC_WAIT1();
        __syncthreads();

        // delayed refill: chunk c+2 into stage (c+2)%3
        if (c >= 1) {
            if (c + 2 < nchunk) {
                uint32_t st2 = sb + ((c + 2) % GSTAGES) * GSTAGE_BYTES;
                int k0 = (c + 2) * 32;
                load_tile32(st2,                  Ahi, m0, k0, K, tid);
                load_tile32(st2 + GMAT_BYTES,     Alo, m0, k0, K, tid);
                load_tile32(st2 + 2 * GMAT_BYTES, Bhi, n0, k0, K, tid);
                load_tile32(st2 + 3 * GMAT_BYTES, Blo, n0, k0, K, tid);
            }
            CP_ASYNC_COMMIT();
        }

#pragma unroll
        for (int ks = 0; ks < 2; ks++) {
            const int ks2 = ks * 2;
            const uint32_t ca = (uint32_t)(((ks2 + a_c8) ^ selA) << 4);
            const uint32_t cb = (uint32_t)(((ks2 + b_c8) ^ selB) << 4);

            uint32_t ah[4][4], al[4][4];
#pragma unroll
            for (int mt = 0; mt < 4; mt++) {
                uint32_t ra = st + (uint32_t)((arow + mt * 16) * 64) + ca;
                ldsm4(ah[mt], ra);
                ldsm4(al[mt], ra + GMAT_BYTES);
            }
#pragma unroll
            for (int np = 0; np < 4; np++) {
                uint32_t bh[4], bl[4];
                uint32_t rb = st + 2 * GMAT_BYTES + (uint32_t)((brow + np * 16) * 64) + cb;
                ldsm4(bh, rb);
                ldsm4(bl, rb + GMAT_BYTES);
#pragma unroll
                for (int mt = 0; mt < 4; mt++)
#pragma unroll
                    for (int hf = 0; hf < 2; hf++) {
                        float* a4 = acc[mt][np * 2 + hf];
                        mma16816(a4, ah[mt], &bh[hf * 2]);
                        mma16816(a4, ah[mt], &bl[hf * 2]);
                        mma16816(a4, al[mt], &bh[hf * 2]);
                    }
            }
        }
    }

    const int crow = lane >> 2, ccol = (lane & 3) * 2;
#pragma unroll
    for (int mt = 0; mt < 4; mt++) {
        int rbase = m0 + wm * 64 + mt * 16 + crow;
#pragma unroll
        for (int nt = 0; nt < 8; nt++) {
            int cbase = n0 + wn * 64 + nt * 8 + ccol;
            float* d0 = C + (size_t)rbase * N + cbase;
            float* d1 = C + (size_t)(rbase + 8) * N + cbase;
            *(float2*)d0 = make_float2(acc[mt][nt][0], acc[mt][nt][1]);
            *(float2*)d1 = make_float2(acc[mt][nt][2], acc[mt][nt][3]);
        }
    }
}

// ================= split / transpose-split =================
__global__ __launch_bounds__(256) void split_kernel(const float* __restrict__ in,
                                                    __nv_bfloat16* __restrict__ hi,
                                                    __nv_bfloat16* __restrict__ lo, int n) {
    int i = blockIdx.x * blockDim.x + threadIdx.x;
    if (i >= n) return;
    float v = in[i];
    __nv_bfloat16 h = __float2bfloat16(v);
    hi[i] = h;
    lo[i] = __float2bfloat16(v - __bfloat162float(h));
}

__global__ __launch_bounds__(256) void tsplit_qkvg_kernel(const float* __restrict__ Wq,
                                                          const float* __restrict__ Wk,
                                                          const float* __restrict__ Wv,
                                                          const float* __restrict__ Wg,
                                                          __nv_bfloat16* __restrict__ Thi,
                                                          __nv_bfloat16* __restrict__ Tlo) {
    __shared__ float t[32][33];
    int n0 = blockIdx.x * 32, k0 = blockIdx.y * 32;
    const float* W;
    int srcN, ln0;
    if (n0 < 1024)       { W = Wq; srcN = 1024; ln0 = n0; }
    else if (n0 < 2048)  { W = Wk; srcN = 1024; ln0 = n0 - 1024; }
    else if (n0 < 4096)  { W = Wv; srcN = 2048; ln0 = n0 - 2048; }
    else                 { W = Wg; srcN = 2048; ln0 = n0 - 4096; }

    int tx = threadIdx.x & 31, ty = threadIdx.x >> 5;
#pragma unroll
    for (int i = ty; i < 32; i += 8)
        t[i][tx] = W[(size_t)(k0 + i) * srcN + ln0 + tx];
    __syncthreads();
#pragma unroll
    for (int i = ty; i < 32; i += 8) {
        float v = t[tx][i];
        __nv_bfloat16 h = __float2bfloat16(v);
        size_t oidx = (size_t)(n0 + i) * DD + k0 + tx;
        Thi[oidx] = h;
        Tlo[oidx] = __float2bfloat16(v - __bfloat162float(h));
    }
}

__global__ __launch_bounds__(256) void tsplit_kernel(const float* __restrict__ W,
                                                     __nv_bfloat16* __restrict__ Thi,
                                                     __nv_bfloat16* __restrict__ Tlo,
                                                     int K, int N) {
    __shared__ float t[32][33];
    int n0 = blockIdx.x * 32, k0 = blockIdx.y * 32;
    int tx = threadIdx.x & 31, ty = threadIdx.x >> 5;
#pragma unroll
    for (int i = ty; i < 32; i += 8)
        t[i][tx] = W[(size_t)(k0 + i) * N + n0 + tx];
    __syncthreads();
#pragma unroll
    for (int i = ty; i < 32; i += 8) {
        float v = t[tx][i];
        __nv_bfloat16 h = __float2bfloat16(v);
        size_t oidx = (size_t)(n0 + i) * K + k0 + tx;
        Thi[oidx] = h;
        Tlo[oidx] = __float2bfloat16(v - __bfloat162float(h));
    }
}

// ---------------- RoPE on the combined buffer --------------------------------
__global__ void rope_kernel(float* __restrict__ qkvg) {
    int idx = blockIdx.x * blockDim.x + threadIdx.x;
    const int total = BB * TT * HH * (DKk / 2);
    if (idx >= total) return;
    int i = idx & 63;
    int h = (idx >> 6) & (HH - 1);
    int t = (idx >> 9) & (TT - 1);
    int b = idx >> 20;

    float inv = powf(10000.f, -(float)i * (1.0f / 64.0f));
    float f = (float)t * inv;
    float s, c;
    sincosf(f, &s, &c);

    size_t base = ((size_t)b * TT + t) * NQKVG + h * DKk;
    const float sc = 0.08838834764831845f;
    float q1 = qkvg[base + i], q2 = qkvg[base + 64 + i];
    qkvg[base + i]      = (q1 * c - q2 * s) * sc;
    qkvg[base + 64 + i] = (q2 * c + q1 * s) * sc;
    size_t kb = base + 1024;
    float k1 = qkvg[kb + i], k2 = qkvg[kb + 64 + i];
    qkvg[kb + i]      = k1 * c - k2 * s;
    qkvg[kb + 64 + i] = k2 * c + k1 * s;
}

// ================= retention, 4 parallel phases ========

// Phase A: attn = (q@k^T)*M   (unchanged — scalar loads; vectorizing conflicts)
#define ATTN_SMEM ((2 * 64 * 129 + 64) * 4)
__global__ __launch_bounds__(256) void ret_attn_kernel(const float* __restrict__ qkvg,
                                                       float* __restrict__ attn_out) {
    const int n = blockIdx.x, h = blockIdx.y, b = blockIdx.z;
    const int tid = threadIdx.x;
    extern __shared__ float sm[];
    float* qs   = sm;
    float* ks   = qs + 64 * 129;
    float* gpow = ks + 64 * 129;

    const float gamma = 1.0f - exp2f(-5.0f - (float)h);
    if (tid < 64) gpow[tid] = powf(gamma, (float)tid);

    const int t0 = n * CC;
    for (int e = tid; e < 64 * 128; e += 256) {
        int i = e >> 7, dk = e & 127;
        size_t gi = ((size_t)b * TT + t0 + i) * NQKVG + h * DKk + dk;
        qs[i * 129 + dk] = qkvg[gi];
        ks[i * 129 + dk] = qkvg[gi + 1024];
    }
    __syncthreads();

    const int ti = tid >> 4, te = tid & 15;
    float acc[4][4];
#pragma unroll
    for (int a = 0; a < 4; a++)
#pragma unroll
        for (int bq = 0; bq < 4; bq++) acc[a][bq] = 0.f;
    for (int dk = 0; dk < 128; dk++) {
        float ra[4], rb[4];
#pragma unroll
        for (int ii = 0; ii < 4; ii++) ra[ii] = qs[(ti * 4 + ii) * 129 + dk];
#pragma unroll
        for (int jj = 0; jj < 4; jj++) rb[jj] = ks[(te * 4 + jj) * 129 + dk];
#pragma unroll
        for (int ii = 0; ii < 4; ii++)
#pragma unroll
            for (int jj = 0; jj < 4; jj++) acc[ii][jj] += ra[ii] * rb[jj];
    }

    float* dst = attn_out + ((((size_t)b * HH + h) * NCHUNK + n) << 12);
#pragma unroll
    for (int ii = 0; ii < 4; ii++) {
        int i = ti * 4 + ii;
        float4 w;
        float* wp = &w.x;
#pragma unroll
        for (int jj = 0; jj < 4; jj++) {
            int j = te * 4 + jj;
            wp[jj] = (i >= j) ? acc[ii][jj] * gpow[i - j] : 0.f;
        }
        *(float4*)(dst + i * 64 + te * 4) = w;
    }
}

// Phase B: kv = (k*deck)^T @ v   (per DV slice of 64) — LDS.128 inner loop
#define KV_SMEM ((64 * 132 + 64 * 68 + 64) * 4)
__global__ __launch_bounds__(256) void ret_kv_kernel(const float* __restrict__ qkvg,
                                                     float* __restrict__ kv_out) {
    const int sl = blockIdx.x & 3, n = blockIdx.x >> 2;
    const int h = blockIdx.y, b = blockIdx.z;
    const int tid = threadIdx.x;
    extern __shared__ float sm[];
    float* ks   = sm;               // 64 x 132
    float* vs   = ks + 64 * 132;    // 64 x 68 (pre-scaled by deck)
    float* deck = vs + 64 * 68;     // 64

    const float gamma = 1.0f - exp2f(-5.0f - (float)h);
    if (tid < 64) deck[tid] = powf(gamma, (float)(63 - tid));
    __syncthreads();

    const int t0 = n * CC;
    for (int e = tid; e < 64 * 128; e += 256) {
        int i = e >> 7, dk = e & 127;
        ks[i * 132 + dk] = qkvg[((size_t)b * TT + t0 + i) * NQKVG + 1024 + h * DKk + dk];
    }
    for (int e = tid; e < 64 * 64; e += 256) {
        int i = e >> 6, ev = e & 63;
        size_t gi = ((size_t)b * TT + t0 + i) * NQKVG + 2048 + h * DVv + sl * 64 + ev;
        vs[i * 68 + ev] = qkvg[gi] * deck[i];
    }
    __syncthreads();

    const int ti = tid >> 4, te = tid & 15;
    float acc[8][4];
#pragma unroll
    for (int a = 0; a < 8; a++)
#pragma unroll
        for (int bq = 0; bq < 4; bq++) acc[a][bq] = 0.f;

    for (int j = 0; j < 64; j++) {
        float4 ka = *(const float4*)&ks[j * 132 + ti * 8];
        float4 kb = *(const float4*)&ks[j * 132 + ti * 8 + 4];
        float4 vb = *(const float4*)&vs[j * 68 + te * 4];
        float ra[8] = {ka.x, ka.y, ka.z, ka.w, kb.x, kb.y, kb.z, kb.w};
        float rb[4] = {vb.x, vb.y, vb.z, vb.w};
#pragma unroll
        for (int dd = 0; dd < 8; dd++)
#pragma unroll
            for (int ee = 0; ee < 4; ee++) acc[dd][ee] += ra[dd] * rb[ee];
    }

    float* dst = kv_out + ((((size_t)b * HH + h) * NCHUNK + n) * DKk) * DVv + sl * 64;
#pragma unroll
    for (int dd = 0; dd < 8; dd++) {
        int dk = ti * 8 + dd;
        *(float4*)(dst + (size_t)dk * DVv + te * 4) =
            make_float4(acc[dd][0], acc[dd][1], acc[dd][2], acc[dd][3]);
    }
}

// Phase C: prefix scan of kv -> Spre
__global__ __launch_bounds__(256) void ret_scan_kernel(const float* __restrict__ kv,
                                                       float* __restrict__ Spre) {
    const int idx = blockIdx.x * 256 + threadIdx.x;
    const int bh  = idx >> 15;
    const int pos = idx & 32767;
    const int h   = bh & (HH - 1);
    const float gamma = 1.0f - exp2f(-5.0f - (float)h);
    const float gC = powf(gamma, 64.0f);

    const size_t base = (size_t)bh * NCHUNK * 32768 + pos;
    float s = 0.f;
    Spre[base] = 0.f;
    for (int n = 1; n < NCHUNK; n++) {
        s = gC * s + kv[base + (size_t)(n - 1) * 32768];
        Spre[base + (size_t)n * 32768] = s;
    }
}

// Phase D: o = attn @ v + decq * (q @ S_pre)  (per DV slice of 64) — LDS.128
#define OUT_SMEM ((64 * 68 + 64 * 68 + 64 * 132 + 128 * 68 + 64) * 4)
__global__ __launch_bounds__(256) void ret_out_kernel(const float* __restrict__ qkvg,
                                                      const float* __restrict__ attn,
                                                      const float* __restrict__ Spre,
                                                      float* __restrict__ o) {
    const int sl = blockIdx.x & 3, n = blockIdx.x >> 2;
    const int h = blockIdx.y, b = blockIdx.z;
    const int tid = threadIdx.x;
    extern __shared__ float sm[];
    float* at   = sm;               // 64 x 68
    float* vs   = at + 64 * 68;     // 64 x 68
    float* qs   = vs + 64 * 68;     // 64 x 132
    float* Ss   = qs + 64 * 132;    // 128 x 68
    float* decq = Ss + 128 * 68;    // 64

    const float gamma = 1.0f - exp2f(-5.0f - (float)h);
    if (tid < 64) decq[tid] = powf(gamma, (float)(tid + 1));

    const int t0 = n * CC;
    const size_t bh = (size_t)b * HH + h;
    const float* asrc = attn + ((bh * NCHUNK + n) << 12);
    for (int e = tid; e < 64 * 64; e += 256) {
        int i = e >> 6, j = e & 63;
        at[i * 68 + j] = asrc[e];
        vs[i * 68 + j] = qkvg[((size_t)b * TT + t0 + i) * NQKVG + 2048 + h * DVv + sl * 64 + j];
    }
    for (int e = tid; e < 64 * 128; e += 256) {
        int i = e >> 7, dk = e & 127;
        qs[i * 132 + dk] = qkvg[((size_t)b * TT + t0 + i) * NQKVG + h * DKk + dk];
    }
    const float* ssrc = Spre + ((bh * NCHUNK + n) * DKk) * DVv + sl * 64;
    for (int e = tid; e < 128 * 64; e += 256) {
        int dk = e >> 6, ev = e & 63;
        Ss[dk * 68 + ev] = ssrc[(size_t)dk * DVv + ev];
    }
    __syncthreads();

    const int ti = tid >> 4, te = tid & 15;
    float aI[4][4], aS[4][4];
#pragma unroll
    for (int a = 0; a < 4; a++)
#pragma unroll
        for (int bq = 0; bq < 4; bq++) { aI[a][bq] = 0.f; aS[a][bq] = 0.f; }

    // aI: group j by 4, LDS.128, accumulation order j = jg*4+jj preserved
    for (int jg = 0; jg < 16; jg++) {
        float4 ra4[4];
#pragma unroll
        for (int ii = 0; ii < 4; ii++)
            ra4[ii] = *(const float4*)&at[(ti * 4 + ii) * 68 + jg * 4];
#pragma unroll
        for (int jj = 0; jj < 4; jj++) {
            float4 vb = *(const float4*)&vs[(jg * 4 + jj) * 68 + te * 4];
#pragma unroll
            for (int ii = 0; ii < 4; ii++) {
                float ra = ((const float*)&ra4[ii])[jj];
                aI[ii][0] += ra * vb.x;
                aI[ii][1] += ra * vb.y;
                aI[ii][2] += ra * vb.z;
                aI[ii][3] += ra * vb.w;
            }
        }
    }
    // aS: group dk by 4, same order preservation
    for (int dg = 0; dg < 32; dg++) {
        float4 ra4[4];
#pragma unroll
        for (int ii = 0; ii < 4; ii++)
            ra4[ii] = *(const float4*)&qs[(ti * 4 + ii) * 132 + dg * 4];
#pragma unroll
        for (int dd = 0; dd < 4; dd++) {
            float4 sb4 = *(const float4*)&Ss[(dg * 4 + dd) * 68 + te * 4];
#pragma unroll
            for (int ii = 0; ii < 4; ii++) {
                float ra = ((const float*)&ra4[ii])[dd];
                aS[ii][0] += ra * sb4.x;
                aS[ii][1] += ra * sb4.y;
                aS[ii][2] += ra * sb4.z;
                aS[ii][3] += ra * sb4.w;
            }
        }
    }

#pragma unroll
    for (int ii = 0; ii < 4; ii++) {
        int i = ti * 4 + ii;
        float dq = decq[i];
        size_t base = (((size_t)b * TT + t0 + i) * HH + h) * DVv + sl * 64 + te * 4;
        *(float4*)(&o[base]) = make_float4(aI[ii][0] + dq * aS[ii][0],
                                           aI[ii][1] + dq * aS[ii][1],
                                           aI[ii][2] + dq * aS[ii][2],
                                           aI[ii][3] + dq * aS[ii][3]);
    }
}

// ---------------- RMSNorm + swish gate + bf16 split ----
__global__ __launch_bounds__(256) void normgate_split_kernel(const float* __restrict__ o,
                                                             const float* __restrict__ qkvg,
                                                             const float* __restrict__ norm_w,
                                                             __nv_bfloat16* __restrict__ ohi,
                                                             __nv_bfloat16* __restrict__ olo) {
    int warp = (blockIdx.x * blockDim.x + threadIdx.x) >> 5;
    int lane = threadIdx.x & 31;
    if (warp >= MROWS * HH) return;
    size_t base  = (size_t)warp * DVv;
    size_t gbase = (size_t)(warp >> 3) * NQKVG + 4096 + (size_t)(warp & 7) * DVv;

    float vals[8];
    float ss = 0.f;
#pragma unroll
    for (int r = 0; r < 8; r++) {
        vals[r] = o[base + lane + 32 * r];
        ss += vals[r] * vals[r];
    }
#pragma unroll
    for (int off = 16; off; off >>= 1) ss += __shfl_xor_sync(0xFFFFFFFFu, ss, off);
    float inv = rsqrtf(ss * (1.0f / 256.0f) + 1e-5f);

#pragma unroll
    for (int r = 0; r < 8; r++) {
        int ev = lane + 32 * r;
        float gv = qkvg[gbase + ev];
        float sg = 1.f / (1.f + expf(-gv));
        float res = vals[r] * inv * norm_w[ev] * gv * sg;
        __nv_bfloat16 h = __float2bfloat16(res);
        ohi[base + ev] = h;
        olo[base + ev] = __float2bfloat16(res - __bfloat162float(h));
    }
}

// ---------------- launch ----------------
static void launch_gemm(const __nv_bfloat16* Ahi, const __nv_bfloat16* Alo,
                        const __nv_bfloat16* Bhi, const __nv_bfloat16* Blo,
                        float* C, int M, int N, int K) {
    gemm_split_mma<<<dim3(N / 128, M / 128), 128, GEMM_SMEM_BYTES>>>(Ahi, Alo, Bhi, Blo, C, M, N, K);
}

extern "C" void kernel_launch(void* const* d_in, const int* in_sizes, int n_in,
                              void* d_out, int out_size) {
    const float* x      = (const float*)d_in[0];
    const float* Wq     = (const float*)d_in[1];
    const float* Wk     = (const float*)d_in[2];
    const float* Wv     = (const float*)d_in[3];
    const float* Wg     = (const float*)d_in[4];
    const float* Wo     = (const float*)d_in[5];
    const float* norm_w = (const float*)d_in[6];
    float* out = (float*)d_out;

    float *qkvg, *o, *attn, *kv, *S;
    cudaGetSymbolAddress((void**)&qkvg, g_qkvg);
    cudaGetSymbolAddress((void**)&o, g_o);
    cudaGetSymbolAddress((void**)&attn, g_attn);
    cudaGetSymbolAddress((void**)&kv, g_kv);
    cudaGetSymbolAddress((void**)&S, g_S);
    __nv_bfloat16 *xhi, *xlo, *ohi, *olo, *wallh, *walll, *woh, *wol;
    cudaGetSymbolAddress((void**)&xhi, g_xhi);
    cudaGetSymbolAddress((void**)&xlo, g_xlo);
    cudaGetSymbolAddress((void**)&ohi, g_ohi);
    cudaGetSymbolAddress((void**)&olo, g_olo);
    cudaGetSymbolAddress((void**)&wallh, g_wall_hi);
    cudaGetSymbolAddress((void**)&walll, g_wall_lo);
    cudaGetSymbolAddress((void**)&woh, g_wo_hi);
    cudaGetSymbolAddress((void**)&wol, g_wo_lo);

    cudaFuncSetAttribute(gemm_split_mma, cudaFuncAttributeMaxDynamicSharedMemorySize, GEMM_SMEM_BYTES);
    cudaFuncSetAttribute(ret_attn_kernel, cudaFuncAttributeMaxDynamicSharedMemorySize, ATTN_SMEM);
    cudaFuncSetAttribute(ret_kv_kernel, cudaFuncAttributeMaxDynamicSharedMemorySize, KV_SMEM);
    cudaFuncSetAttribute(ret_out_kernel, cudaFuncAttributeMaxDynamicSharedMemorySize, OUT_SMEM);

    // split inputs + transpose-split weights
    {
        int n = MROWS * DD;
        split_kernel<<<(n + 255) / 256, 256>>>(x, xhi, xlo, n);
    }
    tsplit_qkvg_kernel<<<dim3(NQKVG / 32, DD / 32), 256>>>(Wq, Wk, Wv, Wg, wallh, walll);
    tsplit_kernel<<<dim3(DD / 32, 2 * DD / 32), 256>>>(Wo, woh, wol, 2 * DD, DD);

    // combined projection GEMM (q|k|v|g)
    launch_gemm(xhi, xlo, wallh, walll, qkvg, MROWS, NQKVG, DD);

    // rope + scale (on combined buffer)
    {
        int total = BB * TT * HH * (DKk / 2);
        rope_kernel<<<(total + 255) / 256, 256>>>(qkvg);
    }

    // retention: 4 parallel phases
    ret_attn_kernel<<<dim3(NCHUNK, HH, BB), 256, ATTN_SMEM>>>(qkvg, attn);
    ret_kv_kernel<<<dim3(4 * NCHUNK, HH, BB), 256, KV_SMEM>>>(qkvg, kv);
    ret_scan_kernel<<<(NBH * DKk * DVv) / 256, 256>>>(kv, S);
    ret_out_kernel<<<dim3(4 * NCHUNK, HH, BB), 256, OUT_SMEM>>>(qkvg, attn, S, o);

    // rmsnorm + gate + split (fused)
    {
        int warps = MROWS * HH;
        normgate_split_kernel<<<(warps * 32 + 255) / 256, 256>>>(o, qkvg, norm_w, ohi, olo);
    }

    // output projection on tensor cores
    launch_gemm(ohi, olo, woh, wol, out, MROWS, DD, 2 * DD);
}

// round 12
// speedup vs baseline: 1.2488x; 1.0175x over previous
#include <cuda_runtime.h>
#include <cuda_bf16.h>
#include <math.h>
#include <stdint.h>

// ---------------- problem constants ----------------
#define BB 4
#define TT 2048
#define DD 1024
#define HH 8
#define DKk 128
#define DVv 256
#define CC 64
#define NCHUNK (TT / CC)   // 32
#define MROWS (BB * TT)    // 8192
#define NBH (BB * HH)      // 32
#define NQKVG 6144         // q(1024) | k(1024) | v(2048) | g(2048)

// ---------------- scratch (no runtime allocation allowed) ----------------
__device__ float g_qkvg[MROWS * NQKVG];
__device__ float g_o[MROWS * HH * DVv];

// retention intermediates
__device__ float g_attn[NBH * NCHUNK * CC * CC];
__device__ float g_kv[NBH * NCHUNK * DKk * DVv];
__device__ float g_S[NBH * NCHUNK * DKk * DVv];

// bf16 split operands
__device__ __nv_bfloat16 g_xhi[MROWS * DD];
__device__ __nv_bfloat16 g_xlo[MROWS * DD];
__device__ __nv_bfloat16 g_ohi[MROWS * HH * DVv];
__device__ __nv_bfloat16 g_olo[MROWS * HH * DVv];
// transposed weights [N, K]
__device__ __nv_bfloat16 g_wall_hi[NQKVG * DD], g_wall_lo[NQKVG * DD];
__device__ __nv_bfloat16 g_wo_hi[2 * DD * DD],  g_wo_lo[2 * DD * DD];

// ================= PTX helpers (plain sm_80+ ISA only) =================
__device__ __forceinline__ uint32_t smem_u32(const void* p) {
    uint32_t a;
    asm("{ .reg .u64 t; cvta.to.shared.u64 t, %1; cvt.u32.u64 %0, t; }" : "=r"(a) : "l"(p));
    return a;
}
#define CP_ASYNC16(dst, src) \
    asm volatile("cp.async.cg.shared.global [%0], [%1], 16;" :: "r"(dst), "l"(src))
#define CP_ASYNC_COMMIT() asm volatile("cp.async.commit_group;" ::: "memory")
#define CP_ASYNC_WAIT1() asm volatile("cp.async.wait_group 1;" ::: "memory")

__device__ __forceinline__ void ldsm4(uint32_t* r, uint32_t addr) {
    asm volatile("ldmatrix.sync.aligned.m8n8.x4.shared.b16 {%0,%1,%2,%3}, [%4];"
        : "=r"(r[0]), "=r"(r[1]), "=r"(r[2]), "=r"(r[3]) : "r"(addr));
}
__device__ __forceinline__ void mma16816(float* c, const uint32_t* a, const uint32_t* b) {
    asm volatile("mma.sync.aligned.m16n8k16.row.col.f32.bf16.bf16.f32 "
        "{%0,%1,%2,%3}, {%4,%5,%6,%7}, {%8,%9}, {%0,%1,%2,%3};"
        : "+f"(c[0]), "+f"(c[1]), "+f"(c[2]), "+f"(c[3])
        : "r"(a[0]), "r"(a[1]), "r"(a[2]), "r"(a[3]), "r"(b[0]), "r"(b[1]));
}

// ================= split-bf16 tensor-core GEMM =================
// single-barrier delayed-refill 3-stage pipeline (verified win in R9)
#define GSTAGES 3
#define GMAT_BYTES (128 * 64)
#define GSTAGE_BYTES (4 * GMAT_BYTES)
#define GEMM_SMEM_BYTES (GSTAGES * GSTAGE_BYTES)

__device__ __forceinline__ uint32_t swz(int row, int c16) {
    return (uint32_t)(row * 64 + ((c16 ^ ((row >> 1) & 3)) << 4));
}

__device__ __forceinline__ void load_tile32(uint32_t dst, const __nv_bfloat16* src,
                                            int row0, int k0, int ldk, int tid) {
    const char* gbase = (const char*)(src + (size_t)row0 * ldk + k0);
    const size_t rowb = (size_t)ldk * 2;
#pragma unroll
    for (int j = 0; j < 4; j++) {
        int e = tid + j * 128;
        int r = e >> 2, c16 = e & 3;
        CP_ASYNC16(dst + swz(r, c16), gbase + (size_t)r * rowb + c16 * 16);
    }
}

__global__ __launch_bounds__(128, 2) void gemm_split_mma(
    const __nv_bfloat16* __restrict__ Ahi, const __nv_bfloat16* __restrict__ Alo,
    const __nv_bfloat16* __restrict__ Bhi, const __nv_bfloat16* __restrict__ Blo,
    float* __restrict__ C, int M, int N, int K) {
    extern __shared__ char smem[];
    const uint32_t sb = smem_u32(smem);
    const int tid = threadIdx.x, lane = tid & 31, wid = tid >> 5;
    const int wm = wid & 1, wn = wid >> 1;
    const int m0 = blockIdx.y * 128, n0 = blockIdx.x * 128;
    const int nchunk = K >> 5;

    const int a_row = (lane & 7) + 8 * ((lane >> 3) & 1);
    const int a_c8  = lane >> 4;
    const int b_row = (lane & 7) + 8 * (lane >> 4);
    const int b_c8  = (lane >> 3) & 1;

    const int arow = wm * 64 + a_row;
    const int selA = (arow >> 1) & 3;
    const int brow = wn * 64 + b_row;
    const int selB = (brow >> 1) & 3;

    float acc[4][8][4];
#pragma unroll
    for (int i = 0; i < 4; i++)
#pragma unroll
        for (int j = 0; j < 8; j++)
#pragma unroll
            for (int r = 0; r < 4; r++) acc[i][j][r] = 0.f;

    // prologue: chunks 0..2 into stages 0..2 (3 groups)
#pragma unroll
    for (int s = 0; s < GSTAGES; s++) {
        uint32_t st = sb + s * GSTAGE_BYTES;
        int k0 = s * 32;
        load_tile32(st,                  Ahi, m0, k0, K, tid);
        load_tile32(st + GMAT_BYTES,     Alo, m0, k0, K, tid);
        load_tile32(st + 2 * GMAT_BYTES, Bhi, n0, k0, K, tid);
        load_tile32(st + 3 * GMAT_BYTES, Blo, n0, k0, K, tid);
        CP_ASYNC_COMMIT();
    }

    for (int c = 0; c < nchunk; c++) {
        uint32_t st = sb + (c % GSTAGES) * GSTAGE_BYTES;
        CP_ASYNC_WAIT1();
        __syncthreads();

        // delayed refill: chunk c+2 into stage (c+2)%3
        if (c >= 1) {
            if (c + 2 < nchunk) {
                uint32_t st2 = sb + ((c + 2) % GSTAGES) * GSTAGE_BYTES;
                int k0 = (c + 2) * 32;
                load_tile32(st2,                  Ahi, m0, k0, K, tid);
                load_tile32(st2 + GMAT_BYTES,     Alo, m0, k0, K, tid);
                load_tile32(st2 + 2 * GMAT_BYTES, Bhi, n0, k0, K, tid);
                load_tile32(st2 + 3 * GMAT_BYTES, Blo, n0, k0, K, tid);
            }
            CP_ASYNC_COMMIT();
        }

#pragma unroll
        for (int ks = 0; ks < 2; ks++) {
            const int ks2 = ks * 2;
            const uint32_t ca = (uint32_t)(((ks2 + a_c8) ^ selA) << 4);
            const uint32_t cb = (uint32_t)(((ks2 + b_c8) ^ selB) << 4);

            uint32_t ah[4][4], al[4][4];
#pragma unroll
            for (int mt = 0; mt < 4; mt++) {
                uint32_t ra = st + (uint32_t)((arow + mt * 16) * 64) + ca;
                ldsm4(ah[mt], ra);
                ldsm4(al[mt], ra + GMAT_BYTES);
            }
#pragma unroll
            for (int np = 0; np < 4; np++) {
                uint32_t bh[4], bl[4];
                uint32_t rb = st + 2 * GMAT_BYTES + (uint32_t)((brow + np * 16) * 64) + cb;
                ldsm4(bh, rb);
                ldsm4(bl, rb + GMAT_BYTES);
#pragma unroll
                for (int mt = 0; mt < 4; mt++)
#pragma unroll
                    for (int hf = 0; hf < 2; hf++) {
                        float* a4 = acc[mt][np * 2 + hf];
                        mma16816(a4, ah[mt], &bh[hf * 2]);
                        mma16816(a4, ah[mt], &bl[hf * 2]);
                        mma16816(a4, al[mt], &bh[hf * 2]);
                    }
            }
        }
    }

    const int crow = lane >> 2, ccol = (lane & 3) * 2;
#pragma unroll
    for (int mt = 0; mt < 4; mt++) {
        int rbase = m0 + wm * 64 + mt * 16 + crow;
#pragma unroll
        for (int nt = 0; nt < 8; nt++) {
            int cbase = n0 + wn * 64 + nt * 8 + ccol;
            float* d0 = C + (size_t)rbase * N + cbase;
            float* d1 = C + (size_t)(rbase + 8) * N + cbase;
            *(float2*)d0 = make_float2(acc[mt][nt][0], acc[mt][nt][1]);
            *(float2*)d1 = make_float2(acc[mt][nt][2], acc[mt][nt][3]);
        }
    }
}

// ================= split / transpose-split =================
// vectorized: float4 in, packed bf16x2 out
__global__ __launch_bounds__(256) void split_kernel(const float4* __restrict__ in,
                                                    uint2* __restrict__ hi,
                                                    uint2* __restrict__ lo, int n4) {
    int i = blockIdx.x * blockDim.x + threadIdx.x;
    if (i >= n4) return;
    float4 v = in[i];
    __nv_bfloat16 h0 = __float2bfloat16(v.x), h1 = __float2bfloat16(v.y);
    __nv_bfloat16 h2 = __float2bfloat16(v.z), h3 = __float2bfloat16(v.w);
    __nv_bfloat16 l0 = __float2bfloat16(v.x - __bfloat162float(h0));
    __nv_bfloat16 l1 = __float2bfloat16(v.y - __bfloat162float(h1));
    __nv_bfloat16 l2 = __float2bfloat16(v.z - __bfloat162float(h2));
    __nv_bfloat16 l3 = __float2bfloat16(v.w - __bfloat162float(h3));
    uint2 hp, lp;
    hp.x = (uint32_t)__bfloat16_as_ushort(h0) | ((uint32_t)__bfloat16_as_ushort(h1) << 16);
    hp.y = (uint32_t)__bfloat16_as_ushort(h2) | ((uint32_t)__bfloat16_as_ushort(h3) << 16);
    lp.x = (uint32_t)__bfloat16_as_ushort(l0) | ((uint32_t)__bfloat16_as_ushort(l1) << 16);
    lp.y = (uint32_t)__bfloat16_as_ushort(l2) | ((uint32_t)__bfloat16_as_ushort(l3) << 16);
    hi[i] = hp;
    lo[i] = lp;
}

__global__ __launch_bounds__(256) void tsplit_qkvg_kernel(const float* __restrict__ Wq,
                                                          const float* __restrict__ Wk,
                                                          const float* __restrict__ Wv,
                                                          const float* __restrict__ Wg,
                                                          __nv_bfloat16* __restrict__ Thi,
                                                          __nv_bfloat16* __restrict__ Tlo) {
    __shared__ float t[32][33];
    int n0 = blockIdx.x * 32, k0 = blockIdx.y * 32;
    const float* W;
    int srcN, ln0;
    if (n0 < 1024)       { W = Wq; srcN = 1024; ln0 = n0; }
    else if (n0 < 2048)  { W = Wk; srcN = 1024; ln0 = n0 - 1024; }
    else if (n0 < 4096)  { W = Wv; srcN = 2048; ln0 = n0 - 2048; }
    else                 { W = Wg; srcN = 2048; ln0 = n0 - 4096; }

    int tx = threadIdx.x & 31, ty = threadIdx.x >> 5;
#pragma unroll
    for (int i = ty; i < 32; i += 8)
        t[i][tx] = W[(size_t)(k0 + i) * srcN + ln0 + tx];
    __syncthreads();
#pragma unroll
    for (int i = ty; i < 32; i += 8) {
        float v = t[tx][i];
        __nv_bfloat16 h = __float2bfloat16(v);
        size_t oidx = (size_t)(n0 + i) * DD + k0 + tx;
        Thi[oidx] = h;
        Tlo[oidx] = __float2bfloat16(v - __bfloat162float(h));
    }
}

__global__ __launch_bounds__(256) void tsplit_kernel(const float* __restrict__ W,
                                                     __nv_bfloat16* __restrict__ Thi,
                                                     __nv_bfloat16* __restrict__ Tlo,
                                                     int K, int N) {
    __shared__ float t[32][33];
    int n0 = blockIdx.x * 32, k0 = blockIdx.y * 32;
    int tx = threadIdx.x & 31, ty = threadIdx.x >> 5;
#pragma unroll
    for (int i = ty; i < 32; i += 8)
        t[i][tx] = W[(size_t)(k0 + i) * N + n0 + tx];
    __syncthreads();
#pragma unroll
    for (int i = ty; i < 32; i += 8) {
        float v = t[tx][i];
        __nv_bfloat16 h = __float2bfloat16(v);
        size_t oidx = (size_t)(n0 + i) * K + k0 + tx;
        Thi[oidx] = h;
        Tlo[oidx] = __float2bfloat16(v - __bfloat162float(h));
    }
}

// ---------------- RoPE on the combined buffer --------------------------------
__global__ void rope_kernel(float* __restrict__ qkvg) {
    int idx = blockIdx.x * blockDim.x + threadIdx.x;
    const int total = BB * TT * HH * (DKk / 2);
    if (idx >= total) return;
    int i = idx & 63;
    int h = (idx >> 6) & (HH - 1);
    int t = (idx >> 9) & (TT - 1);
    int b = idx >> 20;

    float inv = powf(10000.f, -(float)i * (1.0f / 64.0f));
    float f = (float)t * inv;
    float s, c;
    sincosf(f, &s, &c);

    size_t base = ((size_t)b * TT + t) * NQKVG + h * DKk;
    const float sc = 0.08838834764831845f;
    float q1 = qkvg[base + i], q2 = qkvg[base + 64 + i];
    qkvg[base + i]      = (q1 * c - q2 * s) * sc;
    qkvg[base + 64 + i] = (q2 * c + q1 * s) * sc;
    size_t kb = base + 1024;
    float k1 = qkvg[kb + i], k2 = qkvg[kb + 64 + i];
    qkvg[kb + i]      = k1 * c - k2 * s;
    qkvg[kb + 64 + i] = k2 * c + k1 * s;
}

// ================= retention, 4 parallel phases ========

// Phase A: attn = (q@k^T)*M
#define ATTN_SMEM ((2 * 64 * 129 + 64) * 4)
__global__ __launch_bounds__(256) void ret_attn_kernel(const float* __restrict__ qkvg,
                                                       float* __restrict__ attn_out) {
    const int n = blockIdx.x, h = blockIdx.y, b = blockIdx.z;
    const int tid = threadIdx.x;
    extern __shared__ float sm[];
    float* qs   = sm;
    float* ks   = qs + 64 * 129;
    float* gpow = ks + 64 * 129;

    const float gamma = 1.0f - exp2f(-5.0f - (float)h);
    if (tid < 64) gpow[tid] = powf(gamma, (float)tid);

    const int t0 = n * CC;
    for (int e = tid; e < 64 * 128; e += 256) {
        int i = e >> 7, dk = e & 127;
        size_t gi = ((size_t)b * TT + t0 + i) * NQKVG + h * DKk + dk;
        qs[i * 129 + dk] = qkvg[gi];
        ks[i * 129 + dk] = qkvg[gi + 1024];
    }
    __syncthreads();

    const int ti = tid >> 4, te = tid & 15;
    float acc[4][4];
#pragma unroll
    for (int a = 0; a < 4; a++)
#pragma unroll
        for (int bq = 0; bq < 4; bq++) acc[a][bq] = 0.f;
    for (int dk = 0; dk < 128; dk++) {
        float ra[4], rb[4];
#pragma unroll
        for (int ii = 0; ii < 4; ii++) ra[ii] = qs[(ti * 4 + ii) * 129 + dk];
#pragma unroll
        for (int jj = 0; jj < 4; jj++) rb[jj] = ks[(te * 4 + jj) * 129 + dk];
#pragma unroll
        for (int ii = 0; ii < 4; ii++)
#pragma unroll
            for (int jj = 0; jj < 4; jj++) acc[ii][jj] += ra[ii] * rb[jj];
    }

    float* dst = attn_out + ((((size_t)b * HH + h) * NCHUNK + n) << 12);
#pragma unroll
    for (int ii = 0; ii < 4; ii++) {
        int i = ti * 4 + ii;
        float4 w;
        float* wp = &w.x;
#pragma unroll
        for (int jj = 0; jj < 4; jj++) {
            int j = te * 4 + jj;
            wp[jj] = (i >= j) ? acc[ii][jj] * gpow[i - j] : 0.f;
        }
        *(float4*)(dst + i * 64 + te * 4) = w;
    }
}

// Phase B: kv = (k*deck)^T @ v   (per DV slice of 64) — LDS.128 inner loop
#define KV_SMEM ((64 * 132 + 64 * 68 + 64) * 4)
__global__ __launch_bounds__(256) void ret_kv_kernel(const float* __restrict__ qkvg,
                                                     float* __restrict__ kv_out) {
    const int sl = blockIdx.x & 3, n = blockIdx.x >> 2;
    const int h = blockIdx.y, b = blockIdx.z;
    const int tid = threadIdx.x;
    extern __shared__ float sm[];
    float* ks   = sm;               // 64 x 132
    float* vs   = ks + 64 * 132;    // 64 x 68 (pre-scaled by deck)
    float* deck = vs + 64 * 68;     // 64

    const float gamma = 1.0f - exp2f(-5.0f - (float)h);
    if (tid < 64) deck[tid] = powf(gamma, (float)(63 - tid));
    __syncthreads();

    const int t0 = n * CC;
    for (int e = tid; e < 64 * 128; e += 256) {
        int i = e >> 7, dk = e & 127;
        ks[i * 132 + dk] = qkvg[((size_t)b * TT + t0 + i) * NQKVG + 1024 + h * DKk + dk];
    }
    for (int e = tid; e < 64 * 64; e += 256) {
        int i = e >> 6, ev = e & 63;
        size_t gi = ((size_t)b * TT + t0 + i) * NQKVG + 2048 + h * DVv + sl * 64 + ev;
        vs[i * 68 + ev] = qkvg[gi] * deck[i];
    }
    __syncthreads();

    const int ti = tid >> 4, te = tid & 15;
    float acc[8][4];
#pragma unroll
    for (int a = 0; a < 8; a++)
#pragma unroll
        for (int bq = 0; bq < 4; bq++) acc[a][bq] = 0.f;

    for (int j = 0; j < 64; j++) {
        float4 ka = *(const float4*)&ks[j * 132 + ti * 8];
        float4 kb = *(const float4*)&ks[j * 132 + ti * 8 + 4];
        float4 vb = *(const float4*)&vs[j * 68 + te * 4];
        float ra[8] = {ka.x, ka.y, ka.z, ka.w, kb.x, kb.y, kb.z, kb.w};
        float rb[4] = {vb.x, vb.y, vb.z, vb.w};
#pragma unroll
        for (int dd = 0; dd < 8; dd++)
#pragma unroll
            for (int ee = 0; ee < 4; ee++) acc[dd][ee] += ra[dd] * rb[ee];
    }

    float* dst = kv_out + ((((size_t)b * HH + h) * NCHUNK + n) * DKk) * DVv + sl * 64;
#pragma unroll
    for (int dd = 0; dd < 8; dd++) {
        int dk = ti * 8 + dd;
        *(float4*)(dst + (size_t)dk * DVv + te * 4) =
            make_float4(acc[dd][0], acc[dd][1], acc[dd][2], acc[dd][3]);
    }
}

// Phase C: prefix scan of kv -> Spre (float4 per thread)
__global__ __launch_bounds__(256) void ret_scan_kernel(const float4* __restrict__ kv,
                                                       float4* __restrict__ Spre) {
    const int idx = blockIdx.x * 256 + threadIdx.x;     // < 32 * 8192
    const int bh  = idx >> 13;                          // 8192 float4 per chunk-plane
    const int pos = idx & 8191;
    const int h   = bh & (HH - 1);
    const float gamma = 1.0f - exp2f(-5.0f - (float)h);
    const float gC = powf(gamma, 64.0f);

    const size_t base = (size_t)bh * NCHUNK * 8192 + pos;
    float4 s = make_float4(0.f, 0.f, 0.f, 0.f);
    Spre[base] = s;
    for (int n = 1; n < NCHUNK; n++) {
        float4 kvv = kv[base + (size_t)(n - 1) * 8192];
        s.x = gC * s.x + kvv.x;
        s.y = gC * s.y + kvv.y;
        s.z = gC * s.z + kvv.z;
        s.w = gC * s.w + kvv.w;
        Spre[base + (size_t)n * 8192] = s;
    }
}

// Phase D: o = attn @ v + decq * (q @ S_pre)  (per DV slice of 64) — LDS.128
#define OUT_SMEM ((64 * 68 + 64 * 68 + 64 * 132 + 128 * 68 + 64) * 4)
__global__ __launch_bounds__(256) void ret_out_kernel(const float* __restrict__ qkvg,
                                                      const float* __restrict__ attn,
                                                      const float* __restrict__ Spre,
                                                      float* __restrict__ o) {
    const int sl = blockIdx.x & 3, n = blockIdx.x >> 2;
    const int h = blockIdx.y, b = blockIdx.z;
    const int tid = threadIdx.x;
    extern __shared__ float sm[];
    float* at   = sm;               // 64 x 68
    float* vs   = at + 64 * 68;     // 64 x 68
    float* qs   = vs + 64 * 68;     // 64 x 132
    float* Ss   = qs + 64 * 132;    // 128 x 68
    float* decq = Ss + 128 * 68;    // 64

    const float gamma = 1.0f - exp2f(-5.0f - (float)h);
    if (tid < 64) decq[tid] = powf(gamma, (float)(tid + 1));

    const int t0 = n * CC;
    const size_t bh = (size_t)b * HH + h;
    const float* asrc = attn + ((bh * NCHUNK + n) << 12);
    for (int e = tid; e < 64 * 64; e += 256) {
        int i = e >> 6, j = e & 63;
        at[i * 68 + j] = asrc[e];
        vs[i * 68 + j] = qkvg[((size_t)b * TT + t0 + i) * NQKVG + 2048 + h * DVv + sl * 64 + j];
    }
    for (int e = tid; e < 64 * 128; e += 256) {
        int i = e >> 7, dk = e & 127;
        qs[i * 132 + dk] = qkvg[((size_t)b * TT + t0 + i) * NQKVG + h * DKk + dk];
    }
    const float* ssrc = Spre + ((bh * NCHUNK + n) * DKk) * DVv + sl * 64;
    for (int e = tid; e < 128 * 64; e += 256) {
        int dk = e >> 6, ev = e & 63;
        Ss[dk * 68 + ev] = ssrc[(size_t)dk * DVv + ev];
    }
    __syncthreads();

    const int ti = tid >> 4, te = tid & 15;
    float aI[4][4], aS[4][4];
#pragma unroll
    for (int a = 0; a < 4; a++)
#pragma unroll
        for (int bq = 0; bq < 4; bq++) { aI[a][bq] = 0.f; aS[a][bq] = 0.f; }

    // aI: group j by 4, LDS.128, accumulation order preserved
    for (int jg = 0; jg < 16; jg++) {
        float4 ra4[4];
#pragma unroll
        for (int ii = 0; ii < 4; ii++)
            ra4[ii] = *(const float4*)&at[(ti * 4 + ii) * 68 + jg * 4];
#pragma unroll
        for (int jj = 0; jj < 4; jj++) {
            float4 vb = *(const float4*)&vs[(jg * 4 + jj) * 68 + te * 4];
#pragma unroll
            for (int ii = 0; ii < 4; ii++) {
                float ra = ((const float*)&ra4[ii])[jj];
                aI[ii][0] += ra * vb.x;
                aI[ii][1] += ra * vb.y;
                aI[ii][2] += ra * vb.z;
                aI[ii][3] += ra * vb.w;
            }
        }
    }
    // aS: group dk by 4
    for (int dg = 0; dg < 32; dg++) {
        float4 ra4[4];
#pragma unroll
        for (int ii = 0; ii < 4; ii++)
            ra4[ii] = *(const float4*)&qs[(ti * 4 + ii) * 132 + dg * 4];
#pragma unroll
        for (int dd = 0; dd < 4; dd++) {
            float4 sb4 = *(const float4*)&Ss[(dg * 4 + dd) * 68 + te * 4];
#pragma unroll
            for (int ii = 0; ii < 4; ii++) {
                float ra = ((const float*)&ra4[ii])[dd];
                aS[ii][0] += ra * sb4.x;
                aS[ii][1] += ra * sb4.y;
                aS[ii][2] += ra * sb4.z;
                aS[ii][3] += ra * sb4.w;
            }
        }
    }

#pragma unroll
    for (int ii = 0; ii < 4; ii++) {
        int i = ti * 4 + ii;
        float dq = decq[i];
        size_t base = (((size_t)b * TT + t0 + i) * HH + h) * DVv + sl * 64 + te * 4;
        *(float4*)(&o[base]) = make_float4(aI[ii][0] + dq * aS[ii][0],
                                           aI[ii][1] + dq * aS[ii][1],
                                           aI[ii][2] + dq * aS[ii][2],
                                           aI[ii][3] + dq * aS[ii][3]);
    }
}

// ---------------- RMSNorm + swish gate + bf16 split (vectorized) ----
// one warp per (row,head); lane owns 8 consecutive cols: float4 x2 loads,
// uint4 packed bf16 stores.
__global__ __launch_bounds__(256) void normgate_split_kernel(const float* __restrict__ o,
                                                             const float* __restrict__ qkvg,
                                                             const float* __restrict__ norm_w,
                                                             __nv_bfloat16* __restrict__ ohi,
                                                             __nv_bfloat16* __restrict__ olo) {
    int warp = (blockIdx.x * blockDim.x + threadIdx.x) >> 5;
    int lane = threadIdx.x & 31;
    if (warp >= MROWS * HH) return;
    size_t base  = (size_t)warp * DVv + lane * 8;
    size_t gbase = (size_t)(warp >> 3) * NQKVG + 4096 + (size_t)(warp & 7) * DVv + lane * 8;

    float4 v0 = *(const float4*)(o + base);
    float4 v1 = *(const float4*)(o + base + 4);
    float vals[8] = {v0.x, v0.y, v0.z, v0.w, v1.x, v1.y, v1.z, v1.w};

    float ss = 0.f;
#pragma unroll
    for (int r = 0; r < 8; r++) ss += vals[r] * vals[r];
#pragma unroll
    for (int off = 16; off; off >>= 1) ss += __shfl_xor_sync(0xFFFFFFFFu, ss, off);
    float inv = rsqrtf(ss * (1.0f / 256.0f) + 1e-5f);

    float4 g0 = *(const float4*)(qkvg + gbase);
    float4 g1 = *(const float4*)(qkvg + gbase + 4);
    float gv[8] = {g0.x, g0.y, g0.z, g0.w, g1.x, g1.y, g1.z, g1.w};
    float4 w0 = *(const float4*)(norm_w + lane * 8);
    float4 w1 = *(const float4*)(norm_w + lane * 8 + 4);
    float wv[8] = {w0.x, w0.y, w0.z, w0.w, w1.x, w1.y, w1.z, w1.w};

    uint32_t hp[4], lp[4];
#pragma unroll
    for (int p = 0; p < 4; p++) {
        float r0, r1;
        {
            float sg = 1.f / (1.f + expf(-gv[2 * p]));
            r0 = vals[2 * p] * inv * wv[2 * p] * gv[2 * p] * sg;
        }
        {
            float sg = 1.f / (1.f + expf(-gv[2 * p + 1]));
            r1 = vals[2 * p + 1] * inv * wv[2 * p + 1] * gv[2 * p + 1] * sg;
        }
        __nv_bfloat16 h0 = __float2bfloat16(r0), h1 = __float2bfloat16(r1);
        __nv_bfloat16 l0 = __float2bfloat16(r0 - __bfloat162float(h0));
        __nv_bfloat16 l1 = __float2bfloat16(r1 - __bfloat162float(h1));
        hp[p] = (uint32_t)__bfloat16_as_ushort(h0) | ((uint32_t)__bfloat16_as_ushort(h1) << 16);
        lp[p] = (uint32_t)__bfloat16_as_ushort(l0) | ((uint32_t)__bfloat16_as_ushort(l1) << 16);
    }
    *(uint4*)(ohi + base) = make_uint4(hp[0], hp[1], hp[2], hp[3]);
    *(uint4*)(olo + base) = make_uint4(lp[0], lp[1], lp[2], lp[3]);
}

// ---------------- launch ----------------
static void launch_gemm(const __nv_bfloat16* Ahi, const __nv_bfloat16* Alo,
                        const __nv_bfloat16* Bhi, const __nv_bfloat16* Blo,
                        float* C, int M, int N, int K) {
    gemm_split_mma<<<dim3(N / 128, M / 128), 128, GEMM_SMEM_BYTES>>>(Ahi, Alo, Bhi, Blo, C, M, N, K);
}

extern "C" void kernel_launch(void* const* d_in, const int* in_sizes, int n_in,
                              void* d_out, int out_size) {
    const float* x      = (const float*)d_in[0];
    const float* Wq     = (const float*)d_in[1];
    const float* Wk     = (const float*)d_in[2];
    const float* Wv     = (const float*)d_in[3];
    const float* Wg     = (const float*)d_in[4];
    const float* Wo     = (const float*)d_in[5];
    const float* norm_w = (const float*)d_in[6];
    float* out = (float*)d_out;

    float *qkvg, *o, *attn, *kv, *S;
    cudaGetSymbolAddress((void**)&qkvg, g_qkvg);
    cudaGetSymbolAddress((void**)&o, g_o);
    cudaGetSymbolAddress((void**)&attn, g_attn);
    cudaGetSymbolAddress((void**)&kv, g_kv);
    cudaGetSymbolAddress((void**)&S, g_S);
    __nv_bfloat16 *xhi, *xlo, *ohi, *olo, *wallh, *walll, *woh, *wol;
    cudaGetSymbolAddress((void**)&xhi, g_xhi);
    cudaGetSymbolAddress((void**)&xlo, g_xlo);
    cudaGetSymbolAddress((void**)&ohi, g_ohi);
    cudaGetSymbolAddress((void**)&olo, g_olo);
    cudaGetSymbolAddress((void**)&wallh, g_wall_hi);
    cudaGetSymbolAddress((void**)&walll, g_wall_lo);
    cudaGetSymbolAddress((void**)&woh, g_wo_hi);
    cudaGetSymbolAddress((void**)&wol, g_wo_lo);

    cudaFuncSetAttribute(gemm_split_mma, cudaFuncAttributeMaxDynamicSharedMemorySize, GEMM_SMEM_BYTES);
    cudaFuncSetAttribute(ret_attn_kernel, cudaFuncAttributeMaxDynamicSharedMemorySize, ATTN_SMEM);
    cudaFuncSetAttribute(ret_kv_kernel, cudaFuncAttributeMaxDynamicSharedMemorySize, KV_SMEM);
    cudaFuncSetAttribute(ret_out_kernel, cudaFuncAttributeMaxDynamicSharedMemorySize, OUT_SMEM);

    // split inputs + transpose-split weights
    {
        int n4 = (MROWS * DD) / 4;
        split_kernel<<<(n4 + 255) / 256, 256>>>((const float4*)x, (uint2*)xhi, (uint2*)xlo, n4);
    }
    tsplit_qkvg_kernel<<<dim3(NQKVG / 32, DD / 32), 256>>>(Wq, Wk, Wv, Wg, wallh, walll);
    tsplit_kernel<<<dim3(DD / 32, 2 * DD / 32), 256>>>(Wo, woh, wol, 2 * DD, DD);

    // combined projection GEMM (q|k|v|g)
    launch_gemm(xhi, xlo, wallh, walll, qkvg, MROWS, NQKVG, DD);

    // rope + scale (on combined buffer)
    {
        int total = BB * TT * HH * (DKk / 2);
        rope_kernel<<<(total + 255) / 256, 256>>>(qkvg);
    }

    // retention: 4 parallel phases
    ret_attn_kernel<<<dim3(NCHUNK, HH, BB), 256, ATTN_SMEM>>>(qkvg, attn);
    ret_kv_kernel<<<dim3(4 * NCHUNK, HH, BB), 256, KV_SMEM>>>(qkvg, kv);
    ret_scan_kernel<<<(NBH * DKk * DVv / 4) / 256, 256>>>((const float4*)kv, (float4*)S);
    ret_out_kernel<<<dim3(4 * NCHUNK, HH, BB), 256, OUT_SMEM>>>(qkvg, attn, S, o);

    // rmsnorm + gate + split (fused, vectorized)
    {
        int warps = MROWS * HH;
        normgate_split_kernel<<<(warps * 32 + 255) / 256, 256>>>(o, qkvg, norm_w, ohi, olo);
    }

    // output projection on tensor cores
    launch_gemm(ohi, olo, woh, wol, out, MROWS, DD, 2 * DD);
}

// round 13
// speedup vs baseline: 1.3635x; 1.0919x over previous
#include <cuda_runtime.h>
#include <cuda_bf16.h>
#include <math.h>
#include <stdint.h>

// ---------------- problem constants ----------------
#define BB 4
#define TT 2048
#define DD 1024
#define HH 8
#define DKk 128
#define DVv 256
#define CC 64
#define NCHUNK (TT / CC)   // 32
#define MROWS (BB * TT)    // 8192
#define NBH (BB * HH)      // 32
#define NQKVG 6144         // q(1024) | k(1024) | v(2048) | g(2048)

// ---------------- scratch (no runtime allocation allowed) ----------------
__device__ float g_qkvg[MROWS * NQKVG];
__device__ float g_o[MROWS * HH * DVv];

// retention intermediates
__device__ float g_attn[NBH * NCHUNK * CC * CC];
__device__ float g_kv[NBH * NCHUNK * DKk * DVv];
__device__ float g_S[NBH * NCHUNK * DKk * DVv];

// bf16 split operands
__device__ __nv_bfloat16 g_xhi[MROWS * DD];
__device__ __nv_bfloat16 g_xlo[MROWS * DD];
__device__ __nv_bfloat16 g_ohi[MROWS * HH * DVv];
__device__ __nv_bfloat16 g_olo[MROWS * HH * DVv];
// transposed weights [N, K]
__device__ __nv_bfloat16 g_wall_hi[NQKVG * DD], g_wall_lo[NQKVG * DD];
__device__ __nv_bfloat16 g_wo_hi[2 * DD * DD],  g_wo_lo[2 * DD * DD];

// ================= PTX helpers (plain sm_80+ ISA only) =================
__device__ __forceinline__ uint32_t smem_u32(const void* p) {
    uint32_t a;
    asm("{ .reg .u64 t; cvta.to.shared.u64 t, %1; cvt.u32.u64 %0, t; }" : "=r"(a) : "l"(p));
    return a;
}
#define CP_ASYNC16(dst, src) \
    asm volatile("cp.async.cg.shared.global [%0], [%1], 16;" :: "r"(dst), "l"(src))
#define CP_ASYNC_COMMIT() asm volatile("cp.async.commit_group;" ::: "memory")
#define CP_ASYNC_WAIT1() asm volatile("cp.async.wait_group 1;" ::: "memory")

__device__ __forceinline__ void ldsm4(uint32_t* r, uint32_t addr) {
    asm volatile("ldmatrix.sync.aligned.m8n8.x4.shared.b16 {%0,%1,%2,%3}, [%4];"
        : "=r"(r[0]), "=r"(r[1]), "=r"(r[2]), "=r"(r[3]) : "r"(addr));
}
__device__ __forceinline__ void mma16816(float* c, const uint32_t* a, const uint32_t* b) {
    asm volatile("mma.sync.aligned.m16n8k16.row.col.f32.bf16.bf16.f32 "
        "{%0,%1,%2,%3}, {%4,%5,%6,%7}, {%8,%9}, {%0,%1,%2,%3};"
        : "+f"(c[0]), "+f"(c[1]), "+f"(c[2]), "+f"(c[3])
        : "r"(a[0]), "r"(a[1]), "r"(a[2]), "r"(a[3]), "r"(b[0]), "r"(b[1]));
}

// ================= split-bf16 tensor-core GEMM =================
// single-barrier delayed-refill 3-stage pipeline (verified win in R9)
#define GSTAGES 3
#define GMAT_BYTES (128 * 64)
#define GSTAGE_BYTES (4 * GMAT_BYTES)
#define GEMM_SMEM_BYTES (GSTAGES * GSTAGE_BYTES)

__device__ __forceinline__ uint32_t swz(int row, int c16) {
    return (uint32_t)(row * 64 + ((c16 ^ ((row >> 1) & 3)) << 4));
}

__device__ __forceinline__ void load_tile32(uint32_t dst, const __nv_bfloat16* src,
                                            int row0, int k0, int ldk, int tid) {
    const char* gbase = (const char*)(src + (size_t)row0 * ldk + k0);
    const size_t rowb = (size_t)ldk * 2;
#pragma unroll
    for (int j = 0; j < 4; j++) {
        int e = tid + j * 128;
        int r = e >> 2, c16 = e & 3;
        CP_ASYNC16(dst + swz(r, c16), gbase + (size_t)r * rowb + c16 * 16);
    }
}

__global__ __launch_bounds__(128, 2) void gemm_split_mma(
    const __nv_bfloat16* __restrict__ Ahi, const __nv_bfloat16* __restrict__ Alo,
    const __nv_bfloat16* __restrict__ Bhi, const __nv_bfloat16* __restrict__ Blo,
    float* __restrict__ C, int M, int N, int K) {
    extern __shared__ char smem[];
    const uint32_t sb = smem_u32(smem);
    const int tid = threadIdx.x, lane = tid & 31, wid = tid >> 5;
    const int wm = wid & 1, wn = wid >> 1;
    const int m0 = blockIdx.y * 128, n0 = blockIdx.x * 128;
    const int nchunk = K >> 5;

    const int a_row = (lane & 7) + 8 * ((lane >> 3) & 1);
    const int a_c8  = lane >> 4;
    const int b_row = (lane & 7) + 8 * (lane >> 4);
    const int b_c8  = (lane >> 3) & 1;

    const int arow = wm * 64 + a_row;
    const int selA = (arow >> 1) & 3;
    const int brow = wn * 64 + b_row;
    const int selB = (brow >> 1) & 3;

    float acc[4][8][4];
#pragma unroll
    for (int i = 0; i < 4; i++)
#pragma unroll
        for (int j = 0; j < 8; j++)
#pragma unroll
            for (int r = 0; r < 4; r++) acc[i][j][r] = 0.f;

    // prologue: chunks 0..2 into stages 0..2 (3 groups)
#pragma unroll
    for (int s = 0; s < GSTAGES; s++) {
        uint32_t st = sb + s * GSTAGE_BYTES;
        int k0 = s * 32;
        load_tile32(st,                  Ahi, m0, k0, K, tid);
        load_tile32(st + GMAT_BYTES,     Alo, m0, k0, K, tid);
        load_tile32(st + 2 * GMAT_BYTES, Bhi, n0, k0, K, tid);
        load_tile32(st + 3 * GMAT_BYTES, Blo, n0, k0, K, tid);
        CP_ASYNC_COMMIT();
    }

    for (int c = 0; c < nchunk; c++) {
        uint32_t st = sb + (c % GSTAGES) * GSTAGE_BYTES;
        CP_ASYNC_WAIT1();
        __syncthreads();

        // delayed refill: chunk c+2 into stage (c+2)%3
        if (c >= 1) {
            if (c + 2 < nchunk) {
                uint32_t st2 = sb + ((c + 2) % GSTAGES) * GSTAGE_BYTES;
                int k0 = (c + 2) * 32;
                load_tile32(st2,                  Ahi, m0, k0, K, tid);
                load_tile32(st2 + GMAT_BYTES,     Alo, m0, k0, K, tid);
                load_tile32(st2 + 2 * GMAT_BYTES, Bhi, n0, k0, K, tid);
                load_tile32(st2 + 3 * GMAT_BYTES, Blo, n0, k0, K, tid);
            }
            CP_ASYNC_COMMIT();
        }

#pragma unroll
        for (int ks = 0; ks < 2; ks++) {
            const int ks2 = ks * 2;
            const uint32_t ca = (uint32_t)(((ks2 + a_c8) ^ selA) << 4);
            const uint32_t cb = (uint32_t)(((ks2 + b_c8) ^ selB) << 4);

            uint32_t ah[4][4], al[4][4];
#pragma unroll
            for (int mt = 0; mt < 4; mt++) {
                uint32_t ra = st + (uint32_t)((arow + mt * 16) * 64) + ca;
                ldsm4(ah[mt], ra);
                ldsm4(al[mt], ra + GMAT_BYTES);
            }
#pragma unroll
            for (int np = 0; np < 4; np++) {
                uint32_t bh[4], bl[4];
                uint32_t rb = st + 2 * GMAT_BYTES + (uint32_t)((brow + np * 16) * 64) + cb;
                ldsm4(bh, rb);
                ldsm4(bl, rb + GMAT_BYTES);
#pragma unroll
                for (int mt = 0; mt < 4; mt++)
#pragma unroll
                    for (int hf = 0; hf < 2; hf++) {
                        float* a4 = acc[mt][np * 2 + hf];
                        mma16816(a4, ah[mt], &bh[hf * 2]);
                        mma16816(a4, ah[mt], &bl[hf * 2]);
                        mma16816(a4, al[mt], &bh[hf * 2]);
                    }
            }
        }
    }

    const int crow = lane >> 2, ccol = (lane & 3) * 2;
#pragma unroll
    for (int mt = 0; mt < 4; mt++) {
        int rbase = m0 + wm * 64 + mt * 16 + crow;
#pragma unroll
        for (int nt = 0; nt < 8; nt++) {
            int cbase = n0 + wn * 64 + nt * 8 + ccol;
            float* d0 = C + (size_t)rbase * N + cbase;
            float* d1 = C + (size_t)(rbase + 8) * N + cbase;
            *(float2*)d0 = make_float2(acc[mt][nt][0], acc[mt][nt][1]);
            *(float2*)d1 = make_float2(acc[mt][nt][2], acc[mt][nt][3]);
        }
    }
}

// ================= split / transpose-split =================
__global__ __launch_bounds__(256) void split_kernel(const float4* __restrict__ in,
                                                    uint2* __restrict__ hi,
                                                    uint2* __restrict__ lo, int n4) {
    int i = blockIdx.x * blockDim.x + threadIdx.x;
    if (i >= n4) return;
    float4 v = in[i];
    __nv_bfloat16 h0 = __float2bfloat16(v.x), h1 = __float2bfloat16(v.y);
    __nv_bfloat16 h2 = __float2bfloat16(v.z), h3 = __float2bfloat16(v.w);
    __nv_bfloat16 l0 = __float2bfloat16(v.x - __bfloat162float(h0));
    __nv_bfloat16 l1 = __float2bfloat16(v.y - __bfloat162float(h1));
    __nv_bfloat16 l2 = __float2bfloat16(v.z - __bfloat162float(h2));
    __nv_bfloat16 l3 = __float2bfloat16(v.w - __bfloat162float(h3));
    uint2 hp, lp;
    hp.x = (uint32_t)__bfloat16_as_ushort(h0) | ((uint32_t)__bfloat16_as_ushort(h1) << 16);
    hp.y = (uint32_t)__bfloat16_as_ushort(h2) | ((uint32_t)__bfloat16_as_ushort(h3) << 16);
    lp.x = (uint32_t)__bfloat16_as_ushort(l0) | ((uint32_t)__bfloat16_as_ushort(l1) << 16);
    lp.y = (uint32_t)__bfloat16_as_ushort(l2) | ((uint32_t)__bfloat16_as_ushort(l3) << 16);
    hi[i] = hp;
    lo[i] = lp;
}

__global__ __launch_bounds__(256) void tsplit_qkvg_kernel(const float* __restrict__ Wq,
                                                          const float* __restrict__ Wk,
                                                          const float* __restrict__ Wv,
                                                          const float* __restrict__ Wg,
                                                          __nv_bfloat16* __restrict__ Thi,
                                                          __nv_bfloat16* __restrict__ Tlo) {
    __shared__ float t[32][33];
    int n0 = blockIdx.x * 32, k0 = blockIdx.y * 32;
    const float* W;
    int srcN, ln0;
    if (n0 < 1024)       { W = Wq; srcN = 1024; ln0 = n0; }
    else if (n0 < 2048)  { W = Wk; srcN = 1024; ln0 = n0 - 1024; }
    else if (n0 < 4096)  { W = Wv; srcN = 2048; ln0 = n0 - 2048; }
    else                 { W = Wg; srcN = 2048; ln0 = n0 - 4096; }

    int tx = threadIdx.x & 31, ty = threadIdx.x >> 5;
#pragma unroll
    for (int i = ty; i < 32; i += 8)
        t[i][tx] = W[(size_t)(k0 + i) * srcN + ln0 + tx];
    __syncthreads();
#pragma unroll
    for (int i = ty; i < 32; i += 8) {
        float v = t[tx][i];
        __nv_bfloat16 h = __float2bfloat16(v);
        size_t oidx = (size_t)(n0 + i) * DD + k0 + tx;
        Thi[oidx] = h;
        Tlo[oidx] = __float2bfloat16(v - __bfloat162float(h));
    }
}

__global__ __launch_bounds__(256) void tsplit_kernel(const float* __restrict__ W,
                                                     __nv_bfloat16* __restrict__ Thi,
                                                     __nv_bfloat16* __restrict__ Tlo,
                                                     int K, int N) {
    __shared__ float t[32][33];
    int n0 = blockIdx.x * 32, k0 = blockIdx.y * 32;
    int tx = threadIdx.x & 31, ty = threadIdx.x >> 5;
#pragma unroll
    for (int i = ty; i < 32; i += 8)
        t[i][tx] = W[(size_t)(k0 + i) * N + n0 + tx];
    __syncthreads();
#pragma unroll
    for (int i = ty; i < 32; i += 8) {
        float v = t[tx][i];
        __nv_bfloat16 h = __float2bfloat16(v);
        size_t oidx = (size_t)(n0 + i) * K + k0 + tx;
        Thi[oidx] = h;
        Tlo[oidx] = __float2bfloat16(v - __bfloat162float(h));
    }
}

// ---------------- RoPE (vectorized float4: 4 freq indices per thread) --------
__global__ void rope_kernel(float* __restrict__ qkvg) {
    int idx = blockIdx.x * blockDim.x + threadIdx.x;
    const int total = BB * TT * HH * 16;        // 16 float4 groups of freq idx
    if (idx >= total) return;
    int i4 = idx & 15;                 // freq group: i = i4*4 + c
    int h = (idx >> 4) & (HH - 1);
    int t = (idx >> 7) & (TT - 1);
    int b = idx >> 18;

    size_t base = ((size_t)b * TT + t) * NQKVG + h * DKk + i4 * 4;
    const float sc = 0.08838834764831845f;

    float s[4], c[4];
#pragma unroll
    for (int cc = 0; cc < 4; cc++) {
        int i = i4 * 4 + cc;
        float inv = powf(10000.f, -(float)i * (1.0f / 64.0f));
        sincosf((float)t * inv, &s[cc], &c[cc]);
    }

    float4 q1 = *(float4*)&qkvg[base];
    float4 q2 = *(float4*)&qkvg[base + 64];
    float* q1p = &q1.x; float* q2p = &q2.x;
    float4 o1, o2;
    float* o1p = &o1.x; float* o2p = &o2.x;
#pragma unroll
    for (int cc = 0; cc < 4; cc++) {
        o1p[cc] = (q1p[cc] * c[cc] - q2p[cc] * s[cc]) * sc;
        o2p[cc] = (q2p[cc] * c[cc] + q1p[cc] * s[cc]) * sc;
    }
    *(float4*)&qkvg[base]      = o1;
    *(float4*)&qkvg[base + 64] = o2;

    size_t kb = base + 1024;
    float4 k1 = *(float4*)&qkvg[kb];
    float4 k2 = *(float4*)&qkvg[kb + 64];
    float* k1p = &k1.x; float* k2p = &k2.x;
#pragma unroll
    for (int cc = 0; cc < 4; cc++) {
        o1p[cc] = k1p[cc] * c[cc] - k2p[cc] * s[cc];
        o2p[cc] = k2p[cc] * c[cc] + k1p[cc] * s[cc];
    }
    *(float4*)&qkvg[kb]      = o1;
    *(float4*)&qkvg[kb + 64] = o2;
}

// ================= retention, 4 parallel phases ========

// Phase A: attn = (q@k^T)*M  (unchanged)
#define ATTN_SMEM ((2 * 64 * 129 + 64) * 4)
__global__ __launch_bounds__(256) void ret_attn_kernel(const float* __restrict__ qkvg,
                                                       float* __restrict__ attn_out) {
    const int n = blockIdx.x, h = blockIdx.y, b = blockIdx.z;
    const int tid = threadIdx.x;
    extern __shared__ float sm[];
    float* qs   = sm;
    float* ks   = qs + 64 * 129;
    float* gpow = ks + 64 * 129;

    const float gamma = 1.0f - exp2f(-5.0f - (float)h);
    if (tid < 64) gpow[tid] = powf(gamma, (float)tid);

    const int t0 = n * CC;
    for (int e = tid; e < 64 * 128; e += 256) {
        int i = e >> 7, dk = e & 127;
        size_t gi = ((size_t)b * TT + t0 + i) * NQKVG + h * DKk + dk;
        qs[i * 129 + dk] = qkvg[gi];
        ks[i * 129 + dk] = qkvg[gi + 1024];
    }
    __syncthreads();

    const int ti = tid >> 4, te = tid & 15;
    float acc[4][4];
#pragma unroll
    for (int a = 0; a < 4; a++)
#pragma unroll
        for (int bq = 0; bq < 4; bq++) acc[a][bq] = 0.f;
    for (int dk = 0; dk < 128; dk++) {
        float ra[4], rb[4];
#pragma unroll
        for (int ii = 0; ii < 4; ii++) ra[ii] = qs[(ti * 4 + ii) * 129 + dk];
#pragma unroll
        for (int jj = 0; jj < 4; jj++) rb[jj] = ks[(te * 4 + jj) * 129 + dk];
#pragma unroll
        for (int ii = 0; ii < 4; ii++)
#pragma unroll
            for (int jj = 0; jj < 4; jj++) acc[ii][jj] += ra[ii] * rb[jj];
    }

    float* dst = attn_out + ((((size_t)b * HH + h) * NCHUNK + n) << 12);
#pragma unroll
    for (int ii = 0; ii < 4; ii++) {
        int i = ti * 4 + ii;
        float4 w;
        float* wp = &w.x;
#pragma unroll
        for (int jj = 0; jj < 4; jj++) {
            int j = te * 4 + jj;
            wp[jj] = (i >= j) ? acc[ii][jj] * gpow[i - j] : 0.f;
        }
        *(float4*)(dst + i * 64 + te * 4) = w;
    }
}

// Phase B: kv = (k*deck)^T @ v  (per DV slice of 64) — float4 fills + LDS.128
#define KV_SMEM ((64 * 132 + 64 * 68 + 64) * 4)
__global__ __launch_bounds__(256) void ret_kv_kernel(const float* __restrict__ qkvg,
                                                     float* __restrict__ kv_out) {
    const int sl = blockIdx.x & 3, n = blockIdx.x >> 2;
    const int h = blockIdx.y, b = blockIdx.z;
    const int tid = threadIdx.x;
    extern __shared__ float sm[];
    float* ks   = sm;               // 64 x 132
    float* vs   = ks + 64 * 132;    // 64 x 68 (pre-scaled by deck)
    float* deck = vs + 64 * 68;     // 64

    const float gamma = 1.0f - exp2f(-5.0f - (float)h);
    if (tid < 64) deck[tid] = powf(gamma, (float)(63 - tid));
    __syncthreads();

    const int t0 = n * CC;
    // ks fill: 64 rows x 32 float4
    for (int e = tid; e < 64 * 32; e += 256) {
        int i = e >> 5, c4 = e & 31;
        float4 v = *(const float4*)&qkvg[((size_t)b * TT + t0 + i) * NQKVG + 1024 + h * DKk + c4 * 4];
        *(float4*)&ks[i * 132 + c4 * 4] = v;
    }
    // vs fill: 64 rows x 16 float4, scaled by deck[i]
    for (int e = tid; e < 64 * 16; e += 256) {
        int i = e >> 4, c4 = e & 15;
        float d = deck[i];
        float4 v = *(const float4*)&qkvg[((size_t)b * TT + t0 + i) * NQKVG + 2048 + h * DVv + sl * 64 + c4 * 4];
        v.x *= d; v.y *= d; v.z *= d; v.w *= d;
        *(float4*)&vs[i * 68 + c4 * 4] = v;
    }
    __syncthreads();

    const int ti = tid >> 4, te = tid & 15;
    float acc[8][4];
#pragma unroll
    for (int a = 0; a < 8; a++)
#pragma unroll
        for (int bq = 0; bq < 4; bq++) acc[a][bq] = 0.f;

    for (int j = 0; j < 64; j++) {
        float4 ka = *(const float4*)&ks[j * 132 + ti * 8];
        float4 kb = *(const float4*)&ks[j * 132 + ti * 8 + 4];
        float4 vb = *(const float4*)&vs[j * 68 + te * 4];
        float ra[8] = {ka.x, ka.y, ka.z, ka.w, kb.x, kb.y, kb.z, kb.w};
        float rb[4] = {vb.x, vb.y, vb.z, vb.w};
#pragma unroll
        for (int dd = 0; dd < 8; dd++)
#pragma unroll
            for (int ee = 0; ee < 4; ee++) acc[dd][ee] += ra[dd] * rb[ee];
    }

    float* dst = kv_out + ((((size_t)b * HH + h) * NCHUNK + n) * DKk) * DVv + sl * 64;
#pragma unroll
    for (int dd = 0; dd < 8; dd++) {
        int dk = ti * 8 + dd;
        *(float4*)(dst + (size_t)dk * DVv + te * 4) =
            make_float4(acc[dd][0], acc[dd][1], acc[dd][2], acc[dd][3]);
    }
}

// Phase C: prefix scan of kv -> Spre (float4 per thread)
__global__ __launch_bounds__(256) void ret_scan_kernel(const float4* __restrict__ kv,
                                                       float4* __restrict__ Spre) {
    const int idx = blockIdx.x * 256 + threadIdx.x;
    const int bh  = idx >> 13;
    const int pos = idx & 8191;
    const int h   = bh & (HH - 1);
    const float gamma = 1.0f - exp2f(-5.0f - (float)h);
    const float gC = powf(gamma, 64.0f);

    const size_t base = (size_t)bh * NCHUNK * 8192 + pos;
    float4 s = make_float4(0.f, 0.f, 0.f, 0.f);
    Spre[base] = s;
    for (int n = 1; n < NCHUNK; n++) {
        float4 kvv = kv[base + (size_t)(n - 1) * 8192];
        s.x = gC * s.x + kvv.x;
        s.y = gC * s.y + kvv.y;
        s.z = gC * s.z + kvv.z;
        s.w = gC * s.w + kvv.w;
        Spre[base + (size_t)n * 8192] = s;
    }
}

// Phase D: o = attn @ v + decq * (q @ S_pre)  — float4 fills + LDS.128
#define OUT_SMEM ((64 * 68 + 64 * 68 + 64 * 132 + 128 * 68 + 64) * 4)
__global__ __launch_bounds__(256) void ret_out_kernel(const float* __restrict__ qkvg,
                                                      const float* __restrict__ attn,
                                                      const float* __restrict__ Spre,
                                                      float* __restrict__ o) {
    const int sl = blockIdx.x & 3, n = blockIdx.x >> 2;
    const int h = blockIdx.y, b = blockIdx.z;
    const int tid = threadIdx.x;
    extern __shared__ float sm[];
    float* at   = sm;               // 64 x 68
    float* vs   = at + 64 * 68;     // 64 x 68
    float* qs   = vs + 64 * 68;     // 64 x 132
    float* Ss   = qs + 64 * 132;    // 128 x 68
    float* decq = Ss + 128 * 68;    // 64

    const float gamma = 1.0f - exp2f(-5.0f - (float)h);
    if (tid < 64) decq[tid] = powf(gamma, (float)(tid + 1));

    const int t0 = n * CC;
    const size_t bh = (size_t)b * HH + h;
    const float* asrc = attn + ((bh * NCHUNK + n) << 12);
    // at + vs fills: 64 rows x 16 float4 each
    for (int e = tid; e < 64 * 16; e += 256) {
        int i = e >> 4, c4 = e & 15;
        *(float4*)&at[i * 68 + c4 * 4] = *(const float4*)&asrc[i * 64 + c4 * 4];
        *(float4*)&vs[i * 68 + c4 * 4] =
            *(const float4*)&qkvg[((size_t)b * TT + t0 + i) * NQKVG + 2048 + h * DVv + sl * 64 + c4 * 4];
    }
    // qs fill: 64 rows x 32 float4
    for (int e = tid; e < 64 * 32; e += 256) {
        int i = e >> 5, c4 = e & 31;
        *(float4*)&qs[i * 132 + c4 * 4] =
            *(const float4*)&qkvg[((size_t)b * TT + t0 + i) * NQKVG + h * DKk + c4 * 4];
    }
    // Ss fill: 128 rows x 16 float4
    const float* ssrc = Spre + ((bh * NCHUNK + n) * DKk) * DVv + sl * 64;
    for (int e = tid; e < 128 * 16; e += 256) {
        int dk = e >> 4, c4 = e & 15;
        *(float4*)&Ss[dk * 68 + c4 * 4] = *(const float4*)&ssrc[(size_t)dk * DVv + c4 * 4];
    }
    __syncthreads();

    const int ti = tid >> 4, te = tid & 15;
    float aI[4][4], aS[4][4];
#pragma unroll
    for (int a = 0; a < 4; a++)
#pragma unroll
        for (int bq = 0; bq < 4; bq++) { aI[a][bq] = 0.f; aS[a][bq] = 0.f; }

    for (int jg = 0; jg < 16; jg++) {
        float4 ra4[4];
#pragma unroll
        for (int ii = 0; ii < 4; ii++)
            ra4[ii] = *(const float4*)&at[(ti * 4 + ii) * 68 + jg * 4];
#pragma unroll
        for (int jj = 0; jj < 4; jj++) {
            float4 vb = *(const float4*)&vs[(jg * 4 + jj) * 68 + te * 4];
#pragma unroll
            for (int ii = 0; ii < 4; ii++) {
                float ra = ((const float*)&ra4[ii])[jj];
                aI[ii][0] += ra * vb.x;
                aI[ii][1] += ra * vb.y;
                aI[ii][2] += ra * vb.z;
                aI[ii][3] += ra * vb.w;
            }
        }
    }
    for (int dg = 0; dg < 32; dg++) {
        float4 ra4[4];
#pragma unroll
        for (int ii = 0; ii < 4; ii++)
            ra4[ii] = *(const float4*)&qs[(ti * 4 + ii) * 132 + dg * 4];
#pragma unroll
        for (int dd = 0; dd < 4; dd++) {
            float4 sb4 = *(const float4*)&Ss[(dg * 4 + dd) * 68 + te * 4];
#pragma unroll
            for (int ii = 0; ii < 4; ii++) {
                float ra = ((const float*)&ra4[ii])[dd];
                aS[ii][0] += ra * sb4.x;
                aS[ii][1] += ra * sb4.y;
                aS[ii][2] += ra * sb4.z;
                aS[ii][3] += ra * sb4.w;
            }
        }
    }

#pragma unroll
    for (int ii = 0; ii < 4; ii++) {
        int i = ti * 4 + ii;
        float dq = decq[i];
        size_t base = (((size_t)b * TT + t0 + i) * HH + h) * DVv + sl * 64 + te * 4;
        *(float4*)(&o[base]) = make_float4(aI[ii][0] + dq * aS[ii][0],
                                           aI[ii][1] + dq * aS[ii][1],
                                           aI[ii][2] + dq * aS[ii][2],
                                           aI[ii][3] + dq * aS[ii][3]);
    }
}

// ---------------- RMSNorm + swish gate + bf16 split (vectorized) ----
__global__ __launch_bounds__(256) void normgate_split_kernel(const float* __restrict__ o,
                                                             const float* __restrict__ qkvg,
                                                             const float* __restrict__ norm_w,
                                                             __nv_bfloat16* __restrict__ ohi,
                                                             __nv_bfloat16* __restrict__ olo) {
    int warp = (blockIdx.x * blockDim.x + threadIdx.x) >> 5;
    int lane = threadIdx.x & 31;
    if (warp >= MROWS * HH) return;
    size_t base  = (size_t)warp * DVv + lane * 8;
    size_t gbase = (size_t)(warp >> 3) * NQKVG + 4096 + (size_t)(warp & 7) * DVv + lane * 8;

    float4 v0 = *(const float4*)(o + base);
    float4 v1 = *(const float4*)(o + base + 4);
    float vals[8] = {v0.x, v0.y, v0.z, v0.w, v1.x, v1.y, v1.z, v1.w};

    float ss = 0.f;
#pragma unroll
    for (int r = 0; r < 8; r++) ss += vals[r] * vals[r];
#pragma unroll
    for (int off = 16; off; off >>= 1) ss += __shfl_xor_sync(0xFFFFFFFFu, ss, off);
    float inv = rsqrtf(ss * (1.0f / 256.0f) + 1e-5f);

    float4 g0 = *(const float4*)(qkvg + gbase);
    float4 g1 = *(const float4*)(qkvg + gbase + 4);
    float gv[8] = {g0.x, g0.y, g0.z, g0.w, g1.x, g1.y, g1.z, g1.w};
    float4 w0 = *(const float4*)(norm_w + lane * 8);
    float4 w1 = *(const float4*)(norm_w + lane * 8 + 4);
    float wv[8] = {w0.x, w0.y, w0.z, w0.w, w1.x, w1.y, w1.z, w1.w};

    uint32_t hp[4], lp[4];
#pragma unroll
    for (int p = 0; p < 4; p++) {
        float r0, r1;
        {
            float sg = 1.f / (1.f + expf(-gv[2 * p]));
            r0 = vals[2 * p] * inv * wv[2 * p] * gv[2 * p] * sg;
        }
        {
            float sg = 1.f / (1.f + expf(-gv[2 * p + 1]));
            r1 = vals[2 * p + 1] * inv * wv[2 * p + 1] * gv[2 * p + 1] * sg;
        }
        __nv_bfloat16 h0 = __float2bfloat16(r0), h1 = __float2bfloat16(r1);
        __nv_bfloat16 l0 = __float2bfloat16(r0 - __bfloat162float(h0));
        __nv_bfloat16 l1 = __float2bfloat16(r1 - __bfloat162float(h1));
        hp[p] = (uint32_t)__bfloat16_as_ushort(h0) | ((uint32_t)__bfloat16_as_ushort(h1) << 16);
        lp[p] = (uint32_t)__bfloat16_as_ushort(l0) | ((uint32_t)__bfloat16_as_ushort(l1) << 16);
    }
    *(uint4*)(ohi + base) = make_uint4(hp[0], hp[1], hp[2], hp[3]);
    *(uint4*)(olo + base) = make_uint4(lp[0], lp[1], lp[2], lp[3]);
}

// ---------------- launch ----------------
static void launch_gemm(const __nv_bfloat16* Ahi, const __nv_bfloat16* Alo,
                        const __nv_bfloat16* Bhi, const __nv_bfloat16* Blo,
                        float* C, int M, int N, int K) {
    gemm_split_mma<<<dim3(N / 128, M / 128), 128, GEMM_SMEM_BYTES>>>(Ahi, Alo, Bhi, Blo, C, M, N, K);
}

extern "C" void kernel_launch(void* const* d_in, const int* in_sizes, int n_in,
                              void* d_out, int out_size) {
    const float* x      = (const float*)d_in[0];
    const float* Wq     = (const float*)d_in[1];
    const float* Wk     = (const float*)d_in[2];
    const float* Wv     = (const float*)d_in[3];
    const float* Wg     = (const float*)d_in[4];
    const float* Wo     = (const float*)d_in[5];
    const float* norm_w = (const float*)d_in[6];
    float* out = (float*)d_out;

    float *qkvg, *o, *attn, *kv, *S;
    cudaGetSymbolAddress((void**)&qkvg, g_qkvg);
    cudaGetSymbolAddress((void**)&o, g_o);
    cudaGetSymbolAddress((void**)&attn, g_attn);
    cudaGetSymbolAddress((void**)&kv, g_kv);
    cudaGetSymbolAddress((void**)&S, g_S);
    __nv_bfloat16 *xhi, *xlo, *ohi, *olo, *wallh, *walll, *woh, *wol;
    cudaGetSymbolAddress((void**)&xhi, g_xhi);
    cudaGetSymbolAddress((void**)&xlo, g_xlo);
    cudaGetSymbolAddress((void**)&ohi, g_ohi);
    cudaGetSymbolAddress((void**)&olo, g_olo);
    cudaGetSymbolAddress((void**)&wallh, g_wall_hi);
    cudaGetSymbolAddress((void**)&walll, g_wall_lo);
    cudaGetSymbolAddress((void**)&woh, g_wo_hi);
    cudaGetSymbolAddress((void**)&wol, g_wo_lo);

    cudaFuncSetAttribute(gemm_split_mma, cudaFuncAttributeMaxDynamicSharedMemorySize, GEMM_SMEM_BYTES);
    cudaFuncSetAttribute(ret_attn_kernel, cudaFuncAttributeMaxDynamicSharedMemorySize, ATTN_SMEM);
    cudaFuncSetAttribute(ret_kv_kernel, cudaFuncAttributeMaxDynamicSharedMemorySize, KV_SMEM);
    cudaFuncSetAttribute(ret_out_kernel, cudaFuncAttributeMaxDynamicSharedMemorySize, OUT_SMEM);

    // split inputs + transpose-split weights
    {
        int n4 = (MROWS * DD) / 4;
        split_kernel<<<(n4 + 255) / 256, 256>>>((const float4*)x, (uint2*)xhi, (uint2*)xlo, n4);
    }
    tsplit_qkvg_kernel<<<dim3(NQKVG / 32, DD / 32), 256>>>(Wq, Wk, Wv, Wg, wallh, walll);
    tsplit_kernel<<<dim3(DD / 32, 2 * DD / 32), 256>>>(Wo, woh, wol, 2 * DD, DD);

    // combined projection GEMM (q|k|v|g)
    launch_gemm(xhi, xlo, wallh, walll, qkvg, MROWS, NQKVG, DD);

    // rope + scale (vectorized)
    {
        int total = BB * TT * HH * 16;
        rope_kernel<<<(total + 255) / 256, 256>>>(qkvg);
    }

    // retention: 4 parallel phases
    ret_attn_kernel<<<dim3(NCHUNK, HH, BB), 256, ATTN_SMEM>>>(qkvg, attn);
    ret_kv_kernel<<<dim3(4 * NCHUNK, HH, BB), 256, KV_SMEM>>>(qkvg, kv);
    ret_scan_kernel<<<(NBH * DKk * DVv / 4) / 256, 256>>>((const float4*)kv, (float4*)S);
    ret_out_kernel<<<dim3(4 * NCHUNK, HH, BB), 256, OUT_SMEM>>>(qkvg, attn, S, o);

    // rmsnorm + gate + split (fused, vectorized)
    {
        int warps = MROWS * HH;
        normgate_split_kernel<<<(warps * 32 + 255) / 256, 256>>>(o, qkvg, norm_w, ohi, olo);
    }

    // output projection on tensor cores
    launch_gemm(ohi, olo, woh, wol, out, MROWS, DD, 2 * DD);
}

// round 14
// speedup vs baseline: 1.3653x; 1.0013x over previous
#include <cuda_runtime.h>
#include <cuda_bf16.h>
#include <math.h>
#include <stdint.h>

// ---------------- problem constants ----------------
#define BB 4
#define TT 2048
#define DD 1024
#define HH 8
#define DKk 128
#define DVv 256
#define CC 64
#define NCHUNK (TT / CC)   // 32
#define MROWS (BB * TT)    // 8192
#define NBH (BB * HH)      // 32
#define NQKVG 6144         // q(1024) | k(1024) | v(2048) | g(2048)

// ---------------- scratch (no runtime allocation allowed) ----------------
__device__ float g_qkvg[MROWS * NQKVG];
__device__ float g_o[MROWS * HH * DVv];

// retention intermediates
__device__ float g_attn[NBH * NCHUNK * CC * CC];
__device__ float g_kv[NBH * NCHUNK * DKk * DVv];
__device__ float g_S[NBH * NCHUNK * DKk * DVv];

// bf16 split operands
__device__ __nv_bfloat16 g_xhi[MROWS * DD];
__device__ __nv_bfloat16 g_xlo[MROWS * DD];
__device__ __nv_bfloat16 g_ohi[MROWS * HH * DVv];
__device__ __nv_bfloat16 g_olo[MROWS * HH * DVv];
// transposed weights [N, K]
__device__ __nv_bfloat16 g_wall_hi[NQKVG * DD], g_wall_lo[NQKVG * DD];
__device__ __nv_bfloat16 g_wo_hi[2 * DD * DD],  g_wo_lo[2 * DD * DD];

// ================= PTX helpers (plain sm_80+ ISA only) =================
__device__ __forceinline__ uint32_t smem_u32(const void* p) {
    uint32_t a;
    asm("{ .reg .u64 t; cvta.to.shared.u64 t, %1; cvt.u32.u64 %0, t; }" : "=r"(a) : "l"(p));
    return a;
}
#define CP_ASYNC16(dst, src) \
    asm volatile("cp.async.cg.shared.global [%0], [%1], 16;" :: "r"(dst), "l"(src))
#define CP_ASYNC_COMMIT() asm volatile("cp.async.commit_group;" ::: "memory")
#define CP_ASYNC_WAIT1() asm volatile("cp.async.wait_group 1;" ::: "memory")

__device__ __forceinline__ void ldsm4(uint32_t* r, uint32_t addr) {
    asm volatile("ldmatrix.sync.aligned.m8n8.x4.shared.b16 {%0,%1,%2,%3}, [%4];"
        : "=r"(r[0]), "=r"(r[1]), "=r"(r[2]), "=r"(r[3]) : "r"(addr));
}
__device__ __forceinline__ void mma16816(float* c, const uint32_t* a, const uint32_t* b) {
    asm volatile("mma.sync.aligned.m16n8k16.row.col.f32.bf16.bf16.f32 "
        "{%0,%1,%2,%3}, {%4,%5,%6,%7}, {%8,%9}, {%0,%1,%2,%3};"
        : "+f"(c[0]), "+f"(c[1]), "+f"(c[2]), "+f"(c[3])
        : "r"(a[0]), "r"(a[1]), "r"(a[2]), "r"(a[3]), "r"(b[0]), "r"(b[1]));
}

// ================= split-bf16 tensor-core GEMM =================
#define GSTAGES 3
#define GMAT_BYTES (128 * 64)
#define GSTAGE_BYTES (4 * GMAT_BYTES)
#define GEMM_SMEM_BYTES (GSTAGES * GSTAGE_BYTES)

__device__ __forceinline__ uint32_t swz(int row, int c16) {
    return (uint32_t)(row * 64 + ((c16 ^ ((row >> 1) & 3)) << 4));
}

__device__ __forceinline__ void load_tile32(uint32_t dst, const __nv_bfloat16* src,
                                            int row0, int k0, int ldk, int tid) {
    const char* gbase = (const char*)(src + (size_t)row0 * ldk + k0);
    const size_t rowb = (size_t)ldk * 2;
#pragma unroll
    for (int j = 0; j < 4; j++) {
        int e = tid + j * 128;
        int r = e >> 2, c16 = e & 3;
        CP_ASYNC16(dst + swz(r, c16), gbase + (size_t)r * rowb + c16 * 16);
    }
}

__global__ __launch_bounds__(128, 2) void gemm_split_mma(
    const __nv_bfloat16* __restrict__ Ahi, const __nv_bfloat16* __restrict__ Alo,
    const __nv_bfloat16* __restrict__ Bhi, const __nv_bfloat16* __restrict__ Blo,
    float* __restrict__ C, int M, int N, int K) {
    extern __shared__ char smem[];
    const uint32_t sb = smem_u32(smem);
    const int tid = threadIdx.x, lane = tid & 31, wid = tid >> 5;
    const int wm = wid & 1, wn = wid >> 1;
    const int m0 = blockIdx.y * 128, n0 = blockIdx.x * 128;
    const int nchunk = K >> 5;

    const int a_row = (lane & 7) + 8 * ((lane >> 3) & 1);
    const int a_c8  = lane >> 4;
    const int b_row = (lane & 7) + 8 * (lane >> 4);
    const int b_c8  = (lane >> 3) & 1;

    const int arow = wm * 64 + a_row;
    const int selA = (arow >> 1) & 3;
    const int brow = wn * 64 + b_row;
    const int selB = (brow >> 1) & 3;

    float acc[4][8][4];
#pragma unroll
    for (int i = 0; i < 4; i++)
#pragma unroll
        for (int j = 0; j < 8; j++)
#pragma unroll
            for (int r = 0; r < 4; r++) acc[i][j][r] = 0.f;

#pragma unroll
    for (int s = 0; s < GSTAGES; s++) {
        uint32_t st = sb + s * GSTAGE_BYTES;
        int k0 = s * 32;
        load_tile32(st,                  Ahi, m0, k0, K, tid);
        load_tile32(st + GMAT_BYTES,     Alo, m0, k0, K, tid);
        load_tile32(st + 2 * GMAT_BYTES, Bhi, n0, k0, K, tid);
        load_tile32(st + 3 * GMAT_BYTES, Blo, n0, k0, K, tid);
        CP_ASYNC_COMMIT();
    }

    for (int c = 0; c < nchunk; c++) {
        uint32_t st = sb + (c % GSTAGES) * GSTAGE_BYTES;
        CP_ASYNC_WAIT1();
        __syncthreads();

        if (c >= 1) {
            if (c + 2 < nchunk) {
                uint32_t st2 = sb + ((c + 2) % GSTAGES) * GSTAGE_BYTES;
                int k0 = (c + 2) * 32;
                load_tile32(st2,                  Ahi, m0, k0, K, tid);
                load_tile32(st2 + GMAT_BYTES,     Alo, m0, k0, K, tid);
                load_tile32(st2 + 2 * GMAT_BYTES, Bhi, n0, k0, K, tid);
                load_tile32(st2 + 3 * GMAT_BYTES, Blo, n0, k0, K, tid);
            }
            CP_ASYNC_COMMIT();
        }

#pragma unroll
        for (int ks = 0; ks < 2; ks++) {
            const int ks2 = ks * 2;
            const uint32_t ca = (uint32_t)(((ks2 + a_c8) ^ selA) << 4);
            const uint32_t cb = (uint32_t)(((ks2 + b_c8) ^ selB) << 4);

            uint32_t ah[4][4], al[4][4];
#pragma unroll
            for (int mt = 0; mt < 4; mt++) {
                uint32_t ra = st + (uint32_t)((arow + mt * 16) * 64) + ca;
                ldsm4(ah[mt], ra);
                ldsm4(al[mt], ra + GMAT_BYTES);
            }
#pragma unroll
            for (int np = 0; np < 4; np++) {
                uint32_t bh[4], bl[4];
                uint32_t rb = st + 2 * GMAT_BYTES + (uint32_t)((brow + np * 16) * 64) + cb;
                ldsm4(bh, rb);
                ldsm4(bl, rb + GMAT_BYTES);
#pragma unroll
                for (int mt = 0; mt < 4; mt++)
#pragma unroll
                    for (int hf = 0; hf < 2; hf++) {
                        float* a4 = acc[mt][np * 2 + hf];
                        mma16816(a4, ah[mt], &bh[hf * 2]);
                        mma16816(a4, ah[mt], &bl[hf * 2]);
                        mma16816(a4, al[mt], &bh[hf * 2]);
                    }
            }
        }
    }

    const int crow = lane >> 2, ccol = (lane & 3) * 2;
#pragma unroll
    for (int mt = 0; mt < 4; mt++) {
        int rbase = m0 + wm * 64 + mt * 16 + crow;
#pragma unroll
        for (int nt = 0; nt < 8; nt++) {
            int cbase = n0 + wn * 64 + nt * 8 + ccol;
            float* d0 = C + (size_t)rbase * N + cbase;
            float* d1 = C + (size_t)(rbase + 8) * N + cbase;
            *(float2*)d0 = make_float2(acc[mt][nt][0], acc[mt][nt][1]);
            *(float2*)d1 = make_float2(acc[mt][nt][2], acc[mt][nt][3]);
        }
    }
}

// ================= fused prep: split_x | tsplit_qkvg | tsplit_wo =============
__device__ __forceinline__ void tsplit_block(const float* __restrict__ W,
                                             __nv_bfloat16* __restrict__ Thi,
                                             __nv_bfloat16* __restrict__ Tlo,
                                             int K, int srcN, int n0glob, int ln0, int k0,
                                             float (*t)[33]) {
    int tx = threadIdx.x & 31, ty = threadIdx.x >> 5;
#pragma unroll
    for (int i = ty; i < 32; i += 8)
        t[i][tx] = W[(size_t)(k0 + i) * srcN + ln0 + tx];
    __syncthreads();
#pragma unroll
    for (int i = ty; i < 32; i += 8) {
        float v = t[tx][i];
        __nv_bfloat16 h = __float2bfloat16(v);
        size_t oidx = (size_t)(n0glob + i) * K + k0 + tx;
        Thi[oidx] = h;
        Tlo[oidx] = __float2bfloat16(v - __bfloat162float(h));
    }
}

#define PREP_SPLIT_BLKS 8192         // (MROWS*DD/4)/256
#define PREP_QKVG_BLKS  6144         // 192 x 32
#define PREP_WO_BLKS    2048         // 32 x 64
__global__ __launch_bounds__(256) void prep_kernel(
    const float4* __restrict__ x4, uint2* __restrict__ xhi, uint2* __restrict__ xlo,
    const float* __restrict__ Wq, const float* __restrict__ Wk,
    const float* __restrict__ Wv, const float* __restrict__ Wg,
    const float* __restrict__ Wo,
    __nv_bfloat16* __restrict__ wallh, __nv_bfloat16* __restrict__ walll,
    __nv_bfloat16* __restrict__ woh,  __nv_bfloat16* __restrict__ wol) {
    __shared__ float t[32][33];
    const int bx = blockIdx.x;
    if (bx < PREP_SPLIT_BLKS) {
        int i = bx * 256 + threadIdx.x;
        float4 v = x4[i];
        __nv_bfloat16 h0 = __float2bfloat16(v.x), h1 = __float2bfloat16(v.y);
        __nv_bfloat16 h2 = __float2bfloat16(v.z), h3 = __float2bfloat16(v.w);
        __nv_bfloat16 l0 = __float2bfloat16(v.x - __bfloat162float(h0));
        __nv_bfloat16 l1 = __float2bfloat16(v.y - __bfloat162float(h1));
        __nv_bfloat16 l2 = __float2bfloat16(v.z - __bfloat162float(h2));
        __nv_bfloat16 l3 = __float2bfloat16(v.w - __bfloat162float(h3));
        uint2 hp, lp;
        hp.x = (uint32_t)__bfloat16_as_ushort(h0) | ((uint32_t)__bfloat16_as_ushort(h1) << 16);
        hp.y = (uint32_t)__bfloat16_as_ushort(h2) | ((uint32_t)__bfloat16_as_ushort(h3) << 16);
        lp.x = (uint32_t)__bfloat16_as_ushort(l0) | ((uint32_t)__bfloat16_as_ushort(l1) << 16);
        lp.y = (uint32_t)__bfloat16_as_ushort(l2) | ((uint32_t)__bfloat16_as_ushort(l3) << 16);
        xhi[i] = hp;
        xlo[i] = lp;
    } else if (bx < PREP_SPLIT_BLKS + PREP_QKVG_BLKS) {
        int tb = bx - PREP_SPLIT_BLKS;
        int n0 = (tb % 192) * 32, k0 = (tb / 192) * 32;
        const float* W;
        int srcN, ln0;
        if (n0 < 1024)       { W = Wq; srcN = 1024; ln0 = n0; }
        else if (n0 < 2048)  { W = Wk; srcN = 1024; ln0 = n0 - 1024; }
        else if (n0 < 4096)  { W = Wv; srcN = 2048; ln0 = n0 - 2048; }
        else                 { W = Wg; srcN = 2048; ln0 = n0 - 4096; }
        tsplit_block(W, wallh, walll, DD, srcN, n0, ln0, k0, t);
    } else {
        int tb = bx - PREP_SPLIT_BLKS - PREP_QKVG_BLKS;
        int n0 = (tb % 32) * 32, k0 = (tb / 32) * 32;
        tsplit_block(Wo, woh, wol, 2 * DD, DD, n0, n0, k0, t);
    }
}

// ---------------- RoPE (vectorized float4: 4 freq indices per thread) --------
__global__ void rope_kernel(float* __restrict__ qkvg) {
    int idx = blockIdx.x * blockDim.x + threadIdx.x;
    const int total = BB * TT * HH * 16;
    if (idx >= total) return;
    int i4 = idx & 15;
    int h = (idx >> 4) & (HH - 1);
    int t = (idx >> 7) & (TT - 1);
    int b = idx >> 18;

    size_t base = ((size_t)b * TT + t) * NQKVG + h * DKk + i4 * 4;
    const float sc = 0.08838834764831845f;

    float s[4], c[4];
#pragma unroll
    for (int cc = 0; cc < 4; cc++) {
        int i = i4 * 4 + cc;
        float inv = powf(10000.f, -(float)i * (1.0f / 64.0f));
        sincosf((float)t * inv, &s[cc], &c[cc]);
    }

    float4 q1 = *(float4*)&qkvg[base];
    float4 q2 = *(float4*)&qkvg[base + 64];
    float* q1p = &q1.x; float* q2p = &q2.x;
    float4 o1, o2;
    float* o1p = &o1.x; float* o2p = &o2.x;
#pragma unroll
    for (int cc = 0; cc < 4; cc++) {
        o1p[cc] = (q1p[cc] * c[cc] - q2p[cc] * s[cc]) * sc;
        o2p[cc] = (q2p[cc] * c[cc] + q1p[cc] * s[cc]) * sc;
    }
    *(float4*)&qkvg[base]      = o1;
    *(float4*)&qkvg[base + 64] = o2;

    size_t kb = base + 1024;
    float4 k1 = *(float4*)&qkvg[kb];
    float4 k2 = *(float4*)&qkvg[kb + 64];
    float* k1p = &k1.x; float* k2p = &k2.x;
#pragma unroll
    for (int cc = 0; cc < 4; cc++) {
        o1p[cc] = k1p[cc] * c[cc] - k2p[cc] * s[cc];
        o2p[cc] = k2p[cc] * c[cc] + k1p[cc] * s[cc];
    }
    *(float4*)&qkvg[kb]      = o1;
    *(float4*)&qkvg[kb + 64] = o2;
}

// ================= fused retention phases A | B ========
// grid (32 + 128, HH, BB): x < 32 -> Phase A (n = x); else Phase B.
// smem = max(ATTN, KV) bytes.
#define ATTN_SMEM ((2 * 64 * 129 + 64) * 4)
#define KV_SMEM ((64 * 132 + 64 * 68 + 64) * 4)
#define AB_SMEM (ATTN_SMEM > KV_SMEM ? ATTN_SMEM : KV_SMEM)

__global__ __launch_bounds__(256) void ret_ab_kernel(const float* __restrict__ qkvg,
                                                     float* __restrict__ attn_out,
                                                     float* __restrict__ kv_out) {
    const int h = blockIdx.y, b = blockIdx.z;
    const int tid = threadIdx.x;
    extern __shared__ float sm[];
    const float gamma = 1.0f - exp2f(-5.0f - (float)h);

    if (blockIdx.x < NCHUNK) {
        // ---------------- Phase A ----------------
        const int n = blockIdx.x;
        float* qs   = sm;
        float* ks   = qs + 64 * 129;
        float* gpow = ks + 64 * 129;
        if (tid < 64) gpow[tid] = powf(gamma, (float)tid);

        const int t0 = n * CC;
        for (int e = tid; e < 64 * 128; e += 256) {
            int i = e >> 7, dk = e & 127;
            size_t gi = ((size_t)b * TT + t0 + i) * NQKVG + h * DKk + dk;
            qs[i * 129 + dk] = qkvg[gi];
            ks[i * 129 + dk] = qkvg[gi + 1024];
        }
        __syncthreads();

        const int ti = tid >> 4, te = tid & 15;
        float acc[4][4];
#pragma unroll
        for (int a = 0; a < 4; a++)
#pragma unroll
            for (int bq = 0; bq < 4; bq++) acc[a][bq] = 0.f;
        for (int dk = 0; dk < 128; dk++) {
            float ra[4], rb[4];
#pragma unroll
            for (int ii = 0; ii < 4; ii++) ra[ii] = qs[(ti * 4 + ii) * 129 + dk];
#pragma unroll
            for (int jj = 0; jj < 4; jj++) rb[jj] = ks[(te * 4 + jj) * 129 + dk];
#pragma unroll
            for (int ii = 0; ii < 4; ii++)
#pragma unroll
                for (int jj = 0; jj < 4; jj++) acc[ii][jj] += ra[ii] * rb[jj];
        }

        float* dst = attn_out + ((((size_t)b * HH + h) * NCHUNK + n) << 12);
#pragma unroll
        for (int ii = 0; ii < 4; ii++) {
            int i = ti * 4 + ii;
            float4 w;
            float* wp = &w.x;
#pragma unroll
            for (int jj = 0; jj < 4; jj++) {
                int j = te * 4 + jj;
                wp[jj] = (i >= j) ? acc[ii][jj] * gpow[i - j] : 0.f;
            }
            *(float4*)(dst + i * 64 + te * 4) = w;
        }
    } else {
        // ---------------- Phase B ----------------
        const int lin = blockIdx.x - NCHUNK;
        const int sl = lin & 3, n = lin >> 2;
        float* ks   = sm;               // 64 x 132
        float* vs   = ks + 64 * 132;    // 64 x 68
        float* deck = vs + 64 * 68;     // 64
        if (tid < 64) deck[tid] = powf(gamma, (float)(63 - tid));
        __syncthreads();

        const int t0 = n * CC;
        for (int e = tid; e < 64 * 32; e += 256) {
            int i = e >> 5, c4 = e & 31;
            float4 v = *(const float4*)&qkvg[((size_t)b * TT + t0 + i) * NQKVG + 1024 + h * DKk + c4 * 4];
            *(float4*)&ks[i * 132 + c4 * 4] = v;
        }
        for (int e = tid; e < 64 * 16; e += 256) {
            int i = e >> 4, c4 = e & 15;
            float d = deck[i];
            float4 v = *(const float4*)&qkvg[((size_t)b * TT + t0 + i) * NQKVG + 2048 + h * DVv + sl * 64 + c4 * 4];
            v.x *= d; v.y *= d; v.z *= d; v.w *= d;
            *(float4*)&vs[i * 68 + c4 * 4] = v;
        }
        __syncthreads();

        const int ti = tid >> 4, te = tid & 15;
        float acc[8][4];
#pragma unroll
        for (int a = 0; a < 8; a++)
#pragma unroll
            for (int bq = 0; bq < 4; bq++) acc[a][bq] = 0.f;

        for (int j = 0; j < 64; j++) {
            float4 ka = *(const float4*)&ks[j * 132 + ti * 8];
            float4 kb = *(const float4*)&ks[j * 132 + ti * 8 + 4];
            float4 vb = *(const float4*)&vs[j * 68 + te * 4];
            float ra[8] = {ka.x, ka.y, ka.z, ka.w, kb.x, kb.y, kb.z, kb.w};
            float rb[4] = {vb.x, vb.y, vb.z, vb.w};
#pragma unroll
            for (int dd = 0; dd < 8; dd++)
#pragma unroll
                for (int ee = 0; ee < 4; ee++) acc[dd][ee] += ra[dd] * rb[ee];
        }

        float* dst = kv_out + ((((size_t)b * HH + h) * NCHUNK + n) * DKk) * DVv + sl * 64;
#pragma unroll
        for (int dd = 0; dd < 8; dd++) {
            int dk = ti * 8 + dd;
            *(float4*)(dst + (size_t)dk * DVv + te * 4) =
                make_float4(acc[dd][0], acc[dd][1], acc[dd][2], acc[dd][3]);
        }
    }
}

// Phase C: prefix scan of kv -> Spre (float4 per thread)
__global__ __launch_bounds__(256) void ret_scan_kernel(const float4* __restrict__ kv,
                                                       float4* __restrict__ Spre) {
    const int idx = blockIdx.x * 256 + threadIdx.x;
    const int bh  = idx >> 13;
    const int pos = idx & 8191;
    const int h   = bh & (HH - 1);
    const float gamma = 1.0f - exp2f(-5.0f - (float)h);
    const float gC = powf(gamma, 64.0f);

    const size_t base = (size_t)bh * NCHUNK * 8192 + pos;
    float4 s = make_float4(0.f, 0.f, 0.f, 0.f);
    Spre[base] = s;
    for (int n = 1; n < NCHUNK; n++) {
        float4 kvv = kv[base + (size_t)(n - 1) * 8192];
        s.x = gC * s.x + kvv.x;
        s.y = gC * s.y + kvv.y;
        s.z = gC * s.z + kvv.z;
        s.w = gC * s.w + kvv.w;
        Spre[base + (size_t)n * 8192] = s;
    }
}

// Phase D: o = attn @ v + decq * (q @ S_pre)  — float4 fills + LDS.128
#define OUT_SMEM ((64 * 68 + 64 * 68 + 64 * 132 + 128 * 68 + 64) * 4)
__global__ __launch_bounds__(256) void ret_out_kernel(const float* __restrict__ qkvg,
                                                      const float* __restrict__ attn,
                                                      const float* __restrict__ Spre,
                                                      float* __restrict__ o) {
    const int sl = blockIdx.x & 3, n = blockIdx.x >> 2;
    const int h = blockIdx.y, b = blockIdx.z;
    const int tid = threadIdx.x;
    extern __shared__ float sm[];
    float* at   = sm;               // 64 x 68
    float* vs   = at + 64 * 68;     // 64 x 68
    float* qs   = vs + 64 * 68;     // 64 x 132
    float* Ss   = qs + 64 * 132;    // 128 x 68
    float* decq = Ss + 128 * 68;    // 64

    const float gamma = 1.0f - exp2f(-5.0f - (float)h);
    if (tid < 64) decq[tid] = powf(gamma, (float)(tid + 1));

    const int t0 = n * CC;
    const size_t bh = (size_t)b * HH + h;
    const float* asrc = attn + ((bh * NCHUNK + n) << 12);
    for (int e = tid; e < 64 * 16; e += 256) {
        int i = e >> 4, c4 = e & 15;
        *(float4*)&at[i * 68 + c4 * 4] = *(const float4*)&asrc[i * 64 + c4 * 4];
        *(float4*)&vs[i * 68 + c4 * 4] =
            *(const float4*)&qkvg[((size_t)b * TT + t0 + i) * NQKVG + 2048 + h * DVv + sl * 64 + c4 * 4];
    }
    for (int e = tid; e < 64 * 32; e += 256) {
        int i = e >> 5, c4 = e & 31;
        *(float4*)&qs[i * 132 + c4 * 4] =
            *(const float4*)&qkvg[((size_t)b * TT + t0 + i) * NQKVG + h * DKk + c4 * 4];
    }
    const float* ssrc = Spre + ((bh * NCHUNK + n) * DKk) * DVv + sl * 64;
    for (int e = tid; e < 128 * 16; e += 256) {
        int dk = e >> 4, c4 = e & 15;
        *(float4*)&Ss[dk * 68 + c4 * 4] = *(const float4*)&ssrc[(size_t)dk * DVv + c4 * 4];
    }
    __syncthreads();

    const int ti = tid >> 4, te = tid & 15;
    float aI[4][4], aS[4][4];
#pragma unroll
    for (int a = 0; a < 4; a++)
#pragma unroll
        for (int bq = 0; bq < 4; bq++) { aI[a][bq] = 0.f; aS[a][bq] = 0.f; }

    for (int jg = 0; jg < 16; jg++) {
        float4 ra4[4];
#pragma unroll
        for (int ii = 0; ii < 4; ii++)
            ra4[ii] = *(const float4*)&at[(ti * 4 + ii) * 68 + jg * 4];
#pragma unroll
        for (int jj = 0; jj < 4; jj++) {
            float4 vb = *(const float4*)&vs[(jg * 4 + jj) * 68 + te * 4];
#pragma unroll
            for (int ii = 0; ii < 4; ii++) {
                float ra = ((const float*)&ra4[ii])[jj];
                aI[ii][0] += ra * vb.x;
                aI[ii][1] += ra * vb.y;
                aI[ii][2] += ra * vb.z;
                aI[ii][3] += ra * vb.w;
            }
        }
    }
    for (int dg = 0; dg < 32; dg++) {
        float4 ra4[4];
#pragma unroll
        for (int ii = 0; ii < 4; ii++)
            ra4[ii] = *(const float4*)&qs[(ti * 4 + ii) * 132 + dg * 4];
#pragma unroll
        for (int dd = 0; dd < 4; dd++) {
            float4 sb4 = *(const float4*)&Ss[(dg * 4 + dd) * 68 + te * 4];
#pragma unroll
            for (int ii = 0; ii < 4; ii++) {
                float ra = ((const float*)&ra4[ii])[dd];
                aS[ii][0] += ra * sb4.x;
                aS[ii][1] += ra * sb4.y;
                aS[ii][2] += ra * sb4.z;
                aS[ii][3] += ra * sb4.w;
            }
        }
    }

#pragma unroll
    for (int ii = 0; ii < 4; ii++) {
        int i = ti * 4 + ii;
        float dq = decq[i];
        size_t base = (((size_t)b * TT + t0 + i) * HH + h) * DVv + sl * 64 + te * 4;
        *(float4*)(&o[base]) = make_float4(aI[ii][0] + dq * aS[ii][0],
                                           aI[ii][1] + dq * aS[ii][1],
                                           aI[ii][2] + dq * aS[ii][2],
                                           aI[ii][3] + dq * aS[ii][3]);
    }
}

// ---------------- RMSNorm + swish gate + bf16 split (vectorized) ----
__global__ __launch_bounds__(256) void normgate_split_kernel(const float* __restrict__ o,
                                                             const float* __restrict__ qkvg,
                                                             const float* __restrict__ norm_w,
                                                             __nv_bfloat16* __restrict__ ohi,
                                                             __nv_bfloat16* __restrict__ olo) {
    int warp = (blockIdx.x * blockDim.x + threadIdx.x) >> 5;
    int lane = threadIdx.x & 31;
    if (warp >= MROWS * HH) return;
    size_t base  = (size_t)warp * DVv + lane * 8;
    size_t gbase = (size_t)(warp >> 3) * NQKVG + 4096 + (size_t)(warp & 7) * DVv + lane * 8;

    float4 v0 = *(const float4*)(o + base);
    float4 v1 = *(const float4*)(o + base + 4);
    float vals[8] = {v0.x, v0.y, v0.z, v0.w, v1.x, v1.y, v1.z, v1.w};

    float ss = 0.f;
#pragma unroll
    for (int r = 0; r < 8; r++) ss += vals[r] * vals[r];
#pragma unroll
    for (int off = 16; off; off >>= 1) ss += __shfl_xor_sync(0xFFFFFFFFu, ss, off);
    float inv = rsqrtf(ss * (1.0f / 256.0f) + 1e-5f);

    float4 g0 = *(const float4*)(qkvg + gbase);
    float4 g1 = *(const float4*)(qkvg + gbase + 4);
    float gv[8] = {g0.x, g0.y, g0.z, g0.w, g1.x, g1.y, g1.z, g1.w};
    float4 w0 = *(const float4*)(norm_w + lane * 8);
    float4 w1 = *(const float4*)(norm_w + lane * 8 + 4);
    float wv[8] = {w0.x, w0.y, w0.z, w0.w, w1.x, w1.y, w1.z, w1.w};

    uint32_t hp[4], lp[4];
#pragma unroll
    for (int p = 0; p < 4; p++) {
        float r0, r1;
        {
            float sg = 1.f / (1.f + expf(-gv[2 * p]));
            r0 = vals[2 * p] * inv * wv[2 * p] * gv[2 * p] * sg;
        }
        {
            float sg = 1.f / (1.f + expf(-gv[2 * p + 1]));
            r1 = vals[2 * p + 1] * inv * wv[2 * p + 1] * gv[2 * p + 1] * sg;
        }
        __nv_bfloat16 h0 = __float2bfloat16(r0), h1 = __float2bfloat16(r1);
        __nv_bfloat16 l0 = __float2bfloat16(r0 - __bfloat162float(h0));
        __nv_bfloat16 l1 = __float2bfloat16(r1 - __bfloat162float(h1));
        hp[p] = (uint32_t)__bfloat16_as_ushort(h0) | ((uint32_t)__bfloat16_as_ushort(h1) << 16);
        lp[p] = (uint32_t)__bfloat16_as_ushort(l0) | ((uint32_t)__bfloat16_as_ushort(l1) << 16);
    }
    *(uint4*)(ohi + base) = make_uint4(hp[0], hp[1], hp[2], hp[3]);
    *(uint4*)(olo + base) = make_uint4(lp[0], lp[1], lp[2], lp[3]);
}

// ---------------- launch ----------------
static void launch_gemm(const __nv_bfloat16* Ahi, const __nv_bfloat16* Alo,
                        const __nv_bfloat16* Bhi, const __nv_bfloat16* Blo,
                        float* C, int M, int N, int K) {
    gemm_split_mma<<<dim3(N / 128, M / 128), 128, GEMM_SMEM_BYTES>>>(Ahi, Alo, Bhi, Blo, C, M, N, K);
}

extern "C" void kernel_launch(void* const* d_in, const int* in_sizes, int n_in,
                              void* d_out, int out_size) {
    const float* x      = (const float*)d_in[0];
    const float* Wq     = (const float*)d_in[1];
    const float* Wk     = (const float*)d_in[2];
    const float* Wv     = (const float*)d_in[3];
    const float* Wg     = (const float*)d_in[4];
    const float* Wo     = (const float*)d_in[5];
    const float* norm_w = (const float*)d_in[6];
    float* out = (float*)d_out;

    float *qkvg, *o, *attn, *kv, *S;
    cudaGetSymbolAddress((void**)&qkvg, g_qkvg);
    cudaGetSymbolAddress((void**)&o, g_o);
    cudaGetSymbolAddress((void**)&attn, g_attn);
    cudaGetSymbolAddress((void**)&kv, g_kv);
    cudaGetSymbolAddress((void**)&S, g_S);
    __nv_bfloat16 *xhi, *xlo, *ohi, *olo, *wallh, *walll, *woh, *wol;
    cudaGetSymbolAddress((void**)&xhi, g_xhi);
    cudaGetSymbolAddress((void**)&xlo, g_xlo);
    cudaGetSymbolAddress((void**)&ohi, g_ohi);
    cudaGetSymbolAddress((void**)&olo, g_olo);
    cudaGetSymbolAddress((void**)&wallh, g_wall_hi);
    cudaGetSymbolAddress((void**)&walll, g_wall_lo);
    cudaGetSymbolAddress((void**)&woh, g_wo_hi);
    cudaGetSymbolAddress((void**)&wol, g_wo_lo);

    cudaFuncSetAttribute(gemm_split_mma, cudaFuncAttributeMaxDynamicSharedMemorySize, GEMM_SMEM_BYTES);
    cudaFuncSetAttribute(ret_ab_kernel, cudaFuncAttributeMaxDynamicSharedMemorySize, AB_SMEM);
    cudaFuncSetAttribute(ret_out_kernel, cudaFuncAttributeMaxDynamicSharedMemorySize, OUT_SMEM);

    // fused prep: split x | transpose-split qkvg weights | transpose-split Wo
    prep_kernel<<<PREP_SPLIT_BLKS + PREP_QKVG_BLKS + PREP_WO_BLKS, 256>>>(
        (const float4*)x, (uint2*)xhi, (uint2*)xlo,
        Wq, Wk, Wv, Wg, Wo, wallh, walll, woh, wol);

    // combined projection GEMM (q|k|v|g)
    launch_gemm(xhi, xlo, wallh, walll, qkvg, MROWS, NQKVG, DD);

    // rope + scale (vectorized)
    {
        int total = BB * TT * HH * 16;
        rope_kernel<<<(total + 255) / 256, 256>>>(qkvg);
    }

    // retention: fused A|B, then scan, then D
    ret_ab_kernel<<<dim3(NCHUNK + 4 * NCHUNK, HH, BB), 256, AB_SMEM>>>(qkvg, attn, kv);
    ret_scan_kernel<<<(NBH * DKk * DVv / 4) / 256, 256>>>((const float4*)kv, (float4*)S);
    ret_out_kernel<<<dim3(4 * NCHUNK, HH, BB), 256, OUT_SMEM>>>(qkvg, attn, S, o);

    // rmsnorm + gate + split (fused, vectorized)
    {
        int warps = MROWS * HH;
        normgate_split_kernel<<<(warps * 32 + 255) / 256, 256>>>(o, qkvg, norm_w, ohi, olo);
    }

    // output projection on tensor cores
    launch_gemm(ohi, olo, woh, wol, out, MROWS, DD, 2 * DD);
}

// round 15
// speedup vs baseline: 1.4235x; 1.0426x over previous
#include <cuda_runtime.h>
#include <cuda_bf16.h>
#include <math.h>
#include <stdint.h>

// ---------------- problem constants ----------------
#define BB 4
#define TT 2048
#define DD 1024
#define HH 8
#define DKk 128
#define DVv 256
#define CC 64
#define NCHUNK (TT / CC)   // 32
#define MROWS (BB * TT)    // 8192
#define NBH (BB * HH)      // 32
#define NQKVG 6144         // q(1024) | k(1024) | v(2048) | g(2048)

// ---------------- scratch (no runtime allocation allowed) ----------------
__device__ float g_qkvg[MROWS * NQKVG];
__device__ float g_o[MROWS * HH * DVv];

// retention intermediates
__device__ float g_attn[NBH * NCHUNK * CC * CC];
__device__ float g_kv[NBH * NCHUNK * DKk * DVv];
__device__ float g_S[NBH * NCHUNK * DKk * DVv];

// bf16 split operands
__device__ __nv_bfloat16 g_xhi[MROWS * DD];
__device__ __nv_bfloat16 g_xlo[MROWS * DD];
__device__ __nv_bfloat16 g_ohi[MROWS * HH * DVv];
__device__ __nv_bfloat16 g_olo[MROWS * HH * DVv];
// transposed weights [N, K]
__device__ __nv_bfloat16 g_wall_hi[NQKVG * DD], g_wall_lo[NQKVG * DD];
__device__ __nv_bfloat16 g_wo_hi[2 * DD * DD],  g_wo_lo[2 * DD * DD];

// ================= PTX helpers (plain sm_80+ ISA only) =================
__device__ __forceinline__ uint32_t smem_u32(const void* p) {
    uint32_t a;
    asm("{ .reg .u64 t; cvta.to.shared.u64 t, %1; cvt.u32.u64 %0, t; }" : "=r"(a) : "l"(p));
    return a;
}
#define CP_ASYNC16(dst, src) \
    asm volatile("cp.async.cg.shared.global [%0], [%1], 16;" :: "r"(dst), "l"(src))
#define CP_ASYNC_COMMIT() asm volatile("cp.async.commit_group;" ::: "memory")
#define CP_ASYNC_WAIT1() asm volatile("cp.async.wait_group 1;" ::: "memory")

__device__ __forceinline__ void ldsm4(uint32_t* r, uint32_t addr) {
    asm volatile("ldmatrix.sync.aligned.m8n8.x4.shared.b16 {%0,%1,%2,%3}, [%4];"
        : "=r"(r[0]), "=r"(r[1]), "=r"(r[2]), "=r"(r[3]) : "r"(addr));
}
__device__ __forceinline__ void mma16816(float* c, const uint32_t* a, const uint32_t* b) {
    asm volatile("mma.sync.aligned.m16n8k16.row.col.f32.bf16.bf16.f32 "
        "{%0,%1,%2,%3}, {%4,%5,%6,%7}, {%8,%9}, {%0,%1,%2,%3};"
        : "+f"(c[0]), "+f"(c[1]), "+f"(c[2]), "+f"(c[3])
        : "r"(a[0]), "r"(a[1]), "r"(a[2]), "r"(a[3]), "r"(b[0]), "r"(b[1]));
}

// ================= split-bf16 tensor-core GEMM =================
#define GSTAGES 3
#define GMAT_BYTES (128 * 64)
#define GSTAGE_BYTES (4 * GMAT_BYTES)
#define GEMM_SMEM_BYTES (GSTAGES * GSTAGE_BYTES)

__device__ __forceinline__ uint32_t swz(int row, int c16) {
    return (uint32_t)(row * 64 + ((c16 ^ ((row >> 1) & 3)) << 4));
}

__device__ __forceinline__ void load_tile32(uint32_t dst, const __nv_bfloat16* src,
                                            int row0, int k0, int ldk, int tid) {
    const char* gbase = (const char*)(src + (size_t)row0 * ldk + k0);
    const size_t rowb = (size_t)ldk * 2;
#pragma unroll
    for (int j = 0; j < 4; j++) {
        int e = tid + j * 128;
        int r = e >> 2, c16 = e & 3;
        CP_ASYNC16(dst + swz(r, c16), gbase + (size_t)r * rowb + c16 * 16);
    }
}

__global__ __launch_bounds__(128, 2) void gemm_split_mma(
    const __nv_bfloat16* __restrict__ Ahi, const __nv_bfloat16* __restrict__ Alo,
    const __nv_bfloat16* __restrict__ Bhi, const __nv_bfloat16* __restrict__ Blo,
    float* __restrict__ C, int M, int N, int K) {
    extern __shared__ char smem[];
    const uint32_t sb = smem_u32(smem);
    const int tid = threadIdx.x, lane = tid & 31, wid = tid >> 5;
    const int wm = wid & 1, wn = wid >> 1;
    const int m0 = blockIdx.y * 128, n0 = blockIdx.x * 128;
    const int nchunk = K >> 5;

    const int a_row = (lane & 7) + 8 * ((lane >> 3) & 1);
    const int a_c8  = lane >> 4;
    const int b_row = (lane & 7) + 8 * (lane >> 4);
    const int b_c8  = (lane >> 3) & 1;

    const int arow = wm * 64 + a_row;
    const int selA = (arow >> 1) & 3;
    const int brow = wn * 64 + b_row;
    const int selB = (brow >> 1) & 3;

    float acc[4][8][4];
#pragma unroll
    for (int i = 0; i < 4; i++)
#pragma unroll
        for (int j = 0; j < 8; j++)
#pragma unroll
            for (int r = 0; r < 4; r++) acc[i][j][r] = 0.f;

#pragma unroll
    for (int s = 0; s < GSTAGES; s++) {
        uint32_t st = sb + s * GSTAGE_BYTES;
        int k0 = s * 32;
        load_tile32(st,                  Ahi, m0, k0, K, tid);
        load_tile32(st + GMAT_BYTES,     Alo, m0, k0, K, tid);
        load_tile32(st + 2 * GMAT_BYTES, Bhi, n0, k0, K, tid);
        load_tile32(st + 3 * GMAT_BYTES, Blo, n0, k0, K, tid);
        CP_ASYNC_COMMIT();
    }

    for (int c = 0; c < nchunk; c++) {
        uint32_t st = sb + (c % GSTAGES) * GSTAGE_BYTES;
        CP_ASYNC_WAIT1();
        __syncthreads();

        if (c >= 1) {
            if (c + 2 < nchunk) {
                uint32_t st2 = sb + ((c + 2) % GSTAGES) * GSTAGE_BYTES;
                int k0 = (c + 2) * 32;
                load_tile32(st2,                  Ahi, m0, k0, K, tid);
                load_tile32(st2 + GMAT_BYTES,     Alo, m0, k0, K, tid);
                load_tile32(st2 + 2 * GMAT_BYTES, Bhi, n0, k0, K, tid);
                load_tile32(st2 + 3 * GMAT_BYTES, Blo, n0, k0, K, tid);
            }
            CP_ASYNC_COMMIT();
        }

#pragma unroll
        for (int ks = 0; ks < 2; ks++) {
            const int ks2 = ks * 2;
            const uint32_t ca = (uint32_t)(((ks2 + a_c8) ^ selA) << 4);
            const uint32_t cb = (uint32_t)(((ks2 + b_c8) ^ selB) << 4);

            uint32_t ah[4][4], al[4][4];
#pragma unroll
            for (int mt = 0; mt < 4; mt++) {
                uint32_t ra = st + (uint32_t)((arow + mt * 16) * 64) + ca;
                ldsm4(ah[mt], ra);
                ldsm4(al[mt], ra + GMAT_BYTES);
            }
#pragma unroll
            for (int np = 0; np < 4; np++) {
                uint32_t bh[4], bl[4];
                uint32_t rb = st + 2 * GMAT_BYTES + (uint32_t)((brow + np * 16) * 64) + cb;
                ldsm4(bh, rb);
                ldsm4(bl, rb + GMAT_BYTES);
#pragma unroll
                for (int mt = 0; mt < 4; mt++)
#pragma unroll
                    for (int hf = 0; hf < 2; hf++) {
                        float* a4 = acc[mt][np * 2 + hf];
                        mma16816(a4, ah[mt], &bh[hf * 2]);
                        mma16816(a4, ah[mt], &bl[hf * 2]);
                        mma16816(a4, al[mt], &bh[hf * 2]);
                    }
            }
        }
    }

    const int crow = lane >> 2, ccol = (lane & 3) * 2;
#pragma unroll
    for (int mt = 0; mt < 4; mt++) {
        int rbase = m0 + wm * 64 + mt * 16 + crow;
#pragma unroll
        for (int nt = 0; nt < 8; nt++) {
            int cbase = n0 + wn * 64 + nt * 8 + ccol;
            float* d0 = C + (size_t)rbase * N + cbase;
            float* d1 = C + (size_t)(rbase + 8) * N + cbase;
            *(float2*)d0 = make_float2(acc[mt][nt][0], acc[mt][nt][1]);
            *(float2*)d1 = make_float2(acc[mt][nt][2], acc[mt][nt][3]);
        }
    }
}

// ================= fused prep: split_x | tsplit_qkvg | tsplit_wo =============
__device__ __forceinline__ void tsplit_block(const float* __restrict__ W,
                                             __nv_bfloat16* __restrict__ Thi,
                                             __nv_bfloat16* __restrict__ Tlo,
                                             int K, int srcN, int n0glob, int ln0, int k0,
                                             float (*t)[33]) {
    int tx = threadIdx.x & 31, ty = threadIdx.x >> 5;
#pragma unroll
    for (int i = ty; i < 32; i += 8)
        t[i][tx] = W[(size_t)(k0 + i) * srcN + ln0 + tx];
    __syncthreads();
#pragma unroll
    for (int i = ty; i < 32; i += 8) {
        float v = t[tx][i];
        __nv_bfloat16 h = __float2bfloat16(v);
        size_t oidx = (size_t)(n0glob + i) * K + k0 + tx;
        Thi[oidx] = h;
        Tlo[oidx] = __float2bfloat16(v - __bfloat162float(h));
    }
}

#define PREP_SPLIT_BLKS 8192
#define PREP_QKVG_BLKS  6144
#define PREP_WO_BLKS    2048
__global__ __launch_bounds__(256) void prep_kernel(
    const float4* __restrict__ x4, uint2* __restrict__ xhi, uint2* __restrict__ xlo,
    const float* __restrict__ Wq, const float* __restrict__ Wk,
    const float* __restrict__ Wv, const float* __restrict__ Wg,
    const float* __restrict__ Wo,
    __nv_bfloat16* __restrict__ wallh, __nv_bfloat16* __restrict__ walll,
    __nv_bfloat16* __restrict__ woh,  __nv_bfloat16* __restrict__ wol) {
    __shared__ float t[32][33];
    const int bx = blockIdx.x;
    if (bx < PREP_SPLIT_BLKS) {
        int i = bx * 256 + threadIdx.x;
        float4 v = x4[i];
        __nv_bfloat16 h0 = __float2bfloat16(v.x), h1 = __float2bfloat16(v.y);
        __nv_bfloat16 h2 = __float2bfloat16(v.z), h3 = __float2bfloat16(v.w);
        __nv_bfloat16 l0 = __float2bfloat16(v.x - __bfloat162float(h0));
        __nv_bfloat16 l1 = __float2bfloat16(v.y - __bfloat162float(h1));
        __nv_bfloat16 l2 = __float2bfloat16(v.z - __bfloat162float(h2));
        __nv_bfloat16 l3 = __float2bfloat16(v.w - __bfloat162float(h3));
        uint2 hp, lp;
        hp.x = (uint32_t)__bfloat16_as_ushort(h0) | ((uint32_t)__bfloat16_as_ushort(h1) << 16);
        hp.y = (uint32_t)__bfloat16_as_ushort(h2) | ((uint32_t)__bfloat16_as_ushort(h3) << 16);
        lp.x = (uint32_t)__bfloat16_as_ushort(l0) | ((uint32_t)__bfloat16_as_ushort(l1) << 16);
        lp.y = (uint32_t)__bfloat16_as_ushort(l2) | ((uint32_t)__bfloat16_as_ushort(l3) << 16);
        xhi[i] = hp;
        xlo[i] = lp;
    } else if (bx < PREP_SPLIT_BLKS + PREP_QKVG_BLKS) {
        int tb = bx - PREP_SPLIT_BLKS;
        int n0 = (tb % 192) * 32, k0 = (tb / 192) * 32;
        const float* W;
        int srcN, ln0;
        if (n0 < 1024)       { W = Wq; srcN = 1024; ln0 = n0; }
        else if (n0 < 2048)  { W = Wk; srcN = 1024; ln0 = n0 - 1024; }
        else if (n0 < 4096)  { W = Wv; srcN = 2048; ln0 = n0 - 2048; }
        else                 { W = Wg; srcN = 2048; ln0 = n0 - 4096; }
        tsplit_block(W, wallh, walll, DD, srcN, n0, ln0, k0, t);
    } else {
        int tb = bx - PREP_SPLIT_BLKS - PREP_QKVG_BLKS;
        int n0 = (tb % 32) * 32, k0 = (tb / 32) * 32;
        tsplit_block(Wo, woh, wol, 2 * DD, DD, n0, n0, k0, t);
    }
}

// ---------------- RoPE (vectorized float4) -----------------------------------
__global__ void rope_kernel(float* __restrict__ qkvg) {
    int idx = blockIdx.x * blockDim.x + threadIdx.x;
    const int total = BB * TT * HH * 16;
    if (idx >= total) return;
    int i4 = idx & 15;
    int h = (idx >> 4) & (HH - 1);
    int t = (idx >> 7) & (TT - 1);
    int b = idx >> 18;

    size_t base = ((size_t)b * TT + t) * NQKVG + h * DKk + i4 * 4;
    const float sc = 0.08838834764831845f;

    float s[4], c[4];
#pragma unroll
    for (int cc = 0; cc < 4; cc++) {
        int i = i4 * 4 + cc;
        float inv = powf(10000.f, -(float)i * (1.0f / 64.0f));
        sincosf((float)t * inv, &s[cc], &c[cc]);
    }

    float4 q1 = *(float4*)&qkvg[base];
    float4 q2 = *(float4*)&qkvg[base + 64];
    float* q1p = &q1.x; float* q2p = &q2.x;
    float4 o1, o2;
    float* o1p = &o1.x; float* o2p = &o2.x;
#pragma unroll
    for (int cc = 0; cc < 4; cc++) {
        o1p[cc] = (q1p[cc] * c[cc] - q2p[cc] * s[cc]) * sc;
        o2p[cc] = (q2p[cc] * c[cc] + q1p[cc] * s[cc]) * sc;
    }
    *(float4*)&qkvg[base]      = o1;
    *(float4*)&qkvg[base + 64] = o2;

    size_t kb = base + 1024;
    float4 k1 = *(float4*)&qkvg[kb];
    float4 k2 = *(float4*)&qkvg[kb + 64];
    float* k1p = &k1.x; float* k2p = &k2.x;
#pragma unroll
    for (int cc = 0; cc < 4; cc++) {
        o1p[cc] = k1p[cc] * c[cc] - k2p[cc] * s[cc];
        o2p[cc] = k2p[cc] * c[cc] + k1p[cc] * s[cc];
    }
    *(float4*)&qkvg[kb]      = o1;
    *(float4*)&qkvg[kb + 64] = o2;
}

// ================= fused retention phases A | B ========
// A now uses dk-halved k tile + vectorized compute: smem = B's footprint.
// A: qs 64x132 + ks 64x68 + 64 = 12864 floats
// B: ks 64x132 + vs 64x68 + 64 = 12864 floats
#define AB_SMEM (12864 * 4)

__global__ __launch_bounds__(256) void ret_ab_kernel(const float* __restrict__ qkvg,
                                                     float* __restrict__ attn_out,
                                                     float* __restrict__ kv_out) {
    const int h = blockIdx.y, b = blockIdx.z;
    const int tid = threadIdx.x;
    extern __shared__ float sm[];
    const float gamma = 1.0f - exp2f(-5.0f - (float)h);

    if (blockIdx.x < NCHUNK) {
        // ---------------- Phase A ----------------
        const int n = blockIdx.x;
        float* qs   = sm;               // 64 x 132 (full dk)
        float* ks   = qs + 64 * 132;    // 64 x 68 (dk half)
        float* gpow = ks + 64 * 68;     // 64
        if (tid < 64) gpow[tid] = powf(gamma, (float)tid);

        const int t0 = n * CC;
        for (int e = tid; e < 64 * 32; e += 256) {
            int i = e >> 5, c4 = e & 31;
            *(float4*)&qs[i * 132 + c4 * 4] =
                *(const float4*)&qkvg[((size_t)b * TT + t0 + i) * NQKVG + h * DKk + c4 * 4];
        }

        const int ti = tid >> 4, te = tid & 15;
        float acc[4][4];
#pragma unroll
        for (int a = 0; a < 4; a++)
#pragma unroll
            for (int bq = 0; bq < 4; bq++) acc[a][bq] = 0.f;

#pragma unroll
        for (int half = 0; half < 2; half++) {
            if (half) __syncthreads();   // all reads of prev ks half done
            for (int e = tid; e < 64 * 16; e += 256) {
                int i = e >> 4, c4 = e & 15;
                *(float4*)&ks[i * 68 + c4 * 4] =
                    *(const float4*)&qkvg[((size_t)b * TT + t0 + i) * NQKVG + 1024 + h * DKk + half * 64 + c4 * 4];
            }
            __syncthreads();
            for (int dg = 0; dg < 16; dg++) {
                float4 q4[4], k4[4];
#pragma unroll
                for (int ii = 0; ii < 4; ii++)
                    q4[ii] = *(const float4*)&qs[(ti * 4 + ii) * 132 + half * 64 + dg * 4];
#pragma unroll
                for (int jj = 0; jj < 4; jj++)
                    k4[jj] = *(const float4*)&ks[(te * 4 + jj) * 68 + dg * 4];
#pragma unroll
                for (int dd = 0; dd < 4; dd++)
#pragma unroll
                    for (int ii = 0; ii < 4; ii++) {
                        float ra = ((const float*)&q4[ii])[dd];
#pragma unroll
                        for (int jj = 0; jj < 4; jj++)
                            acc[ii][jj] += ra * ((const float*)&k4[jj])[dd];
                    }
            }
        }

        float* dst = attn_out + ((((size_t)b * HH + h) * NCHUNK + n) << 12);
#pragma unroll
        for (int ii = 0; ii < 4; ii++) {
            int i = ti * 4 + ii;
            float4 w;
            float* wp = &w.x;
#pragma unroll
            for (int jj = 0; jj < 4; jj++) {
                int j = te * 4 + jj;
                wp[jj] = (i >= j) ? acc[ii][jj] * gpow[i - j] : 0.f;
            }
            *(float4*)(dst + i * 64 + te * 4) = w;
        }
    } else {
        // ---------------- Phase B ----------------
        const int lin = blockIdx.x - NCHUNK;
        const int sl = lin & 3, n = lin >> 2;
        float* ks   = sm;               // 64 x 132
        float* vs   = ks + 64 * 132;    // 64 x 68
        float* deck = vs + 64 * 68;     // 64
        if (tid < 64) deck[tid] = powf(gamma, (float)(63 - tid));
        __syncthreads();

        const int t0 = n * CC;
        for (int e = tid; e < 64 * 32; e += 256) {
            int i = e >> 5, c4 = e & 31;
            float4 v = *(const float4*)&qkvg[((size_t)b * TT + t0 + i) * NQKVG + 1024 + h * DKk + c4 * 4];
            *(float4*)&ks[i * 132 + c4 * 4] = v;
        }
        for (int e = tid; e < 64 * 16; e += 256) {
            int i = e >> 4, c4 = e & 15;
            float d = deck[i];
            float4 v = *(const float4*)&qkvg[((size_t)b * TT + t0 + i) * NQKVG + 2048 + h * DVv + sl * 64 + c4 * 4];
            v.x *= d; v.y *= d; v.z *= d; v.w *= d;
            *(float4*)&vs[i * 68 + c4 * 4] = v;
        }
        __syncthreads();

        const int ti = tid >> 4, te = tid & 15;
        float acc[8][4];
#pragma unroll
        for (int a = 0; a < 8; a++)
#pragma unroll
            for (int bq = 0; bq < 4; bq++) acc[a][bq] = 0.f;

        for (int j = 0; j < 64; j++) {
            float4 ka = *(const float4*)&ks[j * 132 + ti * 8];
            float4 kb = *(const float4*)&ks[j * 132 + ti * 8 + 4];
            float4 vb = *(const float4*)&vs[j * 68 + te * 4];
            float ra[8] = {ka.x, ka.y, ka.z, ka.w, kb.x, kb.y, kb.z, kb.w};
            float rb[4] = {vb.x, vb.y, vb.z, vb.w};
#pragma unroll
            for (int dd = 0; dd < 8; dd++)
#pragma unroll
                for (int ee = 0; ee < 4; ee++) acc[dd][ee] += ra[dd] * rb[ee];
        }

        float* dst = kv_out + ((((size_t)b * HH + h) * NCHUNK + n) * DKk) * DVv + sl * 64;
#pragma unroll
        for (int dd = 0; dd < 8; dd++) {
            int dk = ti * 8 + dd;
            *(float4*)(dst + (size_t)dk * DVv + te * 4) =
                make_float4(acc[dd][0], acc[dd][1], acc[dd][2], acc[dd][3]);
        }
    }
}

// Phase C: prefix scan of kv -> Spre (float4 per thread)
__global__ __launch_bounds__(256) void ret_scan_kernel(const float4* __restrict__ kv,
                                                       float4* __restrict__ Spre) {
    const int idx = blockIdx.x * 256 + threadIdx.x;
    const int bh  = idx >> 13;
    const int pos = idx & 8191;
    const int h   = bh & (HH - 1);
    const float gamma = 1.0f - exp2f(-5.0f - (float)h);
    const float gC = powf(gamma, 64.0f);

    const size_t base = (size_t)bh * NCHUNK * 8192 + pos;
    float4 s = make_float4(0.f, 0.f, 0.f, 0.f);
    Spre[base] = s;
    for (int n = 1; n < NCHUNK; n++) {
        float4 kvv = kv[base + (size_t)(n - 1) * 8192];
        s.x = gC * s.x + kvv.x;
        s.y = gC * s.y + kvv.y;
        s.z = gC * s.z + kvv.z;
        s.w = gC * s.w + kvv.w;
        Spre[base + (size_t)n * 8192] = s;
    }
}

// Phase D: o = attn @ v + decq * (q @ S_pre)  — qs/Ss in dk-halves for occupancy
// smem: at 64x68 + vs 64x68 + qs 64x68 + Ss 64x68 + 64 = 17472 floats = 68.3KB
#define OUT_SMEM (17472 * 4)
__global__ __launch_bounds__(256) void ret_out_kernel(const float* __restrict__ qkvg,
                                                      const float* __restrict__ attn,
                                                      const float* __restrict__ Spre,
                                                      float* __restrict__ o) {
    const int sl = blockIdx.x & 3, n = blockIdx.x >> 2;
    const int h = blockIdx.y, b = blockIdx.z;
    const int tid = threadIdx.x;
    extern __shared__ float sm[];
    float* at   = sm;               // 64 x 68
    float* vs   = at + 64 * 68;     // 64 x 68
    float* qs   = vs + 64 * 68;     // 64 x 68 (dk half)
    float* Ss   = qs + 64 * 68;     // 64 x 68 (dk half)
    float* decq = Ss + 64 * 68;     // 64

    const float gamma = 1.0f - exp2f(-5.0f - (float)h);
    if (tid < 64) decq[tid] = powf(gamma, (float)(tid + 1));

    const int t0 = n * CC;
    const size_t bh = (size_t)b * HH + h;
    const float* asrc = attn + ((bh * NCHUNK + n) << 12);
    const float* ssrc = Spre + ((bh * NCHUNK + n) * DKk) * DVv + sl * 64;

    for (int e = tid; e < 64 * 16; e += 256) {
        int i = e >> 4, c4 = e & 15;
        *(float4*)&at[i * 68 + c4 * 4] = *(const float4*)&asrc[i * 64 + c4 * 4];
        *(float4*)&vs[i * 68 + c4 * 4] =
            *(const float4*)&qkvg[((size_t)b * TT + t0 + i) * NQKVG + 2048 + h * DVv + sl * 64 + c4 * 4];
    }

    const int ti = tid >> 4, te = tid & 15;
    float aI[4][4], aS[4][4];
#pragma unroll
    for (int a = 0; a < 4; a++)
#pragma unroll
        for (int bq = 0; bq < 4; bq++) { aI[a][bq] = 0.f; aS[a][bq] = 0.f; }

#pragma unroll
    for (int half = 0; half < 2; half++) {
        if (half) __syncthreads();   // all reads of prev qs/Ss halves done
        // qs half: 64 rows x 16 float4 (dk = half*64 + c4*4)
        for (int e = tid; e < 64 * 16; e += 256) {
            int i = e >> 4, c4 = e & 15;
            *(float4*)&qs[i * 68 + c4 * 4] =
                *(const float4*)&qkvg[((size_t)b * TT + t0 + i) * NQKVG + h * DKk + half * 64 + c4 * 4];
        }
        // Ss half: rows dk = half*64 + r
        for (int e = tid; e < 64 * 16; e += 256) {
            int r = e >> 4, c4 = e & 15;
            *(float4*)&Ss[r * 68 + c4 * 4] =
                *(const float4*)&ssrc[(size_t)(half * 64 + r) * DVv + c4 * 4];
        }
        __syncthreads();

        if (half == 0) {
            // aI (uses at, vs — loaded before first sync)
            for (int jg = 0; jg < 16; jg++) {
                float4 ra4[4];
#pragma unroll
                for (int ii = 0; ii < 4; ii++)
                    ra4[ii] = *(const float4*)&at[(ti * 4 + ii) * 68 + jg * 4];
#pragma unroll
                for (int jj = 0; jj < 4; jj++) {
                    float4 vb = *(const float4*)&vs[(jg * 4 + jj) * 68 + te * 4];
#pragma unroll
                    for (int ii = 0; ii < 4; ii++) {
                        float ra = ((const float*)&ra4[ii])[jj];
                        aI[ii][0] += ra * vb.x;
                        aI[ii][1] += ra * vb.y;
                        aI[ii][2] += ra * vb.z;
                        aI[ii][3] += ra * vb.w;
                    }
                }
            }
        }
        // aS over this dk half (dg local 0..15; global order preserved)
        for (int dg = 0; dg < 16; dg++) {
            float4 ra4[4];
#pragma unroll
            for (int ii = 0; ii < 4; ii++)
                ra4[ii] = *(const float4*)&qs[(ti * 4 + ii) * 68 + dg * 4];
#pragma unroll
            for (int dd = 0; dd < 4; dd++) {
                float4 sb4 = *(const float4*)&Ss[(dg * 4 + dd) * 68 + te * 4];
#pragma unroll
                for (int ii = 0; ii < 4; ii++) {
                    float ra = ((const float*)&ra4[ii])[dd];
                    aS[ii][0] += ra * sb4.x;
                    aS[ii][1] += ra * sb4.y;
                    aS[ii][2] += ra * sb4.z;
                    aS[ii][3] += ra * sb4.w;
                }
            }
        }
    }

#pragma unroll
    for (int ii = 0; ii < 4; ii++) {
        int i = ti * 4 + ii;
        float dq = decq[i];
        size_t base = (((size_t)b * TT + t0 + i) * HH + h) * DVv + sl * 64 + te * 4;
        *(float4*)(&o[base]) = make_float4(aI[ii][0] + dq * aS[ii][0],
                                           aI[ii][1] + dq * aS[ii][1],
                                           aI[ii][2] + dq * aS[ii][2],
                                           aI[ii][3] + dq * aS[ii][3]);
    }
}

// ---------------- RMSNorm + swish gate + bf16 split (vectorized) ----
__global__ __launch_bounds__(256) void normgate_split_kernel(const float* __restrict__ o,
                                                             const float* __restrict__ qkvg,
                                                             const float* __restrict__ norm_w,
                                                             __nv_bfloat16* __restrict__ ohi,
                                                             __nv_bfloat16* __restrict__ olo) {
    int warp = (blockIdx.x * blockDim.x + threadIdx.x) >> 5;
    int lane = threadIdx.x & 31;
    if (warp >= MROWS * HH) return;
    size_t base  = (size_t)warp * DVv + lane * 8;
    size_t gbase = (size_t)(warp >> 3) * NQKVG + 4096 + (size_t)(warp & 7) * DVv + lane * 8;

    float4 v0 = *(const float4*)(o + base);
    float4 v1 = *(const float4*)(o + base + 4);
    float vals[8] = {v0.x, v0.y, v0.z, v0.w, v1.x, v1.y, v1.z, v1.w};

    float ss = 0.f;
#pragma unroll
    for (int r = 0; r < 8; r++) ss += vals[r] * vals[r];
#pragma unroll
    for (int off = 16; off; off >>= 1) ss += __shfl_xor_sync(0xFFFFFFFFu, ss, off);
    float inv = rsqrtf(ss * (1.0f / 256.0f) + 1e-5f);

    float4 g0 = *(const float4*)(qkvg + gbase);
    float4 g1 = *(const float4*)(qkvg + gbase + 4);
    float gv[8] = {g0.x, g0.y, g0.z, g0.w, g1.x, g1.y, g1.z, g1.w};
    float4 w0 = *(const float4*)(norm_w + lane * 8);
    float4 w1 = *(const float4*)(norm_w + lane * 8 + 4);
    float wv[8] = {w0.x, w0.y, w0.z, w0.w, w1.x, w1.y, w1.z, w1.w};

    uint32_t hp[4], lp[4];
#pragma unroll
    for (int p = 0; p < 4; p++) {
        float r0, r1;
        {
            float sg = 1.f / (1.f + expf(-gv[2 * p]));
            r0 = vals[2 * p] * inv * wv[2 * p] * gv[2 * p] * sg;
        }
        {
            float sg = 1.f / (1.f + expf(-gv[2 * p + 1]));
            r1 = vals[2 * p + 1] * inv * wv[2 * p + 1] * gv[2 * p + 1] * sg;
        }
        __nv_bfloat16 h0 = __float2bfloat16(r0), h1 = __float2bfloat16(r1);
        __nv_bfloat16 l0 = __float2bfloat16(r0 - __bfloat162float(h0));
        __nv_bfloat16 l1 = __float2bfloat16(r1 - __bfloat162float(h1));
        hp[p] = (uint32_t)__bfloat16_as_ushort(h0) | ((uint32_t)__bfloat16_as_ushort(h1) << 16);
        lp[p] = (uint32_t)__bfloat16_as_ushort(l0) | ((uint32_t)__bfloat16_as_ushort(l1) << 16);
    }
    *(uint4*)(ohi + base) = make_uint4(hp[0], hp[1], hp[2], hp[3]);
    *(uint4*)(olo + base) = make_uint4(lp[0], lp[1], lp[2], lp[3]);
}

// ---------------- launch ----------------
static void launch_gemm(const __nv_bfloat16* Ahi, const __nv_bfloat16* Alo,
                        const __nv_bfloat16* Bhi, const __nv_bfloat16* Blo,
                        float* C, int M, int N, int K) {
    gemm_split_mma<<<dim3(N / 128, M / 128), 128, GEMM_SMEM_BYTES>>>(Ahi, Alo, Bhi, Blo, C, M, N, K);
}

extern "C" void kernel_launch(void* const* d_in, const int* in_sizes, int n_in,
                              void* d_out, int out_size) {
    const float* x      = (const float*)d_in[0];
    const float* Wq     = (const float*)d_in[1];
    const float* Wk     = (const float*)d_in[2];
    const float* Wv     = (const float*)d_in[3];
    const float* Wg     = (const float*)d_in[4];
    const float* Wo     = (const float*)d_in[5];
    const float* norm_w = (const float*)d_in[6];
    float* out = (float*)d_out;

    float *qkvg, *o, *attn, *kv, *S;
    cudaGetSymbolAddress((void**)&qkvg, g_qkvg);
    cudaGetSymbolAddress((void**)&o, g_o);
    cudaGetSymbolAddress((void**)&attn, g_attn);
    cudaGetSymbolAddress((void**)&kv, g_kv);
    cudaGetSymbolAddress((void**)&S, g_S);
    __nv_bfloat16 *xhi, *xlo, *ohi, *olo, *wallh, *walll, *woh, *wol;
    cudaGetSymbolAddress((void**)&xhi, g_xhi);
    cudaGetSymbolAddress((void**)&xlo, g_xlo);
    cudaGetSymbolAddress((void**)&ohi, g_ohi);
    cudaGetSymbolAddress((void**)&olo, g_olo);
    cudaGetSymbolAddress((void**)&wallh, g_wall_hi);
    cudaGetSymbolAddress((void**)&walll, g_wall_lo);
    cudaGetSymbolAddress((void**)&woh, g_wo_hi);
    cudaGetSymbolAddress((void**)&wol, g_wo_lo);

    cudaFuncSetAttribute(gemm_split_mma, cudaFuncAttributeMaxDynamicSharedMemorySize, GEMM_SMEM_BYTES);
    cudaFuncSetAttribute(ret_ab_kernel, cudaFuncAttributeMaxDynamicSharedMemorySize, AB_SMEM);
    cudaFuncSetAttribute(ret_out_kernel, cudaFuncAttributeMaxDynamicSharedMemorySize, OUT_SMEM);

    // fused prep
    prep_kernel<<<PREP_SPLIT_BLKS + PREP_QKVG_BLKS + PREP_WO_BLKS, 256>>>(
        (const float4*)x, (uint2*)xhi, (uint2*)xlo,
        Wq, Wk, Wv, Wg, Wo, wallh, walll, woh, wol);

    // combined projection GEMM (q|k|v|g)
    launch_gemm(xhi, xlo, wallh, walll, qkvg, MROWS, NQKVG, DD);

    // rope + scale (vectorized)
    {
        int total = BB * TT * HH * 16;
        rope_kernel<<<(total + 255) / 256, 256>>>(qkvg);
    }

    // retention: fused A|B, then scan, then D
    ret_ab_kernel<<<dim3(NCHUNK + 4 * NCHUNK, HH, BB), 256, AB_SMEM>>>(qkvg, attn, kv);
    ret_scan_kernel<<<(NBH * DKk * DVv / 4) / 256, 256>>>((const float4*)kv, (float4*)S);
    ret_out_kernel<<<dim3(4 * NCHUNK, HH, BB), 256, OUT_SMEM>>>(qkvg, attn, S, o);

    // rmsnorm + gate + split (fused, vectorized)
    {
        int warps = MROWS * HH;
        normgate_split_kernel<<<(warps * 32 + 255) / 256, 256>>>(o, qkvg, norm_w, ohi, olo);
    }

    // output projection on tensor cores
    launch_gemm(ohi, olo, woh, wol, out, MROWS, DD, 2 * DD);
}

// round 16
// speedup vs baseline: 1.4404x; 1.0119x over previous
#include <cuda_runtime.h>
#include <cuda_bf16.h>
#include <math.h>
#include <stdint.h>

// ---------------- problem constants ----------------
#define BB 4
#define TT 2048
#define DD 1024
#define HH 8
#define DKk 128
#define DVv 256
#define CC 64
#define NCHUNK (TT / CC)   // 32
#define MROWS (BB * TT)    // 8192
#define NBH (BB * HH)      // 32
#define NQKVG 6144         // q(1024) | k(1024) | v(2048) | g(2048)

// ---------------- scratch (no runtime allocation allowed) ----------------
__device__ float g_qkvg[MROWS * NQKVG];
__device__ float g_o[MROWS * HH * DVv];

// retention intermediates
__device__ float g_attn[NBH * NCHUNK * CC * CC];
__device__ float g_kv[NBH * NCHUNK * DKk * DVv];
__device__ float g_S[NBH * NCHUNK * DKk * DVv];

// bf16 split operands
__device__ __nv_bfloat16 g_xhi[MROWS * DD];
__device__ __nv_bfloat16 g_xlo[MROWS * DD];
__device__ __nv_bfloat16 g_ohi[MROWS * HH * DVv];
__device__ __nv_bfloat16 g_olo[MROWS * HH * DVv];
// transposed weights [N, K]
__device__ __nv_bfloat16 g_wall_hi[NQKVG * DD], g_wall_lo[NQKVG * DD];
__device__ __nv_bfloat16 g_wo_hi[2 * DD * DD],  g_wo_lo[2 * DD * DD];

// ================= PTX helpers (plain sm_80+ ISA only) =================
__device__ __forceinline__ uint32_t smem_u32(const void* p) {
    uint32_t a;
    asm("{ .reg .u64 t; cvta.to.shared.u64 t, %1; cvt.u32.u64 %0, t; }" : "=r"(a) : "l"(p));
    return a;
}
#define CP_ASYNC16(dst, src) \
    asm volatile("cp.async.cg.shared.global [%0], [%1], 16;" :: "r"(dst), "l"(src))
#define CP_ASYNC_COMMIT() asm volatile("cp.async.commit_group;" ::: "memory")
#define CP_ASYNC_WAIT1() asm volatile("cp.async.wait_group 1;" ::: "memory")

__device__ __forceinline__ void ldsm4(uint32_t* r, uint32_t addr) {
    asm volatile("ldmatrix.sync.aligned.m8n8.x4.shared.b16 {%0,%1,%2,%3}, [%4];"
        : "=r"(r[0]), "=r"(r[1]), "=r"(r[2]), "=r"(r[3]) : "r"(addr));
}
__device__ __forceinline__ void mma16816(float* c, const uint32_t* a, const uint32_t* b) {
    asm volatile("mma.sync.aligned.m16n8k16.row.col.f32.bf16.bf16.f32 "
        "{%0,%1,%2,%3}, {%4,%5,%6,%7}, {%8,%9}, {%0,%1,%2,%3};"
        : "+f"(c[0]), "+f"(c[1]), "+f"(c[2]), "+f"(c[3])
        : "r"(a[0]), "r"(a[1]), "r"(a[2]), "r"(a[3]), "r"(b[0]), "r"(b[1]));
}

// ================= split-bf16 tensor-core GEMM =================
#define GSTAGES 3
#define GMAT_BYTES (128 * 64)
#define GSTAGE_BYTES (4 * GMAT_BYTES)
#define GEMM_SMEM_BYTES (GSTAGES * GSTAGE_BYTES)

__device__ __forceinline__ uint32_t swz(int row, int c16) {
    return (uint32_t)(row * 64 + ((c16 ^ ((row >> 1) & 3)) << 4));
}

__device__ __forceinline__ void load_tile32(uint32_t dst, const __nv_bfloat16* src,
                                            int row0, int k0, int ldk, int tid) {
    const char* gbase = (const char*)(src + (size_t)row0 * ldk + k0);
    const size_t rowb = (size_t)ldk * 2;
#pragma unroll
    for (int j = 0; j < 4; j++) {
        int e = tid + j * 128;
        int r = e >> 2, c16 = e & 3;
        CP_ASYNC16(dst + swz(r, c16), gbase + (size_t)r * rowb + c16 * 16);
    }
}

__global__ __launch_bounds__(128, 2) void gemm_split_mma(
    const __nv_bfloat16* __restrict__ Ahi, const __nv_bfloat16* __restrict__ Alo,
    const __nv_bfloat16* __restrict__ Bhi, const __nv_bfloat16* __restrict__ Blo,
    float* __restrict__ C, int M, int N, int K) {
    extern __shared__ char smem[];
    const uint32_t sb = smem_u32(smem);
    const int tid = threadIdx.x, lane = tid & 31, wid = tid >> 5;
    const int wm = wid & 1, wn = wid >> 1;
    const int m0 = blockIdx.y * 128, n0 = blockIdx.x * 128;
    const int nchunk = K >> 5;

    const int a_row = (lane & 7) + 8 * ((lane >> 3) & 1);
    const int a_c8  = lane >> 4;
    const int b_row = (lane & 7) + 8 * (lane >> 4);
    const int b_c8  = (lane >> 3) & 1;

    const int arow = wm * 64 + a_row;
    const int selA = (arow >> 1) & 3;
    const int brow = wn * 64 + b_row;
    const int selB = (brow >> 1) & 3;

    float acc[4][8][4];
#pragma unroll
    for (int i = 0; i < 4; i++)
#pragma unroll
        for (int j = 0; j < 8; j++)
#pragma unroll
            for (int r = 0; r < 4; r++) acc[i][j][r] = 0.f;

#pragma unroll
    for (int s = 0; s < GSTAGES; s++) {
        uint32_t st = sb + s * GSTAGE_BYTES;
        int k0 = s * 32;
        load_tile32(st,                  Ahi, m0, k0, K, tid);
        load_tile32(st + GMAT_BYTES,     Alo, m0, k0, K, tid);
        load_tile32(st + 2 * GMAT_BYTES, Bhi, n0, k0, K, tid);
        load_tile32(st + 3 * GMAT_BYTES, Blo, n0, k0, K, tid);
        CP_ASYNC_COMMIT();
    }

    for (int c = 0; c < nchunk; c++) {
        uint32_t st = sb + (c % GSTAGES) * GSTAGE_BYTES;
        CP_ASYNC_WAIT1();
        __syncthreads();

        if (c >= 1) {
            if (c + 2 < nchunk) {
                uint32_t st2 = sb + ((c + 2) % GSTAGES) * GSTAGE_BYTES;
                int k0 = (c + 2) * 32;
                load_tile32(st2,                  Ahi, m0, k0, K, tid);
                load_tile32(st2 + GMAT_BYTES,     Alo, m0, k0, K, tid);
                load_tile32(st2 + 2 * GMAT_BYTES, Bhi, n0, k0, K, tid);
                load_tile32(st2 + 3 * GMAT_BYTES, Blo, n0, k0, K, tid);
            }
            CP_ASYNC_COMMIT();
        }

#pragma unroll
        for (int ks = 0; ks < 2; ks++) {
            const int ks2 = ks * 2;
            const uint32_t ca = (uint32_t)(((ks2 + a_c8) ^ selA) << 4);
            const uint32_t cb = (uint32_t)(((ks2 + b_c8) ^ selB) << 4);

            uint32_t ah[4][4], al[4][4];
#pragma unroll
            for (int mt = 0; mt < 4; mt++) {
                uint32_t ra = st + (uint32_t)((arow + mt * 16) * 64) + ca;
                ldsm4(ah[mt], ra);
                ldsm4(al[mt], ra + GMAT_BYTES);
            }
#pragma unroll
            for (int np = 0; np < 4; np++) {
                uint32_t bh[4], bl[4];
                uint32_t rb = st + 2 * GMAT_BYTES + (uint32_t)((brow + np * 16) * 64) + cb;
                ldsm4(bh, rb);
                ldsm4(bl, rb + GMAT_BYTES);
#pragma unroll
                for (int mt = 0; mt < 4; mt++)
#pragma unroll
                    for (int hf = 0; hf < 2; hf++) {
                        float* a4 = acc[mt][np * 2 + hf];
                        mma16816(a4, ah[mt], &bh[hf * 2]);
                        mma16816(a4, ah[mt], &bl[hf * 2]);
                        mma16816(a4, al[mt], &bh[hf * 2]);
                    }
            }
        }
    }

    const int crow = lane >> 2, ccol = (lane & 3) * 2;
#pragma unroll
    for (int mt = 0; mt < 4; mt++) {
        int rbase = m0 + wm * 64 + mt * 16 + crow;
#pragma unroll
        for (int nt = 0; nt < 8; nt++) {
            int cbase = n0 + wn * 64 + nt * 8 + ccol;
            float* d0 = C + (size_t)rbase * N + cbase;
            float* d1 = C + (size_t)(rbase + 8) * N + cbase;
            *(float2*)d0 = make_float2(acc[mt][nt][0], acc[mt][nt][1]);
            *(float2*)d1 = make_float2(acc[mt][nt][2], acc[mt][nt][3]);
        }
    }
}

// ================= fused prep: split_x | tsplit_qkvg | tsplit_wo =============
__device__ __forceinline__ void tsplit_block(const float* __restrict__ W,
                                             __nv_bfloat16* __restrict__ Thi,
                                             __nv_bfloat16* __restrict__ Tlo,
                                             int K, int srcN, int n0glob, int ln0, int k0,
                                             float (*t)[33]) {
    int tx = threadIdx.x & 31, ty = threadIdx.x >> 5;
#pragma unroll
    for (int i = ty; i < 32; i += 8)
        t[i][tx] = W[(size_t)(k0 + i) * srcN + ln0 + tx];
    __syncthreads();
#pragma unroll
    for (int i = ty; i < 32; i += 8) {
        float v = t[tx][i];
        __nv_bfloat16 h = __float2bfloat16(v);
        size_t oidx = (size_t)(n0glob + i) * K + k0 + tx;
        Thi[oidx] = h;
        Tlo[oidx] = __float2bfloat16(v - __bfloat162float(h));
    }
}

#define PREP_SPLIT_BLKS 8192
#define PREP_QKVG_BLKS  6144
#define PREP_WO_BLKS    2048
__global__ __launch_bounds__(256) void prep_kernel(
    const float4* __restrict__ x4, uint2* __restrict__ xhi, uint2* __restrict__ xlo,
    const float* __restrict__ Wq, const float* __restrict__ Wk,
    const float* __restrict__ Wv, const float* __restrict__ Wg,
    const float* __restrict__ Wo,
    __nv_bfloat16* __restrict__ wallh, __nv_bfloat16* __restrict__ walll,
    __nv_bfloat16* __restrict__ woh,  __nv_bfloat16* __restrict__ wol) {
    __shared__ float t[32][33];
    const int bx = blockIdx.x;
    if (bx < PREP_SPLIT_BLKS) {
        int i = bx * 256 + threadIdx.x;
        float4 v = x4[i];
        __nv_bfloat16 h0 = __float2bfloat16(v.x), h1 = __float2bfloat16(v.y);
        __nv_bfloat16 h2 = __float2bfloat16(v.z), h3 = __float2bfloat16(v.w);
        __nv_bfloat16 l0 = __float2bfloat16(v.x - __bfloat162float(h0));
        __nv_bfloat16 l1 = __float2bfloat16(v.y - __bfloat162float(h1));
        __nv_bfloat16 l2 = __float2bfloat16(v.z - __bfloat162float(h2));
        __nv_bfloat16 l3 = __float2bfloat16(v.w - __bfloat162float(h3));
        uint2 hp, lp;
        hp.x = (uint32_t)__bfloat16_as_ushort(h0) | ((uint32_t)__bfloat16_as_ushort(h1) << 16);
        hp.y = (uint32_t)__bfloat16_as_ushort(h2) | ((uint32_t)__bfloat16_as_ushort(h3) << 16);
        lp.x = (uint32_t)__bfloat16_as_ushort(l0) | ((uint32_t)__bfloat16_as_ushort(l1) << 16);
        lp.y = (uint32_t)__bfloat16_as_ushort(l2) | ((uint32_t)__bfloat16_as_ushort(l3) << 16);
        xhi[i] = hp;
        xlo[i] = lp;
    } else if (bx < PREP_SPLIT_BLKS + PREP_QKVG_BLKS) {
        int tb = bx - PREP_SPLIT_BLKS;
        int n0 = (tb % 192) * 32, k0 = (tb / 192) * 32;
        const float* W;
        int srcN, ln0;
        if (n0 < 1024)       { W = Wq; srcN = 1024; ln0 = n0; }
        else if (n0 < 2048)  { W = Wk; srcN = 1024; ln0 = n0 - 1024; }
        else if (n0 < 4096)  { W = Wv; srcN = 2048; ln0 = n0 - 2048; }
        else                 { W = Wg; srcN = 2048; ln0 = n0 - 4096; }
        tsplit_block(W, wallh, walll, DD, srcN, n0, ln0, k0, t);
    } else {
        int tb = bx - PREP_SPLIT_BLKS - PREP_QKVG_BLKS;
        int n0 = (tb % 32) * 32, k0 = (tb / 32) * 32;
        tsplit_block(Wo, woh, wol, 2 * DD, DD, n0, n0, k0, t);
    }
}

// ---------------- RoPE (vectorized float4) -----------------------------------
__global__ void rope_kernel(float* __restrict__ qkvg) {
    int idx = blockIdx.x * blockDim.x + threadIdx.x;
    const int total = BB * TT * HH * 16;
    if (idx >= total) return;
    int i4 = idx & 15;
    int h = (idx >> 4) & (HH - 1);
    int t = (idx >> 7) & (TT - 1);
    int b = idx >> 18;

    size_t base = ((size_t)b * TT + t) * NQKVG + h * DKk + i4 * 4;
    const float sc = 0.08838834764831845f;

    float s[4], c[4];
#pragma unroll
    for (int cc = 0; cc < 4; cc++) {
        int i = i4 * 4 + cc;
        float inv = powf(10000.f, -(float)i * (1.0f / 64.0f));
        sincosf((float)t * inv, &s[cc], &c[cc]);
    }

    float4 q1 = *(float4*)&qkvg[base];
    float4 q2 = *(float4*)&qkvg[base + 64];
    float* q1p = &q1.x; float* q2p = &q2.x;
    float4 o1, o2;
    float* o1p = &o1.x; float* o2p = &o2.x;
#pragma unroll
    for (int cc = 0; cc < 4; cc++) {
        o1p[cc] = (q1p[cc] * c[cc] - q2p[cc] * s[cc]) * sc;
        o2p[cc] = (q2p[cc] * c[cc] + q1p[cc] * s[cc]) * sc;
    }
    *(float4*)&qkvg[base]      = o1;
    *(float4*)&qkvg[base + 64] = o2;

    size_t kb = base + 1024;
    float4 k1 = *(float4*)&qkvg[kb];
    float4 k2 = *(float4*)&qkvg[kb + 64];
    float* k1p = &k1.x; float* k2p = &k2.x;
#pragma unroll
    for (int cc = 0; cc < 4; cc++) {
        o1p[cc] = k1p[cc] * c[cc] - k2p[cc] * s[cc];
        o2p[cc] = k2p[cc] * c[cc] + k1p[cc] * s[cc];
    }
    *(float4*)&qkvg[kb]      = o1;
    *(float4*)&qkvg[kb + 64] = o2;
}

// ================= fused retention phases A | B ========
// A: R14 scalar version (conflict-free 129 stride): 2*64*129 + 64 = 16576 floats
// B: ks 64x132 + vs 64x68 + 64 = 12864 floats
#define AB_SMEM (16576 * 4)

__global__ __launch_bounds__(256) void ret_ab_kernel(const float* __restrict__ qkvg,
                                                     float* __restrict__ attn_out,
                                                     float* __restrict__ kv_out) {
    const int h = blockIdx.y, b = blockIdx.z;
    const int tid = threadIdx.x;
    extern __shared__ float sm[];
    const float gamma = 1.0f - exp2f(-5.0f - (float)h);

    if (blockIdx.x < NCHUNK) {
        // ---------------- Phase A (R14 scalar, conflict-free) ----------------
        const int n = blockIdx.x;
        float* qs   = sm;
        float* ks   = qs + 64 * 129;
        float* gpow = ks + 64 * 129;
        if (tid < 64) gpow[tid] = powf(gamma, (float)tid);

        const int t0 = n * CC;
        for (int e = tid; e < 64 * 128; e += 256) {
            int i = e >> 7, dk = e & 127;
            size_t gi = ((size_t)b * TT + t0 + i) * NQKVG + h * DKk + dk;
            qs[i * 129 + dk] = qkvg[gi];
            ks[i * 129 + dk] = qkvg[gi + 1024];
        }
        __syncthreads();

        const int ti = tid >> 4, te = tid & 15;
        float acc[4][4];
#pragma unroll
        for (int a = 0; a < 4; a++)
#pragma unroll
            for (int bq = 0; bq < 4; bq++) acc[a][bq] = 0.f;
        for (int dk = 0; dk < 128; dk++) {
            float ra[4], rb[4];
#pragma unroll
            for (int ii = 0; ii < 4; ii++) ra[ii] = qs[(ti * 4 + ii) * 129 + dk];
#pragma unroll
            for (int jj = 0; jj < 4; jj++) rb[jj] = ks[(te * 4 + jj) * 129 + dk];
#pragma unroll
            for (int ii = 0; ii < 4; ii++)
#pragma unroll
                for (int jj = 0; jj < 4; jj++) acc[ii][jj] += ra[ii] * rb[jj];
        }

        float* dst = attn_out + ((((size_t)b * HH + h) * NCHUNK + n) << 12);
#pragma unroll
        for (int ii = 0; ii < 4; ii++) {
            int i = ti * 4 + ii;
            float4 w;
            float* wp = &w.x;
#pragma unroll
            for (int jj = 0; jj < 4; jj++) {
                int j = te * 4 + jj;
                wp[jj] = (i >= j) ? acc[ii][jj] * gpow[i - j] : 0.f;
            }
            *(float4*)(dst + i * 64 + te * 4) = w;
        }
    } else {
        // ---------------- Phase B ----------------
        const int lin = blockIdx.x - NCHUNK;
        const int sl = lin & 3, n = lin >> 2;
        float* ks   = sm;               // 64 x 132
        float* vs   = ks + 64 * 132;    // 64 x 68
        float* deck = vs + 64 * 68;     // 64
        if (tid < 64) deck[tid] = powf(gamma, (float)(63 - tid));
        __syncthreads();

        const int t0 = n * CC;
        for (int e = tid; e < 64 * 32; e += 256) {
            int i = e >> 5, c4 = e & 31;
            float4 v = *(const float4*)&qkvg[((size_t)b * TT + t0 + i) * NQKVG + 1024 + h * DKk + c4 * 4];
            *(float4*)&ks[i * 132 + c4 * 4] = v;
        }
        for (int e = tid; e < 64 * 16; e += 256) {
            int i = e >> 4, c4 = e & 15;
            float d = deck[i];
            float4 v = *(const float4*)&qkvg[((size_t)b * TT + t0 + i) * NQKVG + 2048 + h * DVv + sl * 64 + c4 * 4];
            v.x *= d; v.y *= d; v.z *= d; v.w *= d;
            *(float4*)&vs[i * 68 + c4 * 4] = v;
        }
        __syncthreads();

        const int ti = tid >> 4, te = tid & 15;
        float acc[8][4];
#pragma unroll
        for (int a = 0; a < 8; a++)
#pragma unroll
            for (int bq = 0; bq < 4; bq++) acc[a][bq] = 0.f;

        for (int j = 0; j < 64; j++) {
            float4 ka = *(const float4*)&ks[j * 132 + ti * 8];
            float4 kb = *(const float4*)&ks[j * 132 + ti * 8 + 4];
            float4 vb = *(const float4*)&vs[j * 68 + te * 4];
            float ra[8] = {ka.x, ka.y, ka.z, ka.w, kb.x, kb.y, kb.z, kb.w};
            float rb[4] = {vb.x, vb.y, vb.z, vb.w};
#pragma unroll
            for (int dd = 0; dd < 8; dd++)
#pragma unroll
                for (int ee = 0; ee < 4; ee++) acc[dd][ee] += ra[dd] * rb[ee];
        }

        float* dst = kv_out + ((((size_t)b * HH + h) * NCHUNK + n) * DKk) * DVv + sl * 64;
#pragma unroll
        for (int dd = 0; dd < 8; dd++) {
            int dk = ti * 8 + dd;
            *(float4*)(dst + (size_t)dk * DVv + te * 4) =
                make_float4(acc[dd][0], acc[dd][1], acc[dd][2], acc[dd][3]);
        }
    }
}

// Phase C: prefix scan of kv -> Spre (float4 per thread)
__global__ __launch_bounds__(256) void ret_scan_kernel(const float4* __restrict__ kv,
                                                       float4* __restrict__ Spre) {
    const int idx = blockIdx.x * 256 + threadIdx.x;
    const int bh  = idx >> 13;
    const int pos = idx & 8191;
    const int h   = bh & (HH - 1);
    const float gamma = 1.0f - exp2f(-5.0f - (float)h);
    const float gC = powf(gamma, 64.0f);

    const size_t base = (size_t)bh * NCHUNK * 8192 + pos;
    float4 s = make_float4(0.f, 0.f, 0.f, 0.f);
    Spre[base] = s;
    for (int n = 1; n < NCHUNK; n++) {
        float4 kvv = kv[base + (size_t)(n - 1) * 8192];
        s.x = gC * s.x + kvv.x;
        s.y = gC * s.y + kvv.y;
        s.z = gC * s.z + kvv.z;
        s.w = gC * s.w + kvv.w;
        Spre[base + (size_t)n * 8192] = s;
    }
}

// Phase D: o = attn @ v + decq * (q @ S_pre)  — qs/Ss in dk-halves (R15 win)
#define OUT_SMEM (17472 * 4)
__global__ __launch_bounds__(256) void ret_out_kernel(const float* __restrict__ qkvg,
                                                      const float* __restrict__ attn,
                                                      const float* __restrict__ Spre,
                                                      float* __restrict__ o) {
    const int sl = blockIdx.x & 3, n = blockIdx.x >> 2;
    const int h = blockIdx.y, b = blockIdx.z;
    const int tid = threadIdx.x;
    extern __shared__ float sm[];
    float* at   = sm;               // 64 x 68
    float* vs   = at + 64 * 68;     // 64 x 68
    float* qs   = vs + 64 * 68;     // 64 x 68 (dk half)
    float* Ss   = qs + 64 * 68;     // 64 x 68 (dk half)
    float* decq = Ss + 64 * 68;     // 64

    const float gamma = 1.0f - exp2f(-5.0f - (float)h);
    if (tid < 64) decq[tid] = powf(gamma, (float)(tid + 1));

    const int t0 = n * CC;
    const size_t bh = (size_t)b * HH + h;
    const float* asrc = attn + ((bh * NCHUNK + n) << 12);
    const float* ssrc = Spre + ((bh * NCHUNK + n) * DKk) * DVv + sl * 64;

    for (int e = tid; e < 64 * 16; e += 256) {
        int i = e >> 4, c4 = e & 15;
        *(float4*)&at[i * 68 + c4 * 4] = *(const float4*)&asrc[i * 64 + c4 * 4];
        *(float4*)&vs[i * 68 + c4 * 4] =
            *(const float4*)&qkvg[((size_t)b * TT + t0 + i) * NQKVG + 2048 + h * DVv + sl * 64 + c4 * 4];
    }

    const int ti = tid >> 4, te = tid & 15;
    float aI[4][4], aS[4][4];
#pragma unroll
    for (int a = 0; a < 4; a++)
#pragma unroll
        for (int bq = 0; bq < 4; bq++) { aI[a][bq] = 0.f; aS[a][bq] = 0.f; }

#pragma unroll
    for (int half = 0; half < 2; half++) {
        if (half) __syncthreads();
        for (int e = tid; e < 64 * 16; e += 256) {
            int i = e >> 4, c4 = e & 15;
            *(float4*)&qs[i * 68 + c4 * 4] =
                *(const float4*)&qkvg[((size_t)b * TT + t0 + i) * NQKVG + h * DKk + half * 64 + c4 * 4];
        }
        for (int e = tid; e < 64 * 16; e += 256) {
            int r = e >> 4, c4 = e & 15;
            *(float4*)&Ss[r * 68 + c4 * 4] =
                *(const float4*)&ssrc[(size_t)(half * 64 + r) * DVv + c4 * 4];
        }
        __syncthreads();

        if (half == 0) {
            for (int jg = 0; jg < 16; jg++) {
                float4 ra4[4];
#pragma unroll
                for (int ii = 0; ii < 4; ii++)
                    ra4[ii] = *(const float4*)&at[(ti * 4 + ii) * 68 + jg * 4];
#pragma unroll
                for (int jj = 0; jj < 4; jj++) {
                    float4 vb = *(const float4*)&vs[(jg * 4 + jj) * 68 + te * 4];
#pragma unroll
                    for (int ii = 0; ii < 4; ii++) {
                        float ra = ((const float*)&ra4[ii])[jj];
                        aI[ii][0] += ra * vb.x;
                        aI[ii][1] += ra * vb.y;
                        aI[ii][2] += ra * vb.z;
                        aI[ii][3] += ra * vb.w;
                    }
                }
            }
        }
        for (int dg = 0; dg < 16; dg++) {
            float4 ra4[4];
#pragma unroll
            for (int ii = 0; ii < 4; ii++)
                ra4[ii] = *(const float4*)&qs[(ti * 4 + ii) * 68 + dg * 4];
#pragma unroll
            for (int dd = 0; dd < 4; dd++) {
                float4 sb4 = *(const float4*)&Ss[(dg * 4 + dd) * 68 + te * 4];
#pragma unroll
                for (int ii = 0; ii < 4; ii++) {
                    float ra = ((const float*)&ra4[ii])[dd];
                    aS[ii][0] += ra * sb4.x;
                    aS[ii][1] += ra * sb4.y;
                    aS[ii][2] += ra * sb4.z;
                    aS[ii][3] += ra * sb4.w;
                }
            }
        }
    }

#pragma unroll
    for (int ii = 0; ii < 4; ii++) {
        int i = ti * 4 + ii;
        float dq = decq[i];
        size_t base = (((size_t)b * TT + t0 + i) * HH + h) * DVv + sl * 64 + te * 4;
        *(float4*)(&o[base]) = make_float4(aI[ii][0] + dq * aS[ii][0],
                                           aI[ii][1] + dq * aS[ii][1],
                                           aI[ii][2] + dq * aS[ii][2],
                                           aI[ii][3] + dq * aS[ii][3]);
    }
}

// ---------------- RMSNorm + swish gate + bf16 split (vectorized) ----
__global__ __launch_bounds__(256) void normgate_split_kernel(const float* __restrict__ o,
                                                             const float* __restrict__ qkvg,
                                                             const float* __restrict__ norm_w,
                                                             __nv_bfloat16* __restrict__ ohi,
                                                             __nv_bfloat16* __restrict__ olo) {
    int warp = (blockIdx.x * blockDim.x + threadIdx.x) >> 5;
    int lane = threadIdx.x & 31;
    if (warp >= MROWS * HH) return;
    size_t base  = (size_t)warp * DVv + lane * 8;
    size_t gbase = (size_t)(warp >> 3) * NQKVG + 4096 + (size_t)(warp & 7) * DVv + lane * 8;

    float4 v0 = *(const float4*)(o + base);
    float4 v1 = *(const float4*)(o + base + 4);
    float vals[8] = {v0.x, v0.y, v0.z, v0.w, v1.x, v1.y, v1.z, v1.w};

    float ss = 0.f;
#pragma unroll
    for (int r = 0; r < 8; r++) ss += vals[r] * vals[r];
#pragma unroll
    for (int off = 16; off; off >>= 1) ss += __shfl_xor_sync(0xFFFFFFFFu, ss, off);
    float inv = rsqrtf(ss * (1.0f / 256.0f) + 1e-5f);

    float4 g0 = *(const float4*)(qkvg + gbase);
    float4 g1 = *(const float4*)(qkvg + gbase + 4);
    float gv[8] = {g0.x, g0.y, g0.z, g0.w, g1.x, g1.y, g1.z, g1.w};
    float4 w0 = *(const float4*)(norm_w + lane * 8);
    float4 w1 = *(const float4*)(norm_w + lane * 8 + 4);
    float wv[8] = {w0.x, w0.y, w0.z, w0.w, w1.x, w1.y, w1.z, w1.w};

    uint32_t hp[4], lp[4];
#pragma unroll
    for (int p = 0; p < 4; p++) {
        float r0, r1;
        {
            float sg = 1.f / (1.f + expf(-gv[2 * p]));
            r0 = vals[2 * p] * inv * wv[2 * p] * gv[2 * p] * sg;
        }
        {
            float sg = 1.f / (1.f + expf(-gv[2 * p + 1]));
            r1 = vals[2 * p + 1] * inv * wv[2 * p + 1] * gv[2 * p + 1] * sg;
        }
        __nv_bfloat16 h0 = __float2bfloat16(r0), h1 = __float2bfloat16(r1);
        __nv_bfloat16 l0 = __float2bfloat16(r0 - __bfloat162float(h0));
        __nv_bfloat16 l1 = __float2bfloat16(r1 - __bfloat162float(h1));
        hp[p] = (uint32_t)__bfloat16_as_ushort(h0) | ((uint32_t)__bfloat16_as_ushort(h1) << 16);
        lp[p] = (uint32_t)__bfloat16_as_ushort(l0) | ((uint32_t)__bfloat16_as_ushort(l1) << 16);
    }
    *(uint4*)(ohi + base) = make_uint4(hp[0], hp[1], hp[2], hp[3]);
    *(uint4*)(olo + base) = make_uint4(lp[0], lp[1], lp[2], lp[3]);
}

// ---------------- launch ----------------
static void launch_gemm(const __nv_bfloat16* Ahi, const __nv_bfloat16* Alo,
                        const __nv_bfloat16* Bhi, const __nv_bfloat16* Blo,
                        float* C, int M, int N, int K) {
    gemm_split_mma<<<dim3(N / 128, M / 128), 128, GEMM_SMEM_BYTES>>>(Ahi, Alo, Bhi, Blo, C, M, N, K);
}

extern "C" void kernel_launch(void* const* d_in, const int* in_sizes, int n_in,
                              void* d_out, int out_size) {
    const float* x      = (const float*)d_in[0];
    const float* Wq     = (const float*)d_in[1];
    const float* Wk     = (const float*)d_in[2];
    const float* Wv     = (const float*)d_in[3];
    const float* Wg     = (const float*)d_in[4];
    const float* Wo     = (const float*)d_in[5];
    const float* norm_w = (const float*)d_in[6];
    float* out = (float*)d_out;

    float *qkvg, *o, *attn, *kv, *S;
    cudaGetSymbolAddress((void**)&qkvg, g_qkvg);
    cudaGetSymbolAddress((void**)&o, g_o);
    cudaGetSymbolAddress((void**)&attn, g_attn);
    cudaGetSymbolAddress((void**)&kv, g_kv);
    cudaGetSymbolAddress((void**)&S, g_S);
    __nv_bfloat16 *xhi, *xlo, *ohi, *olo, *wallh, *walll, *woh, *wol;
    cudaGetSymbolAddress((void**)&xhi, g_xhi);
    cudaGetSymbolAddress((void**)&xlo, g_xlo);
    cudaGetSymbolAddress((void**)&ohi, g_ohi);
    cudaGetSymbolAddress((void**)&olo, g_olo);
    cudaGetSymbolAddress((void**)&wallh, g_wall_hi);
    cudaGetSymbolAddress((void**)&walll, g_wall_lo);
    cudaGetSymbolAddress((void**)&woh, g_wo_hi);
    cudaGetSymbolAddress((void**)&wol, g_wo_lo);

    cudaFuncSetAttribute(gemm_split_mma, cudaFuncAttributeMaxDynamicSharedMemorySize, GEMM_SMEM_BYTES);
    cudaFuncSetAttribute(ret_ab_kernel, cudaFuncAttributeMaxDynamicSharedMemorySize, AB_SMEM);
    cudaFuncSetAttribute(ret_out_kernel, cudaFuncAttributeMaxDynamicSharedMemorySize, OUT_SMEM);

    // fused prep
    prep_kernel<<<PREP_SPLIT_BLKS + PREP_QKVG_BLKS + PREP_WO_BLKS, 256>>>(
        (const float4*)x, (uint2*)xhi, (uint2*)xlo,
        Wq, Wk, Wv, Wg, Wo, wallh, walll, woh, wol);

    // combined projection GEMM (q|k|v|g)
    launch_gemm(xhi, xlo, wallh, walll, qkvg, MROWS, NQKVG, DD);

    // rope + scale (vectorized)
    {
        int total = BB * TT * HH * 16;
        rope_kernel<<<(total + 255) / 256, 256>>>(qkvg);
    }

    // retention: fused A|B, then scan, then D
    ret_ab_kernel<<<dim3(NCHUNK + 4 * NCHUNK, HH, BB), 256, AB_SMEM>>>(qkvg, attn, kv);
    ret_scan_kernel<<<(NBH * DKk * DVv / 4) / 256, 256>>>((const float4*)kv, (float4*)S);
    ret_out_kernel<<<dim3(4 * NCHUNK, HH, BB), 256, OUT_SMEM>>>(qkvg, attn, S, o);

    // rmsnorm + gate + split (fused, vectorized)
    {
        int warps = MROWS * HH;
        normgate_split_kernel<<<(warps * 32 + 255) / 256, 256>>>(o, qkvg, norm_w, ohi, olo);
    }

    // output projection on tensor cores
    launch_gemm(ohi, olo, woh, wol, out, MROWS, DD, 2 * DD);
}

// round 17
// speedup vs baseline: 1.4604x; 1.0139x over previous
#include <cuda_runtime.h>
#include <cuda_bf16.h>
#include <math.h>
#include <stdint.h>

// ---------------- problem constants ----------------
#define BB 4
#define TT 2048
#define DD 1024
#define HH 8
#define DKk 128
#define DVv 256
#define CC 64
#define NCHUNK (TT / CC)   // 32
#define MROWS (BB * TT)    // 8192
#define NBH (BB * HH)      // 32
#define NQKVG 6144         // q(1024) | k(1024) | v(2048) | g(2048)

// ---------------- scratch (no runtime allocation allowed) ----------------
__device__ float g_qkvg[MROWS * NQKVG];
__device__ float g_o[MROWS * HH * DVv];

// retention intermediates
__device__ float g_attn[NBH * NCHUNK * CC * CC];
__device__ float g_kv[NBH * NCHUNK * DKk * DVv];
__device__ float g_S[NBH * NCHUNK * DKk * DVv];

// bf16 split operands
__device__ __nv_bfloat16 g_xhi[MROWS * DD];
__device__ __nv_bfloat16 g_xlo[MROWS * DD];
__device__ __nv_bfloat16 g_ohi[MROWS * HH * DVv];
__device__ __nv_bfloat16 g_olo[MROWS * HH * DVv];
// transposed weights [N, K]
__device__ __nv_bfloat16 g_wall_hi[NQKVG * DD], g_wall_lo[NQKVG * DD];
__device__ __nv_bfloat16 g_wo_hi[2 * DD * DD],  g_wo_lo[2 * DD * DD];

// ================= PTX helpers (plain sm_80+ ISA only) =================
__device__ __forceinline__ uint32_t smem_u32(const void* p) {
    uint32_t a;
    asm("{ .reg .u64 t; cvta.to.shared.u64 t, %1; cvt.u32.u64 %0, t; }" : "=r"(a) : "l"(p));
    return a;
}
#define CP_ASYNC16(dst, src) \
    asm volatile("cp.async.cg.shared.global [%0], [%1], 16;" :: "r"(dst), "l"(src))
#define CP_ASYNC_COMMIT() asm volatile("cp.async.commit_group;" ::: "memory")
#define CP_ASYNC_WAIT1() asm volatile("cp.async.wait_group 1;" ::: "memory")

__device__ __forceinline__ void ldsm4(uint32_t* r, uint32_t addr) {
    asm volatile("ldmatrix.sync.aligned.m8n8.x4.shared.b16 {%0,%1,%2,%3}, [%4];"
        : "=r"(r[0]), "=r"(r[1]), "=r"(r[2]), "=r"(r[3]) : "r"(addr));
}
__device__ __forceinline__ void mma16816(float* c, const uint32_t* a, const uint32_t* b) {
    asm volatile("mma.sync.aligned.m16n8k16.row.col.f32.bf16.bf16.f32 "
        "{%0,%1,%2,%3}, {%4,%5,%6,%7}, {%8,%9}, {%0,%1,%2,%3};"
        : "+f"(c[0]), "+f"(c[1]), "+f"(c[2]), "+f"(c[3])
        : "r"(a[0]), "r"(a[1]), "r"(a[2]), "r"(a[3]), "r"(b[0]), "r"(b[1]));
}

// ================= split-bf16 tensor-core GEMM =================
#define GSTAGES 3
#define GMAT_BYTES (128 * 64)
#define GSTAGE_BYTES (4 * GMAT_BYTES)
#define GEMM_SMEM_BYTES (GSTAGES * GSTAGE_BYTES)

__device__ __forceinline__ uint32_t swz(int row, int c16) {
    return (uint32_t)(row * 64 + ((c16 ^ ((row >> 1) & 3)) << 4));
}

__device__ __forceinline__ void load_tile32(uint32_t dst, const __nv_bfloat16* src,
                                            int row0, int k0, int ldk, int tid) {
    const char* gbase = (const char*)(src + (size_t)row0 * ldk + k0);
    const size_t rowb = (size_t)ldk * 2;
#pragma unroll
    for (int j = 0; j < 4; j++) {
        int e = tid + j * 128;
        int r = e >> 2, c16 = e & 3;
        CP_ASYNC16(dst + swz(r, c16), gbase + (size_t)r * rowb + c16 * 16);
    }
}

__global__ __launch_bounds__(128, 2) void gemm_split_mma(
    const __nv_bfloat16* __restrict__ Ahi, const __nv_bfloat16* __restrict__ Alo,
    const __nv_bfloat16* __restrict__ Bhi, const __nv_bfloat16* __restrict__ Blo,
    float* __restrict__ C, int M, int N, int K) {
    extern __shared__ char smem[];
    const uint32_t sb = smem_u32(smem);
    const int tid = threadIdx.x, lane = tid & 31, wid = tid >> 5;
    const int wm = wid & 1, wn = wid >> 1;
    const int m0 = blockIdx.y * 128, n0 = blockIdx.x * 128;
    const int nchunk = K >> 5;

    const int a_row = (lane & 7) + 8 * ((lane >> 3) & 1);
    const int a_c8  = lane >> 4;
    const int b_row = (lane & 7) + 8 * (lane >> 4);
    const int b_c8  = (lane >> 3) & 1;

    const int arow = wm * 64 + a_row;
    const int selA = (arow >> 1) & 3;
    const int brow = wn * 64 + b_row;
    const int selB = (brow >> 1) & 3;

    float acc[4][8][4];
#pragma unroll
    for (int i = 0; i < 4; i++)
#pragma unroll
        for (int j = 0; j < 8; j++)
#pragma unroll
            for (int r = 0; r < 4; r++) acc[i][j][r] = 0.f;

#pragma unroll
    for (int s = 0; s < GSTAGES; s++) {
        uint32_t st = sb + s * GSTAGE_BYTES;
        int k0 = s * 32;
        load_tile32(st,                  Ahi, m0, k0, K, tid);
        load_tile32(st + GMAT_BYTES,     Alo, m0, k0, K, tid);
        load_tile32(st + 2 * GMAT_BYTES, Bhi, n0, k0, K, tid);
        load_tile32(st + 3 * GMAT_BYTES, Blo, n0, k0, K, tid);
        CP_ASYNC_COMMIT();
    }

    for (int c = 0; c < nchunk; c++) {
        uint32_t st = sb + (c % GSTAGES) * GSTAGE_BYTES;
        CP_ASYNC_WAIT1();
        __syncthreads();

        if (c >= 1) {
            if (c + 2 < nchunk) {
                uint32_t st2 = sb + ((c + 2) % GSTAGES) * GSTAGE_BYTES;
                int k0 = (c + 2) * 32;
                load_tile32(st2,                  Ahi, m0, k0, K, tid);
                load_tile32(st2 + GMAT_BYTES,     Alo, m0, k0, K, tid);
                load_tile32(st2 + 2 * GMAT_BYTES, Bhi, n0, k0, K, tid);
                load_tile32(st2 + 3 * GMAT_BYTES, Blo, n0, k0, K, tid);
            }
            CP_ASYNC_COMMIT();
        }

#pragma unroll
        for (int ks = 0; ks < 2; ks++) {
            const int ks2 = ks * 2;
            const uint32_t ca = (uint32_t)(((ks2 + a_c8) ^ selA) << 4);
            const uint32_t cb = (uint32_t)(((ks2 + b_c8) ^ selB) << 4);

            uint32_t ah[4][4], al[4][4];
#pragma unroll
            for (int mt = 0; mt < 4; mt++) {
                uint32_t ra = st + (uint32_t)((arow + mt * 16) * 64) + ca;
                ldsm4(ah[mt], ra);
                ldsm4(al[mt], ra + GMAT_BYTES);
            }
#pragma unroll
            for (int np = 0; np < 4; np++) {
                uint32_t bh[4], bl[4];
                uint32_t rb = st + 2 * GMAT_BYTES + (uint32_t)((brow + np * 16) * 64) + cb;
                ldsm4(bh, rb);
                ldsm4(bl, rb + GMAT_BYTES);
#pragma unroll
                for (int mt = 0; mt < 4; mt++)
#pragma unroll
                    for (int hf = 0; hf < 2; hf++) {
                        float* a4 = acc[mt][np * 2 + hf];
                        mma16816(a4, ah[mt], &bh[hf * 2]);
                        mma16816(a4, ah[mt], &bl[hf * 2]);
                        mma16816(a4, al[mt], &bh[hf * 2]);
                    }
            }
        }
    }

    const int crow = lane >> 2, ccol = (lane & 3) * 2;
#pragma unroll
    for (int mt = 0; mt < 4; mt++) {
        int rbase = m0 + wm * 64 + mt * 16 + crow;
#pragma unroll
        for (int nt = 0; nt < 8; nt++) {
            int cbase = n0 + wn * 64 + nt * 8 + ccol;
            float* d0 = C + (size_t)rbase * N + cbase;
            float* d1 = C + (size_t)(rbase + 8) * N + cbase;
            *(float2*)d0 = make_float2(acc[mt][nt][0], acc[mt][nt][1]);
            *(float2*)d1 = make_float2(acc[mt][nt][2], acc[mt][nt][3]);
        }
    }
}

// ================= fused prep: split_x | tsplit_qkvg | tsplit_wo =============
__device__ __forceinline__ void tsplit_block(const float* __restrict__ W,
                                             __nv_bfloat16* __restrict__ Thi,
                                             __nv_bfloat16* __restrict__ Tlo,
                                             int K, int srcN, int n0glob, int ln0, int k0,
                                             float (*t)[33]) {
    int tx = threadIdx.x & 31, ty = threadIdx.x >> 5;
#pragma unroll
    for (int i = ty; i < 32; i += 8)
        t[i][tx] = W[(size_t)(k0 + i) * srcN + ln0 + tx];
    __syncthreads();
#pragma unroll
    for (int i = ty; i < 32; i += 8) {
        float v = t[tx][i];
        __nv_bfloat16 h = __float2bfloat16(v);
        size_t oidx = (size_t)(n0glob + i) * K + k0 + tx;
        Thi[oidx] = h;
        Tlo[oidx] = __float2bfloat16(v - __bfloat162float(h));
    }
}

#define PREP_SPLIT_BLKS 8192
#define PREP_QKVG_BLKS  6144
#define PREP_WO_BLKS    2048
__global__ __launch_bounds__(256) void prep_kernel(
    const float4* __restrict__ x4, uint2* __restrict__ xhi, uint2* __restrict__ xlo,
    const float* __restrict__ Wq, const float* __restrict__ Wk,
    const float* __restrict__ Wv, const float* __restrict__ Wg,
    const float* __restrict__ Wo,
    __nv_bfloat16* __restrict__ wallh, __nv_bfloat16* __restrict__ walll,
    __nv_bfloat16* __restrict__ woh,  __nv_bfloat16* __restrict__ wol) {
    __shared__ float t[32][33];
    const int bx = blockIdx.x;
    if (bx < PREP_SPLIT_BLKS) {
        int i = bx * 256 + threadIdx.x;
        float4 v = x4[i];
        __nv_bfloat16 h0 = __float2bfloat16(v.x), h1 = __float2bfloat16(v.y);
        __nv_bfloat16 h2 = __float2bfloat16(v.z), h3 = __float2bfloat16(v.w);
        __nv_bfloat16 l0 = __float2bfloat16(v.x - __bfloat162float(h0));
        __nv_bfloat16 l1 = __float2bfloat16(v.y - __bfloat162float(h1));
        __nv_bfloat16 l2 = __float2bfloat16(v.z - __bfloat162float(h2));
        __nv_bfloat16 l3 = __float2bfloat16(v.w - __bfloat162float(h3));
        uint2 hp, lp;
        hp.x = (uint32_t)__bfloat16_as_ushort(h0) | ((uint32_t)__bfloat16_as_ushort(h1) << 16);
        hp.y = (uint32_t)__bfloat16_as_ushort(h2) | ((uint32_t)__bfloat16_as_ushort(h3) << 16);
        lp.x = (uint32_t)__bfloat16_as_ushort(l0) | ((uint32_t)__bfloat16_as_ushort(l1) << 16);
        lp.y = (uint32_t)__bfloat16_as_ushort(l2) | ((uint32_t)__bfloat16_as_ushort(l3) << 16);
        xhi[i] = hp;
        xlo[i] = lp;
    } else if (bx < PREP_SPLIT_BLKS + PREP_QKVG_BLKS) {
        int tb = bx - PREP_SPLIT_BLKS;
        int n0 = (tb % 192) * 32, k0 = (tb / 192) * 32;
        const float* W;
        int srcN, ln0;
        if (n0 < 1024)       { W = Wq; srcN = 1024; ln0 = n0; }
        else if (n0 < 2048)  { W = Wk; srcN = 1024; ln0 = n0 - 1024; }
        else if (n0 < 4096)  { W = Wv; srcN = 2048; ln0 = n0 - 2048; }
        else                 { W = Wg; srcN = 2048; ln0 = n0 - 4096; }
        tsplit_block(W, wallh, walll, DD, srcN, n0, ln0, k0, t);
    } else {
        int tb = bx - PREP_SPLIT_BLKS - PREP_QKVG_BLKS;
        int n0 = (tb % 32) * 32, k0 = (tb / 32) * 32;
        tsplit_block(Wo, woh, wol, 2 * DD, DD, n0, n0, k0, t);
    }
}

// ---------------- RoPE (vectorized float4) -----------------------------------
__global__ void rope_kernel(float* __restrict__ qkvg) {
    int idx = blockIdx.x * blockDim.x + threadIdx.x;
    const int total = BB * TT * HH * 16;
    if (idx >= total) return;
    int i4 = idx & 15;
    int h = (idx >> 4) & (HH - 1);
    int t = (idx >> 7) & (TT - 1);
    int b = idx >> 18;

    size_t base = ((size_t)b * TT + t) * NQKVG + h * DKk + i4 * 4;
    const float sc = 0.08838834764831845f;

    float s[4], c[4];
#pragma unroll
    for (int cc = 0; cc < 4; cc++) {
        int i = i4 * 4 + cc;
        float inv = powf(10000.f, -(float)i * (1.0f / 64.0f));
        sincosf((float)t * inv, &s[cc], &c[cc]);
    }

    float4 q1 = *(float4*)&qkvg[base];
    float4 q2 = *(float4*)&qkvg[base + 64];
    float* q1p = &q1.x; float* q2p = &q2.x;
    float4 o1, o2;
    float* o1p = &o1.x; float* o2p = &o2.x;
#pragma unroll
    for (int cc = 0; cc < 4; cc++) {
        o1p[cc] = (q1p[cc] * c[cc] - q2p[cc] * s[cc]) * sc;
        o2p[cc] = (q2p[cc] * c[cc] + q1p[cc] * s[cc]) * sc;
    }
    *(float4*)&qkvg[base]      = o1;
    *(float4*)&qkvg[base + 64] = o2;

    size_t kb = base + 1024;
    float4 k1 = *(float4*)&qkvg[kb];
    float4 k2 = *(float4*)&qkvg[kb + 64];
    float* k1p = &k1.x; float* k2p = &k2.x;
#pragma unroll
    for (int cc = 0; cc < 4; cc++) {
        o1p[cc] = k1p[cc] * c[cc] - k2p[cc] * s[cc];
        o2p[cc] = k2p[cc] * c[cc] + k1p[cc] * s[cc];
    }
    *(float4*)&qkvg[kb]      = o1;
    *(float4*)&qkvg[kb + 64] = o2;
}

// ================= fused retention phases A | B ========
// A: scalar, conflict-free odd strides, ks in dk-halves:
//    qs 64x129 + ks 64x65 + 64 = 12480 floats (49.9KB)
// B: ks 64x132 + vs 64x68 + 64 = 12864 floats (51.5KB)  -> AB smem = 51.5KB
// 4 blocks/SM (regs capped at 64 via launch bounds).
#define AB_SMEM (12864 * 4)

__global__ __launch_bounds__(256, 4) void ret_ab_kernel(const float* __restrict__ qkvg,
                                                        float* __restrict__ attn_out,
                                                        float* __restrict__ kv_out) {
    const int h = blockIdx.y, b = blockIdx.z;
    const int tid = threadIdx.x;
    extern __shared__ float sm[];
    const float gamma = 1.0f - exp2f(-5.0f - (float)h);

    if (blockIdx.x < NCHUNK) {
        // ---------------- Phase A (scalar, ks in dk-halves) ----------------
        const int n = blockIdx.x;
        float* qs   = sm;               // 64 x 129 (full dk)
        float* ks   = qs + 64 * 129;    // 64 x 65 (dk half)
        float* gpow = ks + 64 * 65;     // 64
        if (tid < 64) gpow[tid] = powf(gamma, (float)tid);

        const int t0 = n * CC;
        for (int e = tid; e < 64 * 128; e += 256) {
            int i = e >> 7, dk = e & 127;
            qs[i * 129 + dk] = qkvg[((size_t)b * TT + t0 + i) * NQKVG + h * DKk + dk];
        }

        const int ti = tid >> 4, te = tid & 15;
        float acc[4][4];
#pragma unroll
        for (int a = 0; a < 4; a++)
#pragma unroll
            for (int bq = 0; bq < 4; bq++) acc[a][bq] = 0.f;

#pragma unroll
        for (int half = 0; half < 2; half++) {
            if (half) __syncthreads();   // all reads of prev ks half done
            for (int e = tid; e < 64 * 64; e += 256) {
                int i = e >> 6, dkl = e & 63;
                ks[i * 65 + dkl] =
                    qkvg[((size_t)b * TT + t0 + i) * NQKVG + 1024 + h * DKk + half * 64 + dkl];
            }
            __syncthreads();
            for (int dkl = 0; dkl < 64; dkl++) {
                int dk = half * 64 + dkl;
                float ra[4], rb[4];
#pragma unroll
                for (int ii = 0; ii < 4; ii++) ra[ii] = qs[(ti * 4 + ii) * 129 + dk];
#pragma unroll
                for (int jj = 0; jj < 4; jj++) rb[jj] = ks[(te * 4 + jj) * 65 + dkl];
#pragma unroll
                for (int ii = 0; ii < 4; ii++)
#pragma unroll
                    for (int jj = 0; jj < 4; jj++) acc[ii][jj] += ra[ii] * rb[jj];
            }
        }

        float* dst = attn_out + ((((size_t)b * HH + h) * NCHUNK + n) << 12);
#pragma unroll
        for (int ii = 0; ii < 4; ii++) {
            int i = ti * 4 + ii;
            float4 w;
            float* wp = &w.x;
#pragma unroll
            for (int jj = 0; jj < 4; jj++) {
                int j = te * 4 + jj;
                wp[jj] = (i >= j) ? acc[ii][jj] * gpow[i - j] : 0.f;
            }
            *(float4*)(dst + i * 64 + te * 4) = w;
        }
    } else {
        // ---------------- Phase B ----------------
        const int lin = blockIdx.x - NCHUNK;
        const int sl = lin & 3, n = lin >> 2;
        float* ks   = sm;               // 64 x 132
        float* vs   = ks + 64 * 132;    // 64 x 68
        float* deck = vs + 64 * 68;     // 64
        if (tid < 64) deck[tid] = powf(gamma, (float)(63 - tid));
        __syncthreads();

        const int t0 = n * CC;
        for (int e = tid; e < 64 * 32; e += 256) {
            int i = e >> 5, c4 = e & 31;
            float4 v = *(const float4*)&qkvg[((size_t)b * TT + t0 + i) * NQKVG + 1024 + h * DKk + c4 * 4];
            *(float4*)&ks[i * 132 + c4 * 4] = v;
        }
        for (int e = tid; e < 64 * 16; e += 256) {
            int i = e >> 4, c4 = e & 15;
            float d = deck[i];
            float4 v = *(const float4*)&qkvg[((size_t)b * TT + t0 + i) * NQKVG + 2048 + h * DVv + sl * 64 + c4 * 4];
            v.x *= d; v.y *= d; v.z *= d; v.w *= d;
            *(float4*)&vs[i * 68 + c4 * 4] = v;
        }
        __syncthreads();

        const int ti = tid >> 4, te = tid & 15;
        float acc[8][4];
#pragma unroll
        for (int a = 0; a < 8; a++)
#pragma unroll
            for (int bq = 0; bq < 4; bq++) acc[a][bq] = 0.f;

        for (int j = 0; j < 64; j++) {
            float4 ka = *(const float4*)&ks[j * 132 + ti * 8];
            float4 kb = *(const float4*)&ks[j * 132 + ti * 8 + 4];
            float4 vb = *(const float4*)&vs[j * 68 + te * 4];
            float ra[8] = {ka.x, ka.y, ka.z, ka.w, kb.x, kb.y, kb.z, kb.w};
            float rb[4] = {vb.x, vb.y, vb.z, vb.w};
#pragma unroll
            for (int dd = 0; dd < 8; dd++)
#pragma unroll
                for (int ee = 0; ee < 4; ee++) acc[dd][ee] += ra[dd] * rb[ee];
        }

        float* dst = kv_out + ((((size_t)b * HH + h) * NCHUNK + n) * DKk) * DVv + sl * 64;
#pragma unroll
        for (int dd = 0; dd < 8; dd++) {
            int dk = ti * 8 + dd;
            *(float4*)(dst + (size_t)dk * DVv + te * 4) =
                make_float4(acc[dd][0], acc[dd][1], acc[dd][2], acc[dd][3]);
        }
    }
}

// Phase C: prefix scan of kv -> Spre (float4 per thread)
__global__ __launch_bounds__(256) void ret_scan_kernel(const float4* __restrict__ kv,
                                                       float4* __restrict__ Spre) {
    const int idx = blockIdx.x * 256 + threadIdx.x;
    const int bh  = idx >> 13;
    const int pos = idx & 8191;
    const int h   = bh & (HH - 1);
    const float gamma = 1.0f - exp2f(-5.0f - (float)h);
    const float gC = powf(gamma, 64.0f);

    const size_t base = (size_t)bh * NCHUNK * 8192 + pos;
    float4 s = make_float4(0.f, 0.f, 0.f, 0.f);
    Spre[base] = s;
    for (int n = 1; n < NCHUNK; n++) {
        float4 kvv = kv[base + (size_t)(n - 1) * 8192];
        s.x = gC * s.x + kvv.x;
        s.y = gC * s.y + kvv.y;
        s.z = gC * s.z + kvv.z;
        s.w = gC * s.w + kvv.w;
        Spre[base + (size_t)n * 8192] = s;
    }
}

// Phase D: o = attn @ v + decq * (q @ S_pre)  — qs/Ss in dk-halves (R15 win)
#define OUT_SMEM (17472 * 4)
__global__ __launch_bounds__(256) void ret_out_kernel(const float* __restrict__ qkvg,
                                                      const float* __restrict__ attn,
                                                      const float* __restrict__ Spre,
                                                      float* __restrict__ o) {
    const int sl = blockIdx.x & 3, n = blockIdx.x >> 2;
    const int h = blockIdx.y, b = blockIdx.z;
    const int tid = threadIdx.x;
    extern __shared__ float sm[];
    float* at   = sm;               // 64 x 68
    float* vs   = at + 64 * 68;     // 64 x 68
    float* qs   = vs + 64 * 68;     // 64 x 68 (dk half)
    float* Ss   = qs + 64 * 68;     // 64 x 68 (dk half)
    float* decq = Ss + 64 * 68;     // 64

    const float gamma = 1.0f - exp2f(-5.0f - (float)h);
    if (tid < 64) decq[tid] = powf(gamma, (float)(tid + 1));

    const int t0 = n * CC;
    const size_t bh = (size_t)b * HH + h;
    const float* asrc = attn + ((bh * NCHUNK + n) << 12);
    const float* ssrc = Spre + ((bh * NCHUNK + n) * DKk) * DVv + sl * 64;

    for (int e = tid; e < 64 * 16; e += 256) {
        int i = e >> 4, c4 = e & 15;
        *(float4*)&at[i * 68 + c4 * 4] = *(const float4*)&asrc[i * 64 + c4 * 4];
        *(float4*)&vs[i * 68 + c4 * 4] =
            *(const float4*)&qkvg[((size_t)b * TT + t0 + i) * NQKVG + 2048 + h * DVv + sl * 64 + c4 * 4];
    }

    const int ti = tid >> 4, te = tid & 15;
    float aI[4][4], aS[4][4];
#pragma unroll
    for (int a = 0; a < 4; a++)
#pragma unroll
        for (int bq = 0; bq < 4; bq++) { aI[a][bq] = 0.f; aS[a][bq] = 0.f; }

#pragma unroll
    for (int half = 0; half < 2; half++) {
        if (half) __syncthreads();
        for (int e = tid; e < 64 * 16; e += 256) {
            int i = e >> 4, c4 = e & 15;
            *(float4*)&qs[i * 68 + c4 * 4] =
                *(const float4*)&qkvg[((size_t)b * TT + t0 + i) * NQKVG + h * DKk + half * 64 + c4 * 4];
        }
        for (int e = tid; e < 64 * 16; e += 256) {
            int r = e >> 4, c4 = e & 15;
            *(float4*)&Ss[r * 68 + c4 * 4] =
                *(const float4*)&ssrc[(size_t)(half * 64 + r) * DVv + c4 * 4];
        }
        __syncthreads();

        if (half == 0) {
            for (int jg = 0; jg < 16; jg++) {
                float4 ra4[4];
#pragma unroll
                for (int ii = 0; ii < 4; ii++)
                    ra4[ii] = *(const float4*)&at[(ti * 4 + ii) * 68 + jg * 4];
#pragma unroll
                for (int jj = 0; jj < 4; jj++) {
                    float4 vb = *(const float4*)&vs[(jg * 4 + jj) * 68 + te * 4];
#pragma unroll
                    for (int ii = 0; ii < 4; ii++) {
                        float ra = ((const float*)&ra4[ii])[jj];
                        aI[ii][0] += ra * vb.x;
                        aI[ii][1] += ra * vb.y;
                        aI[ii][2] += ra * vb.z;
                        aI[ii][3] += ra * vb.w;
                    }
                }
            }
        }
        for (int dg = 0; dg < 16; dg++) {
            float4 ra4[4];
#pragma unroll
            for (int ii = 0; ii < 4; ii++)
                ra4[ii] = *(const float4*)&qs[(ti * 4 + ii) * 68 + dg * 4];
#pragma unroll
            for (int dd = 0; dd < 4; dd++) {
                float4 sb4 = *(const float4*)&Ss[(dg * 4 + dd) * 68 + te * 4];
#pragma unroll
                for (int ii = 0; ii < 4; ii++) {
                    float ra = ((const float*)&ra4[ii])[dd];
                    aS[ii][0] += ra * sb4.x;
                    aS[ii][1] += ra * sb4.y;
                    aS[ii][2] += ra * sb4.z;
                    aS[ii][3] += ra * sb4.w;
                }
            }
        }
    }

#pragma unroll
    for (int ii = 0; ii < 4; ii++) {
        int i = ti * 4 + ii;
        float dq = decq[i];
        size_t base = (((size_t)b * TT + t0 + i) * HH + h) * DVv + sl * 64 + te * 4;
        *(float4*)(&o[base]) = make_float4(aI[ii][0] + dq * aS[ii][0],
                                           aI[ii][1] + dq * aS[ii][1],
                                           aI[ii][2] + dq * aS[ii][2],
                                           aI[ii][3] + dq * aS[ii][3]);
    }
}

// ---------------- RMSNorm + swish gate + bf16 split (vectorized) ----
__global__ __launch_bounds__(256) void normgate_split_kernel(const float* __restrict__ o,
                                                             const float* __restrict__ qkvg,
                                                             const float* __restrict__ norm_w,
                                                             __nv_bfloat16* __restrict__ ohi,
                                                             __nv_bfloat16* __restrict__ olo) {
    int warp = (blockIdx.x * blockDim.x + threadIdx.x) >> 5;
    int lane = threadIdx.x & 31;
    if (warp >= MROWS * HH) return;
    size_t base  = (size_t)warp * DVv + lane * 8;
    size_t gbase = (size_t)(warp >> 3) * NQKVG + 4096 + (size_t)(warp & 7) * DVv + lane * 8;

    float4 v0 = *(const float4*)(o + base);
    float4 v1 = *(const float4*)(o + base + 4);
    float vals[8] = {v0.x, v0.y, v0.z, v0.w, v1.x, v1.y, v1.z, v1.w};

    float ss = 0.f;
#pragma unroll
    for (int r = 0; r < 8; r++) ss += vals[r] * vals[r];
#pragma unroll
    for (int off = 16; off; off >>= 1) ss += __shfl_xor_sync(0xFFFFFFFFu, ss, off);
    float inv = rsqrtf(ss * (1.0f / 256.0f) + 1e-5f);

    float4 g0 = *(const float4*)(qkvg + gbase);
    float4 g1 = *(const float4*)(qkvg + gbase + 4);
    float gv[8] = {g0.x, g0.y, g0.z, g0.w, g1.x, g1.y, g1.z, g1.w};
    float4 w0 = *(const float4*)(norm_w + lane * 8);
    float4 w1 = *(const float4*)(norm_w + lane * 8 + 4);
    float wv[8] = {w0.x, w0.y, w0.z, w0.w, w1.x, w1.y, w1.z, w1.w};

    uint32_t hp[4], lp[4];
#pragma unroll
    for (int p = 0; p < 4; p++) {
        float r0, r1;
        {
            float sg = 1.f / (1.f + expf(-gv[2 * p]));
            r0 = vals[2 * p] * inv * wv[2 * p] * gv[2 * p] * sg;
        }
        {
            float sg = 1.f / (1.f + expf(-gv[2 * p + 1]));
            r1 = vals[2 * p + 1] * inv * wv[2 * p + 1] * gv[2 * p + 1] * sg;
        }
        __nv_bfloat16 h0 = __float2bfloat16(r0), h1 = __float2bfloat16(r1);
        __nv_bfloat16 l0 = __float2bfloat16(r0 - __bfloat162float(h0));
        __nv_bfloat16 l1 = __float2bfloat16(r1 - __bfloat162float(h1));
        hp[p] = (uint32_t)__bfloat16_as_ushort(h0) | ((uint32_t)__bfloat16_as_ushort(h1) << 16);
        lp[p] = (uint32_t)__bfloat16_as_ushort(l0) | ((uint32_t)__bfloat16_as_ushort(l1) << 16);
    }
    *(uint4*)(ohi + base) = make_uint4(hp[0], hp[1], hp[2], hp[3]);
    *(uint4*)(olo + base) = make_uint4(lp[0], lp[1], lp[2], lp[3]);
}

// ---------------- launch ----------------
static void launch_gemm(const __nv_bfloat16* Ahi, const __nv_bfloat16* Alo,
                        const __nv_bfloat16* Bhi, const __nv_bfloat16* Blo,
                        float* C, int M, int N, int K) {
    gemm_split_mma<<<dim3(N / 128, M / 128), 128, GEMM_SMEM_BYTES>>>(Ahi, Alo, Bhi, Blo, C, M, N, K);
}

extern "C" void kernel_launch(void* const* d_in, const int* in_sizes, int n_in,
                              void* d_out, int out_size) {
    const float* x      = (const float*)d_in[0];
    const float* Wq     = (const float*)d_in[1];
    const float* Wk     = (const float*)d_in[2];
    const float* Wv     = (const float*)d_in[3];
    const float* Wg     = (const float*)d_in[4];
    const float* Wo     = (const float*)d_in[5];
    const float* norm_w = (const float*)d_in[6];
    float* out = (float*)d_out;

    float *qkvg, *o, *attn, *kv, *S;
    cudaGetSymbolAddress((void**)&qkvg, g_qkvg);
    cudaGetSymbolAddress((void**)&o, g_o);
    cudaGetSymbolAddress((void**)&attn, g_attn);
    cudaGetSymbolAddress((void**)&kv, g_kv);
    cudaGetSymbolAddress((void**)&S, g_S);
    __nv_bfloat16 *xhi, *xlo, *ohi, *olo, *wallh, *walll, *woh, *wol;
    cudaGetSymbolAddress((void**)&xhi, g_xhi);
    cudaGetSymbolAddress((void**)&xlo, g_xlo);
    cudaGetSymbolAddress((void**)&ohi, g_ohi);
    cudaGetSymbolAddress((void**)&olo, g_olo);
    cudaGetSymbolAddress((void**)&wallh, g_wall_hi);
    cudaGetSymbolAddress((void**)&walll, g_wall_lo);
    cudaGetSymbolAddress((void**)&woh, g_wo_hi);
    cudaGetSymbolAddress((void**)&wol, g_wo_lo);

    cudaFuncSetAttribute(gemm_split_mma, cudaFuncAttributeMaxDynamicSharedMemorySize, GEMM_SMEM_BYTES);
    cudaFuncSetAttribute(ret_ab_kernel, cudaFuncAttributeMaxDynamicSharedMemorySize, AB_SMEM);
    cudaFuncSetAttribute(ret_out_kernel, cudaFuncAttributeMaxDynamicSharedMemorySize, OUT_SMEM);

    // fused prep
    prep_kernel<<<PREP_SPLIT_BLKS + PREP_QKVG_BLKS + PREP_WO_BLKS, 256>>>(
        (const float4*)x, (uint2*)xhi, (uint2*)xlo,
        Wq, Wk, Wv, Wg, Wo, wallh, walll, woh, wol);

    // combined projection GEMM (q|k|v|g)
    launch_gemm(xhi, xlo, wallh, walll, qkvg, MROWS, NQKVG, DD);

    // rope + scale (vectorized)
    {
        int total = BB * TT * HH * 16;
        rope_kernel<<<(total + 255) / 256, 256>>>(qkvg);
    }

    // retention: fused A|B, then scan, then D
    ret_ab_kernel<<<dim3(NCHUNK + 4 * NCHUNK, HH, BB), 256, AB_SMEM>>>(qkvg, attn, kv);
    ret_scan_kernel<<<(NBH * DKk * DVv / 4) / 256, 256>>>((const float4*)kv, (float4*)S);
    ret_out_kernel<<<dim3(4 * NCHUNK, HH, BB), 256, OUT_SMEM>>>(qkvg, attn, S, o);

    // rmsnorm + gate + split (fused, vectorized)
    {
        int warps = MROWS * HH;
        normgate_split_kernel<<<(warps * 32 + 255) / 256, 256>>>(o, qkvg, norm_w, ohi, olo);
    }

    // output projection on tensor cores
    launch_gemm(ohi, olo, woh, wol, out, MROWS, DD, 2 * DD);
}